// round 7
// baseline (speedup 1.0000x reference)
#include <cuda_runtime.h>
#include <cuda_bf16.h>
#include <math_constants.h>

#define C_DIM 1024
#define C3    3072
#define NH    16
#define HD    64
#define B_SZ  2
#define T_SZ  2048
#define M_ROWS (B_SZ*T_SZ)

#define ATT_SCALE 0.5f
#define LOG2E 1.4426950408889634f

typedef unsigned long long u64;
typedef unsigned int u32;

// ---------------- scratch (no device allocation allowed) -------------------
__device__ __nv_bfloat16 g_qh[(size_t)M_ROWS * C_DIM];
__device__ __nv_bfloat16 g_ql[(size_t)M_ROWS * C_DIM];
__device__ __nv_bfloat16 g_kh[(size_t)M_ROWS * C_DIM];
__device__ __nv_bfloat16 g_kl[(size_t)M_ROWS * C_DIM];
__device__ __nv_bfloat16 g_vh[(size_t)M_ROWS * C_DIM];
__device__ __nv_bfloat16 g_vl[(size_t)M_ROWS * C_DIM];
__device__ __nv_bfloat16 g_xh[(size_t)M_ROWS * C_DIM];
__device__ __nv_bfloat16 g_xl[(size_t)M_ROWS * C_DIM];
__device__ __nv_bfloat16 g_ah[(size_t)M_ROWS * C_DIM];
__device__ __nv_bfloat16 g_al[(size_t)M_ROWS * C_DIM];
__device__ __nv_bfloat16 g_wqh[(size_t)C3 * C_DIM];   // Wqkv^T hi [N][K]
__device__ __nv_bfloat16 g_wql[(size_t)C3 * C_DIM];
__device__ __nv_bfloat16 g_wph[(size_t)C_DIM * C_DIM];
__device__ __nv_bfloat16 g_wpl[(size_t)C_DIM * C_DIM];

// ---------------- helpers ----------------------------------------------------
__device__ __forceinline__ u32 smem_u32(const void* p) {
    u32 a; asm("{ .reg .u64 t; cvta.to.shared.u64 t, %1; cvt.u32.u64 %0, t; }"
               : "=r"(a) : "l"(p));
    return a;
}
__device__ __forceinline__ void ldsm_x4(u32& r0, u32& r1, u32& r2, u32& r3, u32 a) {
    asm volatile("ldmatrix.sync.aligned.m8n8.x4.shared.b16 {%0,%1,%2,%3}, [%4];"
                 : "=r"(r0), "=r"(r1), "=r"(r2), "=r"(r3) : "r"(a));
}
__device__ __forceinline__ void ldsm_x4t(u32& r0, u32& r1, u32& r2, u32& r3, u32 a) {
    asm volatile("ldmatrix.sync.aligned.m8n8.x4.trans.shared.b16 {%0,%1,%2,%3}, [%4];"
                 : "=r"(r0), "=r"(r1), "=r"(r2), "=r"(r3) : "r"(a));
}
__device__ __forceinline__ void mma16816(float* c, const u32* a, const u32* b) {
    asm volatile(
        "mma.sync.aligned.m16n8k16.row.col.f32.bf16.bf16.f32 "
        "{%0,%1,%2,%3},{%4,%5,%6,%7},{%8,%9},{%0,%1,%2,%3};"
        : "+f"(c[0]), "+f"(c[1]), "+f"(c[2]), "+f"(c[3])
        : "r"(a[0]), "r"(a[1]), "r"(a[2]), "r"(a[3]), "r"(b[0]), "r"(b[1]));
}
__device__ __forceinline__ float fast_exp2(float x) {
    float r; asm("ex2.approx.ftz.f32 %0, %1;" : "=f"(r) : "f"(x)); return r;
}
__device__ __forceinline__ u32 cvt_bf16x2(float lo, float hi) {
    u32 r; asm("cvt.rn.bf16x2.f32 %0, %1, %2;" : "=r"(r) : "f"(hi), "f"(lo));
    return r;
}
__device__ __forceinline__ void split2(float f0, float f1, u32& hi, u32& lo) {
    hi = cvt_bf16x2(f0, f1);
    float h0 = __uint_as_float(hi << 16);
    float h1 = __uint_as_float(hi & 0xffff0000u);
    lo = cvt_bf16x2(f0 - h0, f1 - h1);
}
#define CP_ASYNC16(d, s) asm volatile("cp.async.cg.shared.global [%0], [%1], 16;" :: "r"(d), "l"(s))
#define CP_COMMIT()      asm volatile("cp.async.commit_group;" ::: "memory")
#define CP_WAIT1()       asm volatile("cp.async.wait_group 1;" ::: "memory")
#define CP_WAIT0()       asm volatile("cp.async.wait_group 0;" ::: "memory")

// ---------------- prep: fp32 -> bf16 hi/lo split ----------------------------
__global__ void split_kernel(const float* __restrict__ in,
                             __nv_bfloat16* __restrict__ hi,
                             __nv_bfloat16* __restrict__ lo, int n4)
{
    int i = blockIdx.x * blockDim.x + threadIdx.x;
    if (i >= n4) return;
    float4 v = ((const float4*)in)[i];
    u32 h0, l0, h1, l1;
    split2(v.x, v.y, h0, l0);
    split2(v.z, v.w, h1, l1);
    ((uint2*)hi)[i] = make_uint2(h0, h1);
    ((uint2*)lo)[i] = make_uint2(l0, l1);
}

// ---------------- prep: W[K][N] -> W^T hi/lo [N][K] -------------------------
__global__ void transpose_split_kernel(const float* __restrict__ W,
                                       __nv_bfloat16* __restrict__ Wh,
                                       __nv_bfloat16* __restrict__ Wl,
                                       int K, int N)
{
    __shared__ float ts[32][33];
    int n0 = blockIdx.x * 32, k0 = blockIdx.y * 32;
    int tx = threadIdx.x, ty = threadIdx.y;  // 32 x 8
#pragma unroll
    for (int r = 0; r < 4; r++)
        ts[ty + 8 * r][tx] = W[(size_t)(k0 + ty + 8 * r) * N + n0 + tx];
    __syncthreads();
#pragma unroll
    for (int r = 0; r < 4; r++) {
        float v = ts[tx][ty + 8 * r];
        __nv_bfloat16 h = __float2bfloat16(v);
        __nv_bfloat16 l = __float2bfloat16(v - __bfloat162float(h));
        size_t o = (size_t)(n0 + ty + 8 * r) * K + k0 + tx;
        Wh[o] = h; Wl[o] = l;
    }
}

// ---------------- warp-MMA bf16x3 GEMM --------------------------------------
// C = (Ah+Al) @ (Bh+Bl)^T + bias   (Al*Bl dropped)
// 128x128 CTA tile, BK=32, 4 warps (2m x 2n), each 64x64, 2-stage cp.async.
// MMAs issued pass-major: 32 independent accumulators between dependent issues.
#define RSTRIDE 80
#define ARR_B   (128 * RSTRIDE)
#define STAGE_B (4 * ARR_B)
#define GSMEM   (2 * STAGE_B)

extern __shared__ char sm_raw[];

template<int SPLIT>
__global__ void __launch_bounds__(128) gemm_mma_kernel(
    const __nv_bfloat16* __restrict__ Ah, const __nv_bfloat16* __restrict__ Al,
    const __nv_bfloat16* __restrict__ Bh, const __nv_bfloat16* __restrict__ Bl,
    const float* __restrict__ bias, float* __restrict__ C,
    int M, int N, int K,
    __nv_bfloat16* oq_h, __nv_bfloat16* oq_l,
    __nv_bfloat16* ok_h, __nv_bfloat16* ok_l,
    __nv_bfloat16* ov_h, __nv_bfloat16* ov_l)
{
    const int tid = threadIdx.x, lane = tid & 31, wid = tid >> 5;
    const int warp_m = wid & 1, warp_n = wid >> 1;   // 2 x 2
    const int m0 = blockIdx.y * 128, n0 = blockIdx.x * 128;

    const int grp = lane >> 3, lrow = lane & 7;
    const int a_row = (grp & 1) * 8 + lrow, a_kb = (grp >> 1) * 16;
    const int b_row = (grp >> 1) * 8 + lrow, b_kb = (grp & 1) * 16;

    const __nv_bfloat16* srcs[4] = {Ah, Al, Bh, Bl};
    const int r0s[4] = {m0, m0, n0, n0};

    float cf[4][8][4];
#pragma unroll
    for (int tm = 0; tm < 4; tm++)
#pragma unroll
        for (int tn = 0; tn < 8; tn++)
#pragma unroll
            for (int q = 0; q < 4; q++) cf[tm][tn][q] = 0.f;

#define G_LOAD(st, k0v)                                                         \
    do {                                                                        \
        char* _b = sm_raw + (st) * STAGE_B;                                     \
        _Pragma("unroll")                                                       \
        for (int t = 0; t < 4; t++) {                                           \
            const __nv_bfloat16* _s = srcs[t] + (size_t)r0s[t] * K + (k0v);     \
            _Pragma("unroll")                                                   \
            for (int j = 0; j < 4; j++) {                                       \
                int _i = tid + j * 128;                                         \
                int _r = _i >> 2, _c = _i & 3;                                  \
                u32 _d = smem_u32(_b + t * ARR_B + _r * RSTRIDE + _c * 16);     \
                CP_ASYNC16(_d, _s + (size_t)_r * K + _c * 8);                   \
            }                                                                   \
        }                                                                       \
    } while (0)

// pass-major MMA issue: for each pass, 32 independent accumulator tiles.
#define COMPUTE(st)                                                             \
    do {                                                                        \
        u32 _sb = smem_u32(sm_raw) + (st) * STAGE_B;                            \
        _Pragma("unroll")                                                       \
        for (int ks = 0; ks < 2; ks++) {                                        \
            u32 afr[2][4][4], bfr[2][4][4];                                     \
            _Pragma("unroll")                                                   \
            for (int s = 0; s < 2; s++)                                         \
                _Pragma("unroll")                                               \
                for (int tm = 0; tm < 4; tm++)                                  \
                    ldsm_x4(afr[s][tm][0], afr[s][tm][1],                       \
                            afr[s][tm][2], afr[s][tm][3],                       \
                            _sb + s * ARR_B +                                   \
                            (warp_m * 64 + tm * 16 + a_row) * RSTRIDE +         \
                            ks * 32 + a_kb);                                    \
            _Pragma("unroll")                                                   \
            for (int s = 0; s < 2; s++)                                         \
                _Pragma("unroll")                                               \
                for (int t2 = 0; t2 < 4; t2++)                                  \
                    ldsm_x4(bfr[s][t2][0], bfr[s][t2][1],                       \
                            bfr[s][t2][2], bfr[s][t2][3],                       \
                            _sb + (2 + s) * ARR_B +                             \
                            (warp_n * 64 + t2 * 16 + b_row) * RSTRIDE +         \
                            ks * 32 + b_kb);                                    \
            _Pragma("unroll")                                                   \
            for (int tm = 0; tm < 4; tm++)                                      \
                _Pragma("unroll")                                               \
                for (int tn = 0; tn < 8; tn++)                                  \
                    mma16816(cf[tm][tn], afr[0][tm],                            \
                             &bfr[0][tn >> 1][(tn & 1) * 2]);                   \
            _Pragma("unroll")                                                   \
            for (int tm = 0; tm < 4; tm++)                                      \
                _Pragma("unroll")                                               \
                for (int tn = 0; tn < 8; tn++)                                  \
                    mma16816(cf[tm][tn], afr[0][tm],                            \
                             &bfr[1][tn >> 1][(tn & 1) * 2]);                   \
            _Pragma("unroll")                                                   \
            for (int tm = 0; tm < 4; tm++)                                      \
                _Pragma("unroll")                                               \
                for (int tn = 0; tn < 8; tn++)                                  \
                    mma16816(cf[tm][tn], afr[1][tm],                            \
                             &bfr[0][tn >> 1][(tn & 1) * 2]);                   \
        }                                                                       \
    } while (0)

    const int NIT = K / 32;
    G_LOAD(0, 0);
    CP_COMMIT();
    for (int it = 0; it < NIT; it++) {
        if (it + 1 < NIT) {
            G_LOAD((it + 1) & 1, (it + 1) * 32);
            CP_COMMIT();
            CP_WAIT1();
        } else {
            CP_WAIT0();
        }
        __syncthreads();
        COMPUTE(it & 1);
        __syncthreads();
    }

    const int mrow = lane >> 2, ncol = (lane & 3) * 2;
    if (SPLIT) {
        int part = n0 >> 10;
        __nv_bfloat16* dh = part == 0 ? oq_h : (part == 1 ? ok_h : ov_h);
        __nv_bfloat16* dl = part == 0 ? oq_l : (part == 1 ? ok_l : ov_l);
#pragma unroll
        for (int tm = 0; tm < 4; tm++)
#pragma unroll
            for (int tn = 0; tn < 8; tn++) {
                int r = m0 + warp_m * 64 + tm * 16 + mrow;
                int c = n0 + warp_n * 64 + tn * 8 + ncol;
                int lc = c & 1023;
                float2 bb = *(const float2*)&bias[c];
                u32 h0, l0, h1, l1;
                split2(cf[tm][tn][0] + bb.x, cf[tm][tn][1] + bb.y, h0, l0);
                split2(cf[tm][tn][2] + bb.x, cf[tm][tn][3] + bb.y, h1, l1);
                *(u32*)(dh + (size_t)r * C_DIM + lc) = h0;
                *(u32*)(dl + (size_t)r * C_DIM + lc) = l0;
                *(u32*)(dh + (size_t)(r + 8) * C_DIM + lc) = h1;
                *(u32*)(dl + (size_t)(r + 8) * C_DIM + lc) = l1;
            }
    } else {
#pragma unroll
        for (int tm = 0; tm < 4; tm++)
#pragma unroll
            for (int tn = 0; tn < 8; tn++) {
                int r = m0 + warp_m * 64 + tm * 16 + mrow;
                int c = n0 + warp_n * 64 + tn * 8 + ncol;
                float2 bb = *(const float2*)&bias[c];
                *(float2*)&C[(size_t)r * N + c] =
                    make_float2(cf[tm][tn][0] + bb.x, cf[tm][tn][1] + bb.y);
                *(float2*)&C[(size_t)(r + 8) * N + c] =
                    make_float2(cf[tm][tn][2] + bb.x, cf[tm][tn][3] + bb.y);
            }
    }
#undef G_LOAD
#undef COMPUTE
}

// ---------------- tensor-core flash attention -------------------------------
#define FA_RS   72
#define FA_ARR  (128 * FA_RS)
#define FA_ST0  (2 * FA_ARR)
#define FA_STSZ (4 * FA_ARR)
#define FA_SMEM ((2 * FA_ARR + 2 * FA_STSZ) * 2)   // 184320 B

__global__ void __launch_bounds__(256) flash_attn_mma(
    const __nv_bfloat16* __restrict__ qh, const __nv_bfloat16* __restrict__ ql,
    const __nv_bfloat16* __restrict__ kh, const __nv_bfloat16* __restrict__ kl,
    const __nv_bfloat16* __restrict__ vh, const __nv_bfloat16* __restrict__ vl,
    __nv_bfloat16* __restrict__ oh, __nv_bfloat16* __restrict__ ol)
{
    __nv_bfloat16* sm = (__nv_bfloat16*)sm_raw;
    const int tid = threadIdx.x, lane = tid & 31, w = tid >> 5;
    const int qt = blockIdx.x;
    const int b = blockIdx.y >> 4, h = blockIdx.y & 15;
    const size_t rowbase = (size_t)b * T_SZ;
    const int colbase = h * HD;

    const __nv_bfloat16* kvsrc[4] = {kh, kl, vh, vl};

#define FA_LOAD(st, kt)                                                         \
    do {                                                                        \
        _Pragma("unroll")                                                       \
        for (int a4 = 0; a4 < 4; a4++) {                                        \
            _Pragma("unroll")                                                   \
            for (int j = 0; j < 4; j++) {                                       \
                int idx = tid + j * 256;                                        \
                int r = idx >> 3, c8 = idx & 7;                                 \
                u32 d = smem_u32(sm + FA_ST0 + (st) * FA_STSZ + a4 * FA_ARR +   \
                                 r * FA_RS + c8 * 8);                           \
                CP_ASYNC16(d, kvsrc[a4] +                                       \
                           (rowbase + (kt) * 128 + r) * C_DIM + colbase + c8 * 8); \
            }                                                                   \
        }                                                                       \
    } while (0)

    FA_LOAD(0, 0);
    CP_COMMIT();

    {
        const __nv_bfloat16* qsrc[2] = {qh, ql};
#pragma unroll
        for (int a2 = 0; a2 < 2; a2++)
#pragma unroll
            for (int j = 0; j < 4; j++) {
                int idx = tid + j * 256;
                int r = idx >> 3, c8 = idx & 7;
                uint4 v = *(const uint4*)(qsrc[a2] +
                    (rowbase + qt * 128 + r) * C_DIM + colbase + c8 * 8);
                *(uint4*)(sm + a2 * FA_ARR + r * FA_RS + c8 * 8) = v;
            }
    }
    __syncthreads();

    u32 qfh[4][4], qfl[4][4];
    {
        u32 qbase = smem_u32(sm);
        int arow = w * 16 + (lane & 15);
        int acol = (lane >> 4) * 8;
#pragma unroll
        for (int ks = 0; ks < 4; ks++) {
            u32 off = (arow * FA_RS + ks * 16 + acol) * 2;
            ldsm_x4(qfh[ks][0], qfh[ks][1], qfh[ks][2], qfh[ks][3], qbase + off);
            ldsm_x4(qfl[ks][0], qfl[ks][1], qfl[ks][2], qfl[ks][3],
                    qbase + FA_ARR * 2 + off);
        }
    }

    float sf[16][4];
    float of[8][4];
#pragma unroll
    for (int j = 0; j < 8; j++)
#pragma unroll
        for (int q = 0; q < 4; q++) of[j][q] = 0.f;
    float m0 = -CUDART_INF_F, m1 = -CUDART_INF_F, l0 = 0.f, l1 = 0.f;

    const u32 sbase = smem_u32(sm);
    const int krow = (lane & 7) + ((lane >> 4) << 3);
    const int kch  = (lane >> 3) & 1;
    const int vrow = (lane & 7) + (((lane >> 3) & 1) << 3);
    const int vch  = lane >> 4;
    const float sc = ATT_SCALE * LOG2E;

    for (int kt = 0; kt < T_SZ / 128; kt++) {
        if (kt + 1 < T_SZ / 128) { FA_LOAD((kt + 1) & 1, kt + 1); CP_COMMIT(); CP_WAIT1(); }
        else CP_WAIT0();
        __syncthreads();
        u32 stb = sbase + (FA_ST0 + (kt & 1) * FA_STSZ) * 2;

        // ---- S = Q K^T (bf16x3), js processed in pairs, pass-major ----
#pragma unroll
        for (int j = 0; j < 16; j++) {
            sf[j][0] = 0.f; sf[j][1] = 0.f; sf[j][2] = 0.f; sf[j][3] = 0.f;
        }
#pragma unroll
        for (int jp = 0; jp < 4; jp++) {
            u32 bh[2][4][4], bl[2][4][4];
#pragma unroll
            for (int j2 = 0; j2 < 2; j2++)
#pragma unroll
                for (int ks = 0; ks < 4; ks++) {
                    u32 off = (((jp * 2 + j2) * 16 + krow) * FA_RS +
                               ks * 16 + kch * 8) * 2;
                    ldsm_x4(bh[j2][ks][0], bh[j2][ks][1], bh[j2][ks][2], bh[j2][ks][3],
                            stb + off);
                    ldsm_x4(bl[j2][ks][0], bl[j2][ks][1], bl[j2][ks][2], bl[j2][ks][3],
                            stb + FA_ARR * 2 + off);
                }
            float* s0 = sf[4 * jp];     float* s1 = sf[4 * jp + 1];
            float* s2 = sf[4 * jp + 2]; float* s3 = sf[4 * jp + 3];
#pragma unroll
            for (int ks = 0; ks < 4; ks++) {     // pass hh: 4 indep per step
                mma16816(s0, qfh[ks], &bh[0][ks][0]);
                mma16816(s1, qfh[ks], &bh[0][ks][2]);
                mma16816(s2, qfh[ks], &bh[1][ks][0]);
                mma16816(s3, qfh[ks], &bh[1][ks][2]);
            }
#pragma unroll
            for (int ks = 0; ks < 4; ks++) {     // pass hl
                mma16816(s0, qfh[ks], &bl[0][ks][0]);
                mma16816(s1, qfh[ks], &bl[0][ks][2]);
                mma16816(s2, qfh[ks], &bl[1][ks][0]);
                mma16816(s3, qfh[ks], &bl[1][ks][2]);
            }
#pragma unroll
            for (int ks = 0; ks < 4; ks++) {     // pass lh
                mma16816(s0, qfl[ks], &bh[0][ks][0]);
                mma16816(s1, qfl[ks], &bh[0][ks][2]);
                mma16816(s2, qfl[ks], &bh[1][ks][0]);
                mma16816(s3, qfl[ks], &bh[1][ks][2]);
            }
        }

        // ---- online softmax ----
        float mt0 = -CUDART_INF_F, mt1 = -CUDART_INF_F;
#pragma unroll
        for (int j = 0; j < 16; j++) {
            sf[j][0] *= sc; sf[j][1] *= sc; sf[j][2] *= sc; sf[j][3] *= sc;
            mt0 = fmaxf(mt0, fmaxf(sf[j][0], sf[j][1]));
            mt1 = fmaxf(mt1, fmaxf(sf[j][2], sf[j][3]));
        }
        mt0 = fmaxf(mt0, __shfl_xor_sync(0xffffffffu, mt0, 1));
        mt0 = fmaxf(mt0, __shfl_xor_sync(0xffffffffu, mt0, 2));
        mt1 = fmaxf(mt1, __shfl_xor_sync(0xffffffffu, mt1, 1));
        mt1 = fmaxf(mt1, __shfl_xor_sync(0xffffffffu, mt1, 2));
        float mn0 = fmaxf(m0, mt0), mn1 = fmaxf(m1, mt1);
        float f0 = fast_exp2(m0 - mn0), f1 = fast_exp2(m1 - mn1);
        m0 = mn0; m1 = mn1;
        float rs0 = 0.f, rs1 = 0.f;
#pragma unroll
        for (int j = 0; j < 16; j++) {
            sf[j][0] = fast_exp2(sf[j][0] - mn0);
            sf[j][1] = fast_exp2(sf[j][1] - mn0);
            sf[j][2] = fast_exp2(sf[j][2] - mn1);
            sf[j][3] = fast_exp2(sf[j][3] - mn1);
            rs0 += sf[j][0] + sf[j][1];
            rs1 += sf[j][2] + sf[j][3];
        }
        rs0 += __shfl_xor_sync(0xffffffffu, rs0, 1);
        rs0 += __shfl_xor_sync(0xffffffffu, rs0, 2);
        rs1 += __shfl_xor_sync(0xffffffffu, rs1, 1);
        rs1 += __shfl_xor_sync(0xffffffffu, rs1, 2);
        l0 = l0 * f0 + rs0;
        l1 = l1 * f1 + rs1;
#pragma unroll
        for (int j = 0; j < 8; j++) {
            of[j][0] *= f0; of[j][1] *= f0; of[j][2] *= f1; of[j][3] *= f1;
        }

        // ---- O += P V (bf16x3), V fragments preloaded, pass-major ----
#pragma unroll
        for (int kp = 0; kp < 8; kp++) {
            u32 ah[4], al[4];
            split2(sf[2 * kp][0],     sf[2 * kp][1],     ah[0], al[0]);
            split2(sf[2 * kp][2],     sf[2 * kp][3],     ah[1], al[1]);
            split2(sf[2 * kp + 1][0], sf[2 * kp + 1][1], ah[2], al[2]);
            split2(sf[2 * kp + 1][2], sf[2 * kp + 1][3], ah[3], al[3]);
            u32 bvh[4][4], bvl[4][4];
#pragma unroll
            for (int dt = 0; dt < 4; dt++) {
                u32 off = ((kp * 16 + vrow) * FA_RS + dt * 16 + vch * 8) * 2;
                ldsm_x4t(bvh[dt][0], bvh[dt][1], bvh[dt][2], bvh[dt][3],
                         stb + 2 * FA_ARR * 2 + off);
                ldsm_x4t(bvl[dt][0], bvl[dt][1], bvl[dt][2], bvl[dt][3],
                         stb + 3 * FA_ARR * 2 + off);
            }
#pragma unroll
            for (int dt = 0; dt < 4; dt++) {     // pass hh: 8 indep
                mma16816(of[2 * dt],     ah, &bvh[dt][0]);
                mma16816(of[2 * dt + 1], ah, &bvh[dt][2]);
            }
#pragma unroll
            for (int dt = 0; dt < 4; dt++) {     // pass lh
                mma16816(of[2 * dt],     al, &bvh[dt][0]);
                mma16816(of[2 * dt + 1], al, &bvh[dt][2]);
            }
#pragma unroll
            for (int dt = 0; dt < 4; dt++) {     // pass hl
                mma16816(of[2 * dt],     ah, &bvl[dt][0]);
                mma16816(of[2 * dt + 1], ah, &bvl[dt][2]);
            }
        }
        __syncthreads();
    }

    float inv0 = 1.f / l0, inv1 = 1.f / l1;
    const int g = lane >> 2, t2 = (lane & 3) * 2;
    size_t r0 = rowbase + qt * 128 + w * 16 + g;
#pragma unroll
    for (int j = 0; j < 8; j++) {
        int c = colbase + j * 8 + t2;
        u32 h0, lo0, h1, lo1;
        split2(of[j][0] * inv0, of[j][1] * inv0, h0, lo0);
        split2(of[j][2] * inv1, of[j][3] * inv1, h1, lo1);
        *(u32*)(oh + r0 * C_DIM + c) = h0;
        *(u32*)(ol + r0 * C_DIM + c) = lo0;
        *(u32*)(oh + (r0 + 8) * C_DIM + c) = h1;
        *(u32*)(ol + (r0 + 8) * C_DIM + c) = lo1;
    }
#undef FA_LOAD
}

// ---------------------------------------------------------------------------
extern "C" void kernel_launch(void* const* d_in, const int* in_sizes, int n_in,
                              void* d_out, int out_size)
{
    const float* x     = (const float*)d_in[0];
    const float* Wqkv  = (const float*)d_in[1];
    const float* bqkv  = (const float*)d_in[2];
    const float* Wproj = (const float*)d_in[3];
    const float* bproj = (const float*)d_in[4];
    float* out = (float*)d_out;

    __nv_bfloat16 *qh, *ql, *kh, *kl, *vh, *vl, *xh, *xl, *ah, *al;
    __nv_bfloat16 *wqh, *wql, *wph, *wpl;
    cudaGetSymbolAddress((void**)&qh, g_qh);   cudaGetSymbolAddress((void**)&ql, g_ql);
    cudaGetSymbolAddress((void**)&kh, g_kh);   cudaGetSymbolAddress((void**)&kl, g_kl);
    cudaGetSymbolAddress((void**)&vh, g_vh);   cudaGetSymbolAddress((void**)&vl, g_vl);
    cudaGetSymbolAddress((void**)&xh, g_xh);   cudaGetSymbolAddress((void**)&xl, g_xl);
    cudaGetSymbolAddress((void**)&ah, g_ah);   cudaGetSymbolAddress((void**)&al, g_al);
    cudaGetSymbolAddress((void**)&wqh, g_wqh); cudaGetSymbolAddress((void**)&wql, g_wql);
    cudaGetSymbolAddress((void**)&wph, g_wph); cudaGetSymbolAddress((void**)&wpl, g_wpl);

    cudaFuncSetAttribute(gemm_mma_kernel<0>,
                         cudaFuncAttributeMaxDynamicSharedMemorySize, GSMEM);
    cudaFuncSetAttribute(gemm_mma_kernel<1>,
                         cudaFuncAttributeMaxDynamicSharedMemorySize, GSMEM);
    cudaFuncSetAttribute(flash_attn_mma,
                         cudaFuncAttributeMaxDynamicSharedMemorySize, FA_SMEM);

    split_kernel<<<(M_ROWS * C_DIM / 4 + 255) / 256, 256>>>(x, xh, xl, M_ROWS * C_DIM / 4);
    transpose_split_kernel<<<dim3(C3 / 32, C_DIM / 32), dim3(32, 8)>>>(Wqkv, wqh, wql, C_DIM, C3);
    transpose_split_kernel<<<dim3(C_DIM / 32, C_DIM / 32), dim3(32, 8)>>>(Wproj, wph, wpl, C_DIM, C_DIM);

    // 1) qkv projection -> bf16 hi/lo q/k/v buffers directly
    gemm_mma_kernel<1><<<dim3(C3 / 128, M_ROWS / 128), 128, GSMEM>>>(
        xh, xl, wqh, wql, bqkv, nullptr, M_ROWS, C3, C_DIM,
        qh, ql, kh, kl, vh, vl);

    // 2) attention -> bf16 hi/lo
    flash_attn_mma<<<dim3(T_SZ / 128, B_SZ * NH), 256, FA_SMEM>>>(
        qh, ql, kh, kl, vh, vl, ah, al);

    // 3) out = attn @ Wproj + bproj (fp32 out)
    gemm_mma_kernel<0><<<dim3(C_DIM / 128, M_ROWS / 128), 128, GSMEM>>>(
        ah, al, wph, wpl, bproj, out, M_ROWS, C_DIM, C_DIM,
        nullptr, nullptr, nullptr, nullptr, nullptr, nullptr);
}

// round 8
// speedup vs baseline: 1.1185x; 1.1185x over previous
#include <cuda_runtime.h>
#include <cuda_bf16.h>
#include <cuda_fp16.h>
#include <math_constants.h>

#define C_DIM 1024
#define C3    3072
#define NH    16
#define HD    64
#define B_SZ  2
#define T_SZ  2048
#define M_ROWS (B_SZ*T_SZ)

#define ATT_SCALE 0.5f
#define LOG2E 1.4426950408889634f

typedef unsigned long long u64;
typedef unsigned int u32;

// ---------------- scratch (no device allocation allowed) -------------------
__device__ __nv_bfloat16 g_qh[(size_t)M_ROWS * C_DIM];
__device__ __nv_bfloat16 g_ql[(size_t)M_ROWS * C_DIM];
__device__ __nv_bfloat16 g_kh[(size_t)M_ROWS * C_DIM];
__device__ __nv_bfloat16 g_kl[(size_t)M_ROWS * C_DIM];
__device__ __half        g_v16[(size_t)M_ROWS * C_DIM];   // V single fp16
__device__ __nv_bfloat16 g_xh[(size_t)M_ROWS * C_DIM];
__device__ __nv_bfloat16 g_xl[(size_t)M_ROWS * C_DIM];
__device__ __half        g_oh16[(size_t)M_ROWS * C_DIM];  // attn out hi (fp16)
__device__ __half        g_ol16[(size_t)M_ROWS * C_DIM];  // attn out lo (fp16)
__device__ __nv_bfloat16 g_wqh[(size_t)C3 * C_DIM];       // Wqkv^T hi [N][K]
__device__ __nv_bfloat16 g_wql[(size_t)C3 * C_DIM];
__device__ __half        g_wp16[(size_t)C_DIM * C_DIM];   // Wproj^T single fp16

// ---------------- helpers ----------------------------------------------------
__device__ __forceinline__ u32 smem_u32(const void* p) {
    u32 a; asm("{ .reg .u64 t; cvta.to.shared.u64 t, %1; cvt.u32.u64 %0, t; }"
               : "=r"(a) : "l"(p));
    return a;
}
__device__ __forceinline__ void ldsm_x4(u32& r0, u32& r1, u32& r2, u32& r3, u32 a) {
    asm volatile("ldmatrix.sync.aligned.m8n8.x4.shared.b16 {%0,%1,%2,%3}, [%4];"
                 : "=r"(r0), "=r"(r1), "=r"(r2), "=r"(r3) : "r"(a));
}
__device__ __forceinline__ void ldsm_x4t(u32& r0, u32& r1, u32& r2, u32& r3, u32 a) {
    asm volatile("ldmatrix.sync.aligned.m8n8.x4.trans.shared.b16 {%0,%1,%2,%3}, [%4];"
                 : "=r"(r0), "=r"(r1), "=r"(r2), "=r"(r3) : "r"(a));
}
__device__ __forceinline__ void mma16816(float* c, const u32* a, const u32* b) {
    asm volatile(
        "mma.sync.aligned.m16n8k16.row.col.f32.bf16.bf16.f32 "
        "{%0,%1,%2,%3},{%4,%5,%6,%7},{%8,%9},{%0,%1,%2,%3};"
        : "+f"(c[0]), "+f"(c[1]), "+f"(c[2]), "+f"(c[3])
        : "r"(a[0]), "r"(a[1]), "r"(a[2]), "r"(a[3]), "r"(b[0]), "r"(b[1]));
}
__device__ __forceinline__ void mma16816h(float* c, const u32* a, const u32* b) {
    asm volatile(
        "mma.sync.aligned.m16n8k16.row.col.f32.f16.f16.f32 "
        "{%0,%1,%2,%3},{%4,%5,%6,%7},{%8,%9},{%0,%1,%2,%3};"
        : "+f"(c[0]), "+f"(c[1]), "+f"(c[2]), "+f"(c[3])
        : "r"(a[0]), "r"(a[1]), "r"(a[2]), "r"(a[3]), "r"(b[0]), "r"(b[1]));
}
__device__ __forceinline__ float fast_exp2(float x) {
    float r; asm("ex2.approx.ftz.f32 %0, %1;" : "=f"(r) : "f"(x)); return r;
}
__device__ __forceinline__ u32 cvt_bf16x2(float lo, float hi) {
    u32 r; asm("cvt.rn.bf16x2.f32 %0, %1, %2;" : "=r"(r) : "f"(hi), "f"(lo));
    return r;
}
__device__ __forceinline__ void split2(float f0, float f1, u32& hi, u32& lo) {
    hi = cvt_bf16x2(f0, f1);
    float h0 = __uint_as_float(hi << 16);
    float h1 = __uint_as_float(hi & 0xffff0000u);
    lo = cvt_bf16x2(f0 - h0, f1 - h1);
}
__device__ __forceinline__ u32 cvt_f16x2(float lo, float hi) {
    u32 r; asm("cvt.rn.f16x2.f32 %0, %1, %2;" : "=r"(r) : "f"(hi), "f"(lo));
    return r;
}
__device__ __forceinline__ void split2h(float f0, float f1, u32& hi, u32& lo) {
    hi = cvt_f16x2(f0, f1);
    __half2 h2 = *reinterpret_cast<__half2*>(&hi);
    float2 hf = __half22float2(h2);   // .x = low half (f0h), .y = high (f1h)
    lo = cvt_f16x2(f0 - hf.x, f1 - hf.y);
}
#define CP_ASYNC16(d, s) asm volatile("cp.async.cg.shared.global [%0], [%1], 16;" :: "r"(d), "l"(s))
#define CP_COMMIT()      asm volatile("cp.async.commit_group;" ::: "memory")
#define CP_WAIT1()       asm volatile("cp.async.wait_group 1;" ::: "memory")
#define CP_WAIT0()       asm volatile("cp.async.wait_group 0;" ::: "memory")

// ---------------- prep: fp32 -> bf16 hi/lo split ----------------------------
__global__ void split_kernel(const float* __restrict__ in,
                             __nv_bfloat16* __restrict__ hi,
                             __nv_bfloat16* __restrict__ lo, int n4)
{
    int i = blockIdx.x * blockDim.x + threadIdx.x;
    if (i >= n4) return;
    float4 v = ((const float4*)in)[i];
    u32 h0, l0, h1, l1;
    split2(v.x, v.y, h0, l0);
    split2(v.z, v.w, h1, l1);
    ((uint2*)hi)[i] = make_uint2(h0, h1);
    ((uint2*)lo)[i] = make_uint2(l0, l1);
}

// ---------------- prep: W[K][N] -> W^T hi/lo bf16 [N][K] --------------------
__global__ void transpose_split_kernel(const float* __restrict__ W,
                                       __nv_bfloat16* __restrict__ Wh,
                                       __nv_bfloat16* __restrict__ Wl,
                                       int K, int N)
{
    __shared__ float ts[32][33];
    int n0 = blockIdx.x * 32, k0 = blockIdx.y * 32;
    int tx = threadIdx.x, ty = threadIdx.y;  // 32 x 8
#pragma unroll
    for (int r = 0; r < 4; r++)
        ts[ty + 8 * r][tx] = W[(size_t)(k0 + ty + 8 * r) * N + n0 + tx];
    __syncthreads();
#pragma unroll
    for (int r = 0; r < 4; r++) {
        float v = ts[tx][ty + 8 * r];
        __nv_bfloat16 h = __float2bfloat16(v);
        __nv_bfloat16 l = __float2bfloat16(v - __bfloat162float(h));
        size_t o = (size_t)(n0 + ty + 8 * r) * K + k0 + tx;
        Wh[o] = h; Wl[o] = l;
    }
}

// ---------------- prep: W[K][N] -> W^T single fp16 [N][K] -------------------
__global__ void transpose_f16_kernel(const float* __restrict__ W,
                                     __half* __restrict__ W16, int K, int N)
{
    __shared__ float ts[32][33];
    int n0 = blockIdx.x * 32, k0 = blockIdx.y * 32;
    int tx = threadIdx.x, ty = threadIdx.y;
#pragma unroll
    for (int r = 0; r < 4; r++)
        ts[ty + 8 * r][tx] = W[(size_t)(k0 + ty + 8 * r) * N + n0 + tx];
    __syncthreads();
#pragma unroll
    for (int r = 0; r < 4; r++) {
        float v = ts[tx][ty + 8 * r];
        W16[(size_t)(n0 + ty + 8 * r) * K + k0 + tx] = __float2half_rn(v);
    }
}

// ---------------- warp-MMA bf16x3 GEMM (QKV) ---------------------------------
// qkv = (xh+xl) @ (Wh+Wl)^T + bias; q,k -> bf16 hi/lo; v -> single fp16.
#define RSTRIDE 80
#define ARR_B   (128 * RSTRIDE)
#define STAGE_B (4 * ARR_B)
#define GSMEM   (2 * STAGE_B)

extern __shared__ char sm_raw[];

__global__ void __launch_bounds__(128) gemm_qkv_kernel(
    const __nv_bfloat16* __restrict__ Ah, const __nv_bfloat16* __restrict__ Al,
    const __nv_bfloat16* __restrict__ Bh, const __nv_bfloat16* __restrict__ Bl,
    const float* __restrict__ bias,
    int M, int N, int K,
    __nv_bfloat16* oq_h, __nv_bfloat16* oq_l,
    __nv_bfloat16* ok_h, __nv_bfloat16* ok_l,
    __half* ov16)
{
    const int tid = threadIdx.x, lane = tid & 31, wid = tid >> 5;
    const int warp_m = wid & 1, warp_n = wid >> 1;
    const int m0 = blockIdx.y * 128, n0 = blockIdx.x * 128;

    const int grp = lane >> 3, lrow = lane & 7;
    const int a_row = (grp & 1) * 8 + lrow, a_kb = (grp >> 1) * 16;
    const int b_row = (grp >> 1) * 8 + lrow, b_kb = (grp & 1) * 16;

    const __nv_bfloat16* srcs[4] = {Ah, Al, Bh, Bl};
    const int r0s[4] = {m0, m0, n0, n0};

    float cf[4][8][4];
#pragma unroll
    for (int tm = 0; tm < 4; tm++)
#pragma unroll
        for (int tn = 0; tn < 8; tn++)
#pragma unroll
            for (int q = 0; q < 4; q++) cf[tm][tn][q] = 0.f;

#define G_LOAD(st, k0v)                                                         \
    do {                                                                        \
        char* _b = sm_raw + (st) * STAGE_B;                                     \
        _Pragma("unroll")                                                       \
        for (int t = 0; t < 4; t++) {                                           \
            const __nv_bfloat16* _s = srcs[t] + (size_t)r0s[t] * K + (k0v);     \
            _Pragma("unroll")                                                   \
            for (int j = 0; j < 4; j++) {                                       \
                int _i = tid + j * 128;                                         \
                int _r = _i >> 2, _c = _i & 3;                                  \
                u32 _d = smem_u32(_b + t * ARR_B + _r * RSTRIDE + _c * 16);     \
                CP_ASYNC16(_d, _s + (size_t)_r * K + _c * 8);                   \
            }                                                                   \
        }                                                                       \
    } while (0)

#define COMPUTE(st)                                                             \
    do {                                                                        \
        u32 _sb = smem_u32(sm_raw) + (st) * STAGE_B;                            \
        _Pragma("unroll")                                                       \
        for (int ks = 0; ks < 2; ks++) {                                        \
            u32 afr[2][4][4], bfr[2][4][4];                                     \
            _Pragma("unroll")                                                   \
            for (int s = 0; s < 2; s++)                                         \
                _Pragma("unroll")                                               \
                for (int tm = 0; tm < 4; tm++)                                  \
                    ldsm_x4(afr[s][tm][0], afr[s][tm][1],                       \
                            afr[s][tm][2], afr[s][tm][3],                       \
                            _sb + s * ARR_B +                                   \
                            (warp_m * 64 + tm * 16 + a_row) * RSTRIDE +         \
                            ks * 32 + a_kb);                                    \
            _Pragma("unroll")                                                   \
            for (int s = 0; s < 2; s++)                                         \
                _Pragma("unroll")                                               \
                for (int t2 = 0; t2 < 4; t2++)                                  \
                    ldsm_x4(bfr[s][t2][0], bfr[s][t2][1],                       \
                            bfr[s][t2][2], bfr[s][t2][3],                       \
                            _sb + (2 + s) * ARR_B +                             \
                            (warp_n * 64 + t2 * 16 + b_row) * RSTRIDE +         \
                            ks * 32 + b_kb);                                    \
            _Pragma("unroll")                                                   \
            for (int tm = 0; tm < 4; tm++)                                      \
                _Pragma("unroll")                                               \
                for (int tn = 0; tn < 8; tn++)                                  \
                    mma16816(cf[tm][tn], afr[0][tm],                            \
                             &bfr[0][tn >> 1][(tn & 1) * 2]);                   \
            _Pragma("unroll")                                                   \
            for (int tm = 0; tm < 4; tm++)                                      \
                _Pragma("unroll")                                               \
                for (int tn = 0; tn < 8; tn++)                                  \
                    mma16816(cf[tm][tn], afr[0][tm],                            \
                             &bfr[1][tn >> 1][(tn & 1) * 2]);                   \
            _Pragma("unroll")                                                   \
            for (int tm = 0; tm < 4; tm++)                                      \
                _Pragma("unroll")                                               \
                for (int tn = 0; tn < 8; tn++)                                  \
                    mma16816(cf[tm][tn], afr[1][tm],                            \
                             &bfr[0][tn >> 1][(tn & 1) * 2]);                   \
        }                                                                       \
    } while (0)

    const int NIT = K / 32;
    G_LOAD(0, 0);
    CP_COMMIT();
    for (int it = 0; it < NIT; it++) {
        if (it + 1 < NIT) {
            G_LOAD((it + 1) & 1, (it + 1) * 32);
            CP_COMMIT();
            CP_WAIT1();
        } else {
            CP_WAIT0();
        }
        __syncthreads();
        COMPUTE(it & 1);
        __syncthreads();
    }

    const int mrow = lane >> 2, ncol = (lane & 3) * 2;
    int part = n0 >> 10;
    if (part < 2) {
        __nv_bfloat16* dh = part == 0 ? oq_h : ok_h;
        __nv_bfloat16* dl = part == 0 ? oq_l : ok_l;
#pragma unroll
        for (int tm = 0; tm < 4; tm++)
#pragma unroll
            for (int tn = 0; tn < 8; tn++) {
                int r = m0 + warp_m * 64 + tm * 16 + mrow;
                int c = n0 + warp_n * 64 + tn * 8 + ncol;
                int lc = c & 1023;
                float2 bb = *(const float2*)&bias[c];
                u32 h0, l0, h1, l1;
                split2(cf[tm][tn][0] + bb.x, cf[tm][tn][1] + bb.y, h0, l0);
                split2(cf[tm][tn][2] + bb.x, cf[tm][tn][3] + bb.y, h1, l1);
                *(u32*)(dh + (size_t)r * C_DIM + lc) = h0;
                *(u32*)(dl + (size_t)r * C_DIM + lc) = l0;
                *(u32*)(dh + (size_t)(r + 8) * C_DIM + lc) = h1;
                *(u32*)(dl + (size_t)(r + 8) * C_DIM + lc) = l1;
            }
    } else {
#pragma unroll
        for (int tm = 0; tm < 4; tm++)
#pragma unroll
            for (int tn = 0; tn < 8; tn++) {
                int r = m0 + warp_m * 64 + tm * 16 + mrow;
                int c = n0 + warp_n * 64 + tn * 8 + ncol;
                int lc = c & 1023;
                float2 bb = *(const float2*)&bias[c];
                u32 v0 = cvt_f16x2(cf[tm][tn][0] + bb.x, cf[tm][tn][1] + bb.y);
                u32 v1 = cvt_f16x2(cf[tm][tn][2] + bb.x, cf[tm][tn][3] + bb.y);
                *(u32*)(ov16 + (size_t)r * C_DIM + lc) = v0;
                *(u32*)(ov16 + (size_t)(r + 8) * C_DIM + lc) = v1;
            }
    }
#undef G_LOAD
#undef COMPUTE
}

// ---------------- fp16 2-pass GEMM (proj): C = (Ah+Al) @ B16^T + bias --------
#define STAGE3_B (3 * ARR_B)
#define G2SMEM   (2 * STAGE3_B)

__global__ void __launch_bounds__(128) gemm_proj_kernel(
    const __half* __restrict__ Ah, const __half* __restrict__ Al,
    const __half* __restrict__ B16,
    const float* __restrict__ bias, float* __restrict__ C,
    int M, int N, int K)
{
    const int tid = threadIdx.x, lane = tid & 31, wid = tid >> 5;
    const int warp_m = wid & 1, warp_n = wid >> 1;
    const int m0 = blockIdx.y * 128, n0 = blockIdx.x * 128;

    const int grp = lane >> 3, lrow = lane & 7;
    const int a_row = (grp & 1) * 8 + lrow, a_kb = (grp >> 1) * 16;
    const int b_row = (grp >> 1) * 8 + lrow, b_kb = (grp & 1) * 16;

    const __half* srcs[3] = {Ah, Al, B16};
    const int r0s[3] = {m0, m0, n0};

    float cf[4][8][4];
#pragma unroll
    for (int tm = 0; tm < 4; tm++)
#pragma unroll
        for (int tn = 0; tn < 8; tn++)
#pragma unroll
            for (int q = 0; q < 4; q++) cf[tm][tn][q] = 0.f;

#define G2_LOAD(st, k0v)                                                        \
    do {                                                                        \
        char* _b = sm_raw + (st) * STAGE3_B;                                    \
        _Pragma("unroll")                                                       \
        for (int t = 0; t < 3; t++) {                                           \
            const __half* _s = srcs[t] + (size_t)r0s[t] * K + (k0v);            \
            _Pragma("unroll")                                                   \
            for (int j = 0; j < 4; j++) {                                       \
                int _i = tid + j * 128;                                         \
                int _r = _i >> 2, _c = _i & 3;                                  \
                u32 _d = smem_u32(_b + t * ARR_B + _r * RSTRIDE + _c * 16);     \
                CP_ASYNC16(_d, _s + (size_t)_r * K + _c * 8);                   \
            }                                                                   \
        }                                                                       \
    } while (0)

#define G2_COMPUTE(st)                                                          \
    do {                                                                        \
        u32 _sb = smem_u32(sm_raw) + (st) * STAGE3_B;                           \
        _Pragma("unroll")                                                       \
        for (int ks = 0; ks < 2; ks++) {                                        \
            u32 afr[2][4][4], bfr[4][4];                                        \
            _Pragma("unroll")                                                   \
            for (int s = 0; s < 2; s++)                                         \
                _Pragma("unroll")                                               \
                for (int tm = 0; tm < 4; tm++)                                  \
                    ldsm_x4(afr[s][tm][0], afr[s][tm][1],                       \
                            afr[s][tm][2], afr[s][tm][3],                       \
                            _sb + s * ARR_B +                                   \
                            (warp_m * 64 + tm * 16 + a_row) * RSTRIDE +         \
                            ks * 32 + a_kb);                                    \
            _Pragma("unroll")                                                   \
            for (int t2 = 0; t2 < 4; t2++)                                      \
                ldsm_x4(bfr[t2][0], bfr[t2][1], bfr[t2][2], bfr[t2][3],         \
                        _sb + 2 * ARR_B +                                       \
                        (warp_n * 64 + t2 * 16 + b_row) * RSTRIDE +             \
                        ks * 32 + b_kb);                                        \
            _Pragma("unroll")                                                   \
            for (int tm = 0; tm < 4; tm++)                                      \
                _Pragma("unroll")                                               \
                for (int tn = 0; tn < 8; tn++)                                  \
                    mma16816h(cf[tm][tn], afr[0][tm],                           \
                              &bfr[tn >> 1][(tn & 1) * 2]);                     \
            _Pragma("unroll")                                                   \
            for (int tm = 0; tm < 4; tm++)                                      \
                _Pragma("unroll")                                               \
                for (int tn = 0; tn < 8; tn++)                                  \
                    mma16816h(cf[tm][tn], afr[1][tm],                           \
                              &bfr[tn >> 1][(tn & 1) * 2]);                     \
        }                                                                       \
    } while (0)

    const int NIT = K / 32;
    G2_LOAD(0, 0);
    CP_COMMIT();
    for (int it = 0; it < NIT; it++) {
        if (it + 1 < NIT) {
            G2_LOAD((it + 1) & 1, (it + 1) * 32);
            CP_COMMIT();
            CP_WAIT1();
        } else {
            CP_WAIT0();
        }
        __syncthreads();
        G2_COMPUTE(it & 1);
        __syncthreads();
    }

    const int mrow = lane >> 2, ncol = (lane & 3) * 2;
#pragma unroll
    for (int tm = 0; tm < 4; tm++)
#pragma unroll
        for (int tn = 0; tn < 8; tn++) {
            int r = m0 + warp_m * 64 + tm * 16 + mrow;
            int c = n0 + warp_n * 64 + tn * 8 + ncol;
            float2 bb = *(const float2*)&bias[c];
            *(float2*)&C[(size_t)r * N + c] =
                make_float2(cf[tm][tn][0] + bb.x, cf[tm][tn][1] + bb.y);
            *(float2*)&C[(size_t)(r + 8) * N + c] =
                make_float2(cf[tm][tn][2] + bb.x, cf[tm][tn][3] + bb.y);
        }
#undef G2_LOAD
#undef G2_COMPUTE
}

// ---------------- tensor-core flash attention -------------------------------
// S = bf16x3 (Q,K hi/lo).  PV = fp16 2-pass: (Ph+Pl) @ V16.
#define FA_RS   72
#define FA_ARR  (128 * FA_RS)
#define FA_ST0  (2 * FA_ARR)
#define FA_STSZ (3 * FA_ARR)                 // Kh, Kl, V16
#define FA_SMEM ((2 * FA_ARR + 2 * FA_STSZ) * 2)   // 147456 B

__global__ void __launch_bounds__(256) flash_attn_mma(
    const __nv_bfloat16* __restrict__ qh, const __nv_bfloat16* __restrict__ ql,
    const __nv_bfloat16* __restrict__ kh, const __nv_bfloat16* __restrict__ kl,
    const __half* __restrict__ v16,
    __half* __restrict__ oh, __half* __restrict__ ol)
{
    __nv_bfloat16* sm = (__nv_bfloat16*)sm_raw;
    const int tid = threadIdx.x, lane = tid & 31, w = tid >> 5;
    const int qt = blockIdx.x;
    const int b = blockIdx.y >> 4, h = blockIdx.y & 15;
    const size_t rowbase = (size_t)b * T_SZ;
    const int colbase = h * HD;

    const void* kvsrc[3] = {kh, kl, v16};

#define FA_LOAD(st, kt)                                                         \
    do {                                                                        \
        _Pragma("unroll")                                                       \
        for (int a4 = 0; a4 < 3; a4++) {                                        \
            _Pragma("unroll")                                                   \
            for (int j = 0; j < 4; j++) {                                       \
                int idx = tid + j * 256;                                        \
                int r = idx >> 3, c8 = idx & 7;                                 \
                u32 d = smem_u32(sm + FA_ST0 + (st) * FA_STSZ + a4 * FA_ARR +   \
                                 r * FA_RS + c8 * 8);                           \
                CP_ASYNC16(d, (const __nv_bfloat16*)kvsrc[a4] +                 \
                           (rowbase + (kt) * 128 + r) * C_DIM + colbase + c8 * 8); \
            }                                                                   \
        }                                                                       \
    } while (0)

    FA_LOAD(0, 0);
    CP_COMMIT();

    {
        const __nv_bfloat16* qsrc[2] = {qh, ql};
#pragma unroll
        for (int a2 = 0; a2 < 2; a2++)
#pragma unroll
            for (int j = 0; j < 4; j++) {
                int idx = tid + j * 256;
                int r = idx >> 3, c8 = idx & 7;
                uint4 v = *(const uint4*)(qsrc[a2] +
                    (rowbase + qt * 128 + r) * C_DIM + colbase + c8 * 8);
                *(uint4*)(sm + a2 * FA_ARR + r * FA_RS + c8 * 8) = v;
            }
    }
    __syncthreads();

    u32 qfh[4][4], qfl[4][4];
    {
        u32 qbase = smem_u32(sm);
        int arow = w * 16 + (lane & 15);
        int acol = (lane >> 4) * 8;
#pragma unroll
        for (int ks = 0; ks < 4; ks++) {
            u32 off = (arow * FA_RS + ks * 16 + acol) * 2;
            ldsm_x4(qfh[ks][0], qfh[ks][1], qfh[ks][2], qfh[ks][3], qbase + off);
            ldsm_x4(qfl[ks][0], qfl[ks][1], qfl[ks][2], qfl[ks][3],
                    qbase + FA_ARR * 2 + off);
        }
    }

    float sf[16][4];
    float of[8][4];
#pragma unroll
    for (int j = 0; j < 8; j++)
#pragma unroll
        for (int q = 0; q < 4; q++) of[j][q] = 0.f;
    float m0 = -CUDART_INF_F, m1 = -CUDART_INF_F, l0 = 0.f, l1 = 0.f;

    const u32 sbase = smem_u32(sm);
    const int krow = (lane & 7) + ((lane >> 4) << 3);
    const int kch  = (lane >> 3) & 1;
    const int vrow = (lane & 7) + (((lane >> 3) & 1) << 3);
    const int vch  = lane >> 4;
    const float sc = ATT_SCALE * LOG2E;

    for (int kt = 0; kt < T_SZ / 128; kt++) {
        if (kt + 1 < T_SZ / 128) { FA_LOAD((kt + 1) & 1, kt + 1); CP_COMMIT(); CP_WAIT1(); }
        else CP_WAIT0();
        __syncthreads();
        u32 stb = sbase + (FA_ST0 + (kt & 1) * FA_STSZ) * 2;

        // ---- S = Q K^T (bf16x3), pass-major ----
#pragma unroll
        for (int j = 0; j < 16; j++) {
            sf[j][0] = 0.f; sf[j][1] = 0.f; sf[j][2] = 0.f; sf[j][3] = 0.f;
        }
#pragma unroll
        for (int jp = 0; jp < 4; jp++) {
            u32 bh[2][4][4], bl[2][4][4];
#pragma unroll
            for (int j2 = 0; j2 < 2; j2++)
#pragma unroll
                for (int ks = 0; ks < 4; ks++) {
                    u32 off = (((jp * 2 + j2) * 16 + krow) * FA_RS +
                               ks * 16 + kch * 8) * 2;
                    ldsm_x4(bh[j2][ks][0], bh[j2][ks][1], bh[j2][ks][2], bh[j2][ks][3],
                            stb + off);
                    ldsm_x4(bl[j2][ks][0], bl[j2][ks][1], bl[j2][ks][2], bl[j2][ks][3],
                            stb + FA_ARR * 2 + off);
                }
            float* s0 = sf[4 * jp];     float* s1 = sf[4 * jp + 1];
            float* s2 = sf[4 * jp + 2]; float* s3 = sf[4 * jp + 3];
#pragma unroll
            for (int ks = 0; ks < 4; ks++) {
                mma16816(s0, qfh[ks], &bh[0][ks][0]);
                mma16816(s1, qfh[ks], &bh[0][ks][2]);
                mma16816(s2, qfh[ks], &bh[1][ks][0]);
                mma16816(s3, qfh[ks], &bh[1][ks][2]);
            }
#pragma unroll
            for (int ks = 0; ks < 4; ks++) {
                mma16816(s0, qfh[ks], &bl[0][ks][0]);
                mma16816(s1, qfh[ks], &bl[0][ks][2]);
                mma16816(s2, qfh[ks], &bl[1][ks][0]);
                mma16816(s3, qfh[ks], &bl[1][ks][2]);
            }
#pragma unroll
            for (int ks = 0; ks < 4; ks++) {
                mma16816(s0, qfl[ks], &bh[0][ks][0]);
                mma16816(s1, qfl[ks], &bh[0][ks][2]);
                mma16816(s2, qfl[ks], &bh[1][ks][0]);
                mma16816(s3, qfl[ks], &bh[1][ks][2]);
            }
        }

        // ---- online softmax ----
        float mt0 = -CUDART_INF_F, mt1 = -CUDART_INF_F;
#pragma unroll
        for (int j = 0; j < 16; j++) {
            sf[j][0] *= sc; sf[j][1] *= sc; sf[j][2] *= sc; sf[j][3] *= sc;
            mt0 = fmaxf(mt0, fmaxf(sf[j][0], sf[j][1]));
            mt1 = fmaxf(mt1, fmaxf(sf[j][2], sf[j][3]));
        }
        mt0 = fmaxf(mt0, __shfl_xor_sync(0xffffffffu, mt0, 1));
        mt0 = fmaxf(mt0, __shfl_xor_sync(0xffffffffu, mt0, 2));
        mt1 = fmaxf(mt1, __shfl_xor_sync(0xffffffffu, mt1, 1));
        mt1 = fmaxf(mt1, __shfl_xor_sync(0xffffffffu, mt1, 2));
        float mn0 = fmaxf(m0, mt0), mn1 = fmaxf(m1, mt1);
        float f0 = fast_exp2(m0 - mn0), f1 = fast_exp2(m1 - mn1);
        m0 = mn0; m1 = mn1;
        float rs0 = 0.f, rs1 = 0.f;
#pragma unroll
        for (int j = 0; j < 16; j++) {
            sf[j][0] = fast_exp2(sf[j][0] - mn0);
            sf[j][1] = fast_exp2(sf[j][1] - mn0);
            sf[j][2] = fast_exp2(sf[j][2] - mn1);
            sf[j][3] = fast_exp2(sf[j][3] - mn1);
            rs0 += sf[j][0] + sf[j][1];
            rs1 += sf[j][2] + sf[j][3];
        }
        rs0 += __shfl_xor_sync(0xffffffffu, rs0, 1);
        rs0 += __shfl_xor_sync(0xffffffffu, rs0, 2);
        rs1 += __shfl_xor_sync(0xffffffffu, rs1, 1);
        rs1 += __shfl_xor_sync(0xffffffffu, rs1, 2);
        l0 = l0 * f0 + rs0;
        l1 = l1 * f1 + rs1;
#pragma unroll
        for (int j = 0; j < 8; j++) {
            of[j][0] *= f0; of[j][1] *= f0; of[j][2] *= f1; of[j][3] *= f1;
        }

        // ---- O += P V (fp16 2-pass: Ph·V + Pl·V) ----
#pragma unroll
        for (int kp = 0; kp < 8; kp++) {
            u32 ah[4], al[4];
            split2h(sf[2 * kp][0],     sf[2 * kp][1],     ah[0], al[0]);
            split2h(sf[2 * kp][2],     sf[2 * kp][3],     ah[1], al[1]);
            split2h(sf[2 * kp + 1][0], sf[2 * kp + 1][1], ah[2], al[2]);
            split2h(sf[2 * kp + 1][2], sf[2 * kp + 1][3], ah[3], al[3]);
            u32 bv[4][4];
#pragma unroll
            for (int dt = 0; dt < 4; dt++) {
                u32 off = ((kp * 16 + vrow) * FA_RS + dt * 16 + vch * 8) * 2;
                ldsm_x4t(bv[dt][0], bv[dt][1], bv[dt][2], bv[dt][3],
                         stb + 2 * FA_ARR * 2 + off);
            }
#pragma unroll
            for (int dt = 0; dt < 4; dt++) {
                mma16816h(of[2 * dt],     ah, &bv[dt][0]);
                mma16816h(of[2 * dt + 1], ah, &bv[dt][2]);
            }
#pragma unroll
            for (int dt = 0; dt < 4; dt++) {
                mma16816h(of[2 * dt],     al, &bv[dt][0]);
                mma16816h(of[2 * dt + 1], al, &bv[dt][2]);
            }
        }
        __syncthreads();
    }

    // ---- epilogue: normalize, split to fp16 hi/lo ----
    float inv0 = 1.f / l0, inv1 = 1.f / l1;
    const int g = lane >> 2, t2 = (lane & 3) * 2;
    size_t r0 = rowbase + qt * 128 + w * 16 + g;
#pragma unroll
    for (int j = 0; j < 8; j++) {
        int c = colbase + j * 8 + t2;
        u32 h0, lo0, h1, lo1;
        split2h(of[j][0] * inv0, of[j][1] * inv0, h0, lo0);
        split2h(of[j][2] * inv1, of[j][3] * inv1, h1, lo1);
        *(u32*)(oh + r0 * C_DIM + c) = h0;
        *(u32*)(ol + r0 * C_DIM + c) = lo0;
        *(u32*)(oh + (r0 + 8) * C_DIM + c) = h1;
        *(u32*)(ol + (r0 + 8) * C_DIM + c) = lo1;
    }
#undef FA_LOAD
}

// ---------------------------------------------------------------------------
extern "C" void kernel_launch(void* const* d_in, const int* in_sizes, int n_in,
                              void* d_out, int out_size)
{
    const float* x     = (const float*)d_in[0];
    const float* Wqkv  = (const float*)d_in[1];
    const float* bqkv  = (const float*)d_in[2];
    const float* Wproj = (const float*)d_in[3];
    const float* bproj = (const float*)d_in[4];
    float* out = (float*)d_out;

    __nv_bfloat16 *qh, *ql, *kh, *kl, *xh, *xl, *wqh, *wql;
    __half *v16, *oh16, *ol16, *wp16;
    cudaGetSymbolAddress((void**)&qh, g_qh);     cudaGetSymbolAddress((void**)&ql, g_ql);
    cudaGetSymbolAddress((void**)&kh, g_kh);     cudaGetSymbolAddress((void**)&kl, g_kl);
    cudaGetSymbolAddress((void**)&v16, g_v16);
    cudaGetSymbolAddress((void**)&xh, g_xh);     cudaGetSymbolAddress((void**)&xl, g_xl);
    cudaGetSymbolAddress((void**)&oh16, g_oh16); cudaGetSymbolAddress((void**)&ol16, g_ol16);
    cudaGetSymbolAddress((void**)&wqh, g_wqh);   cudaGetSymbolAddress((void**)&wql, g_wql);
    cudaGetSymbolAddress((void**)&wp16, g_wp16);

    cudaFuncSetAttribute(gemm_qkv_kernel,
                         cudaFuncAttributeMaxDynamicSharedMemorySize, GSMEM);
    cudaFuncSetAttribute(gemm_proj_kernel,
                         cudaFuncAttributeMaxDynamicSharedMemorySize, G2SMEM);
    cudaFuncSetAttribute(flash_attn_mma,
                         cudaFuncAttributeMaxDynamicSharedMemorySize, FA_SMEM);

    split_kernel<<<(M_ROWS * C_DIM / 4 + 255) / 256, 256>>>(x, xh, xl, M_ROWS * C_DIM / 4);
    transpose_split_kernel<<<dim3(C3 / 32, C_DIM / 32), dim3(32, 8)>>>(Wqkv, wqh, wql, C_DIM, C3);
    transpose_f16_kernel<<<dim3(C_DIM / 32, C_DIM / 32), dim3(32, 8)>>>(Wproj, wp16, C_DIM, C_DIM);

    // 1) qkv projection: q,k -> bf16 hi/lo; v -> single fp16
    gemm_qkv_kernel<<<dim3(C3 / 128, M_ROWS / 128), 128, GSMEM>>>(
        xh, xl, wqh, wql, bqkv, M_ROWS, C3, C_DIM,
        qh, ql, kh, kl, v16);

    // 2) attention -> fp16 hi/lo
    flash_attn_mma<<<dim3(T_SZ / 128, B_SZ * NH), 256, FA_SMEM>>>(
        qh, ql, kh, kl, v16, oh16, ol16);

    // 3) out = attn @ Wproj + bproj (fp16 2-pass)
    gemm_proj_kernel<<<dim3(C_DIM / 128, M_ROWS / 128), 128, G2SMEM>>>(
        oh16, ol16, wp16, bproj, out, M_ROWS, C_DIM, C_DIM);
}

// round 9
// speedup vs baseline: 1.2184x; 1.0892x over previous
#include <cuda_runtime.h>
#include <cuda_bf16.h>
#include <cuda_fp16.h>
#include <math_constants.h>

#define C_DIM 1024
#define C3    3072
#define NH    16
#define HD    64
#define B_SZ  2
#define T_SZ  2048
#define M_ROWS (B_SZ*T_SZ)

#define ATT_SCALE 0.5f
#define LOG2E 1.4426950408889634f

typedef unsigned long long u64;
typedef unsigned int u32;

// ---------------- scratch (no device allocation allowed) -------------------
__device__ __half        g_q16h[(size_t)M_ROWS * C_DIM];  // Q fp16 hi
__device__ __half        g_q16l[(size_t)M_ROWS * C_DIM];  // Q fp16 lo
__device__ __half        g_k16[(size_t)M_ROWS * C_DIM];   // K single fp16
__device__ __half        g_v16[(size_t)M_ROWS * C_DIM];   // V single fp16
__device__ __nv_bfloat16 g_xh[(size_t)M_ROWS * C_DIM];
__device__ __nv_bfloat16 g_xl[(size_t)M_ROWS * C_DIM];
__device__ __half        g_oh16[(size_t)M_ROWS * C_DIM];  // attn out hi (fp16)
__device__ __half        g_ol16[(size_t)M_ROWS * C_DIM];  // attn out lo (fp16)
__device__ __nv_bfloat16 g_wqh[(size_t)C3 * C_DIM];       // Wqkv^T hi [N][K]
__device__ __nv_bfloat16 g_wql[(size_t)C3 * C_DIM];
__device__ __half        g_wp16[(size_t)C_DIM * C_DIM];   // Wproj^T single fp16

// ---------------- helpers ----------------------------------------------------
__device__ __forceinline__ u32 smem_u32(const void* p) {
    u32 a; asm("{ .reg .u64 t; cvta.to.shared.u64 t, %1; cvt.u32.u64 %0, t; }"
               : "=r"(a) : "l"(p));
    return a;
}
__device__ __forceinline__ void ldsm_x4(u32& r0, u32& r1, u32& r2, u32& r3, u32 a) {
    asm volatile("ldmatrix.sync.aligned.m8n8.x4.shared.b16 {%0,%1,%2,%3}, [%4];"
                 : "=r"(r0), "=r"(r1), "=r"(r2), "=r"(r3) : "r"(a));
}
__device__ __forceinline__ void ldsm_x4t(u32& r0, u32& r1, u32& r2, u32& r3, u32 a) {
    asm volatile("ldmatrix.sync.aligned.m8n8.x4.trans.shared.b16 {%0,%1,%2,%3}, [%4];"
                 : "=r"(r0), "=r"(r1), "=r"(r2), "=r"(r3) : "r"(a));
}
__device__ __forceinline__ void mma16816(float* c, const u32* a, const u32* b) {
    asm volatile(
        "mma.sync.aligned.m16n8k16.row.col.f32.bf16.bf16.f32 "
        "{%0,%1,%2,%3},{%4,%5,%6,%7},{%8,%9},{%0,%1,%2,%3};"
        : "+f"(c[0]), "+f"(c[1]), "+f"(c[2]), "+f"(c[3])
        : "r"(a[0]), "r"(a[1]), "r"(a[2]), "r"(a[3]), "r"(b[0]), "r"(b[1]));
}
__device__ __forceinline__ void mma16816h(float* c, const u32* a, const u32* b) {
    asm volatile(
        "mma.sync.aligned.m16n8k16.row.col.f32.f16.f16.f32 "
        "{%0,%1,%2,%3},{%4,%5,%6,%7},{%8,%9},{%0,%1,%2,%3};"
        : "+f"(c[0]), "+f"(c[1]), "+f"(c[2]), "+f"(c[3])
        : "r"(a[0]), "r"(a[1]), "r"(a[2]), "r"(a[3]), "r"(b[0]), "r"(b[1]));
}
__device__ __forceinline__ float fast_exp2(float x) {
    float r; asm("ex2.approx.ftz.f32 %0, %1;" : "=f"(r) : "f"(x)); return r;
}
__device__ __forceinline__ u32 cvt_bf16x2(float lo, float hi) {
    u32 r; asm("cvt.rn.bf16x2.f32 %0, %1, %2;" : "=r"(r) : "f"(hi), "f"(lo));
    return r;
}
__device__ __forceinline__ void split2(float f0, float f1, u32& hi, u32& lo) {
    hi = cvt_bf16x2(f0, f1);
    float h0 = __uint_as_float(hi << 16);
    float h1 = __uint_as_float(hi & 0xffff0000u);
    lo = cvt_bf16x2(f0 - h0, f1 - h1);
}
__device__ __forceinline__ u32 cvt_f16x2(float lo, float hi) {
    u32 r; asm("cvt.rn.f16x2.f32 %0, %1, %2;" : "=r"(r) : "f"(hi), "f"(lo));
    return r;
}
__device__ __forceinline__ void split2h(float f0, float f1, u32& hi, u32& lo) {
    hi = cvt_f16x2(f0, f1);
    __half2 h2 = *reinterpret_cast<__half2*>(&hi);
    float2 hf = __half22float2(h2);
    lo = cvt_f16x2(f0 - hf.x, f1 - hf.y);
}
#define CP_ASYNC16(d, s) asm volatile("cp.async.cg.shared.global [%0], [%1], 16;" :: "r"(d), "l"(s))
#define CP_COMMIT()      asm volatile("cp.async.commit_group;" ::: "memory")
#define CP_WAIT1()       asm volatile("cp.async.wait_group 1;" ::: "memory")
#define CP_WAIT0()       asm volatile("cp.async.wait_group 0;" ::: "memory")

// ---------------- prep: fp32 -> bf16 hi/lo split ----------------------------
__global__ void split_kernel(const float* __restrict__ in,
                             __nv_bfloat16* __restrict__ hi,
                             __nv_bfloat16* __restrict__ lo, int n4)
{
    int i = blockIdx.x * blockDim.x + threadIdx.x;
    if (i >= n4) return;
    float4 v = ((const float4*)in)[i];
    u32 h0, l0, h1, l1;
    split2(v.x, v.y, h0, l0);
    split2(v.z, v.w, h1, l1);
    ((uint2*)hi)[i] = make_uint2(h0, h1);
    ((uint2*)lo)[i] = make_uint2(l0, l1);
}

// ---------------- prep: W[K][N] -> W^T hi/lo bf16 [N][K] --------------------
__global__ void transpose_split_kernel(const float* __restrict__ W,
                                       __nv_bfloat16* __restrict__ Wh,
                                       __nv_bfloat16* __restrict__ Wl,
                                       int K, int N)
{
    __shared__ float ts[32][33];
    int n0 = blockIdx.x * 32, k0 = blockIdx.y * 32;
    int tx = threadIdx.x, ty = threadIdx.y;  // 32 x 8
#pragma unroll
    for (int r = 0; r < 4; r++)
        ts[ty + 8 * r][tx] = W[(size_t)(k0 + ty + 8 * r) * N + n0 + tx];
    __syncthreads();
#pragma unroll
    for (int r = 0; r < 4; r++) {
        float v = ts[tx][ty + 8 * r];
        __nv_bfloat16 h = __float2bfloat16(v);
        __nv_bfloat16 l = __float2bfloat16(v - __bfloat162float(h));
        size_t o = (size_t)(n0 + ty + 8 * r) * K + k0 + tx;
        Wh[o] = h; Wl[o] = l;
    }
}

// ---------------- prep: W[K][N] -> W^T single fp16 [N][K] -------------------
__global__ void transpose_f16_kernel(const float* __restrict__ W,
                                     __half* __restrict__ W16, int K, int N)
{
    __shared__ float ts[32][33];
    int n0 = blockIdx.x * 32, k0 = blockIdx.y * 32;
    int tx = threadIdx.x, ty = threadIdx.y;
#pragma unroll
    for (int r = 0; r < 4; r++)
        ts[ty + 8 * r][tx] = W[(size_t)(k0 + ty + 8 * r) * N + n0 + tx];
    __syncthreads();
#pragma unroll
    for (int r = 0; r < 4; r++) {
        float v = ts[tx][ty + 8 * r];
        W16[(size_t)(n0 + ty + 8 * r) * K + k0 + tx] = __float2half_rn(v);
    }
}

// ---------------- warp-MMA bf16x3 GEMM (QKV) ---------------------------------
// qkv = (xh+xl) @ (Wh+Wl)^T + bias
// q -> fp16 hi/lo; k -> single fp16; v -> single fp16.
#define RSTRIDE 80
#define ARR_B   (128 * RSTRIDE)
#define STAGE_B (4 * ARR_B)
#define GSMEM   (2 * STAGE_B)

extern __shared__ char sm_raw[];

__global__ void __launch_bounds__(128) gemm_qkv_kernel(
    const __nv_bfloat16* __restrict__ Ah, const __nv_bfloat16* __restrict__ Al,
    const __nv_bfloat16* __restrict__ Bh, const __nv_bfloat16* __restrict__ Bl,
    const float* __restrict__ bias,
    int M, int N, int K,
    __half* oq_h, __half* oq_l, __half* ok16, __half* ov16)
{
    const int tid = threadIdx.x, lane = tid & 31, wid = tid >> 5;
    const int warp_m = wid & 1, warp_n = wid >> 1;
    const int m0 = blockIdx.y * 128, n0 = blockIdx.x * 128;

    const int grp = lane >> 3, lrow = lane & 7;
    const int a_row = (grp & 1) * 8 + lrow, a_kb = (grp >> 1) * 16;
    const int b_row = (grp >> 1) * 8 + lrow, b_kb = (grp & 1) * 16;

    const __nv_bfloat16* srcs[4] = {Ah, Al, Bh, Bl};
    const int r0s[4] = {m0, m0, n0, n0};

    float cf[4][8][4];
#pragma unroll
    for (int tm = 0; tm < 4; tm++)
#pragma unroll
        for (int tn = 0; tn < 8; tn++)
#pragma unroll
            for (int q = 0; q < 4; q++) cf[tm][tn][q] = 0.f;

#define G_LOAD(st, k0v)                                                         \
    do {                                                                        \
        char* _b = sm_raw + (st) * STAGE_B;                                     \
        _Pragma("unroll")                                                       \
        for (int t = 0; t < 4; t++) {                                           \
            const __nv_bfloat16* _s = srcs[t] + (size_t)r0s[t] * K + (k0v);     \
            _Pragma("unroll")                                                   \
            for (int j = 0; j < 4; j++) {                                       \
                int _i = tid + j * 128;                                         \
                int _r = _i >> 2, _c = _i & 3;                                  \
                u32 _d = smem_u32(_b + t * ARR_B + _r * RSTRIDE + _c * 16);     \
                CP_ASYNC16(_d, _s + (size_t)_r * K + _c * 8);                   \
            }                                                                   \
        }                                                                       \
    } while (0)

#define COMPUTE(st)                                                             \
    do {                                                                        \
        u32 _sb = smem_u32(sm_raw) + (st) * STAGE_B;                            \
        _Pragma("unroll")                                                       \
        for (int ks = 0; ks < 2; ks++) {                                        \
            u32 afr[2][4][4], bfr[2][4][4];                                     \
            _Pragma("unroll")                                                   \
            for (int s = 0; s < 2; s++)                                         \
                _Pragma("unroll")                                               \
                for (int tm = 0; tm < 4; tm++)                                  \
                    ldsm_x4(afr[s][tm][0], afr[s][tm][1],                       \
                            afr[s][tm][2], afr[s][tm][3],                       \
                            _sb + s * ARR_B +                                   \
                            (warp_m * 64 + tm * 16 + a_row) * RSTRIDE +         \
                            ks * 32 + a_kb);                                    \
            _Pragma("unroll")                                                   \
            for (int s = 0; s < 2; s++)                                         \
                _Pragma("unroll")                                               \
                for (int t2 = 0; t2 < 4; t2++)                                  \
                    ldsm_x4(bfr[s][t2][0], bfr[s][t2][1],                       \
                            bfr[s][t2][2], bfr[s][t2][3],                       \
                            _sb + (2 + s) * ARR_B +                             \
                            (warp_n * 64 + t2 * 16 + b_row) * RSTRIDE +         \
                            ks * 32 + b_kb);                                    \
            _Pragma("unroll")                                                   \
            for (int tm = 0; tm < 4; tm++)                                      \
                _Pragma("unroll")                                               \
                for (int tn = 0; tn < 8; tn++)                                  \
                    mma16816(cf[tm][tn], afr[0][tm],                            \
                             &bfr[0][tn >> 1][(tn & 1) * 2]);                   \
            _Pragma("unroll")                                                   \
            for (int tm = 0; tm < 4; tm++)                                      \
                _Pragma("unroll")                                               \
                for (int tn = 0; tn < 8; tn++)                                  \
                    mma16816(cf[tm][tn], afr[0][tm],                            \
                             &bfr[1][tn >> 1][(tn & 1) * 2]);                   \
            _Pragma("unroll")                                                   \
            for (int tm = 0; tm < 4; tm++)                                      \
                _Pragma("unroll")                                               \
                for (int tn = 0; tn < 8; tn++)                                  \
                    mma16816(cf[tm][tn], afr[1][tm],                            \
                             &bfr[0][tn >> 1][(tn & 1) * 2]);                   \
        }                                                                       \
    } while (0)

    const int NIT = K / 32;
    G_LOAD(0, 0);
    CP_COMMIT();
    for (int it = 0; it < NIT; it++) {
        if (it + 1 < NIT) {
            G_LOAD((it + 1) & 1, (it + 1) * 32);
            CP_COMMIT();
            CP_WAIT1();
        } else {
            CP_WAIT0();
        }
        __syncthreads();
        COMPUTE(it & 1);
        __syncthreads();
    }

    const int mrow = lane >> 2, ncol = (lane & 3) * 2;
    int part = n0 >> 10;
    if (part == 0) {
        // Q: fp16 hi/lo split
#pragma unroll
        for (int tm = 0; tm < 4; tm++)
#pragma unroll
            for (int tn = 0; tn < 8; tn++) {
                int r = m0 + warp_m * 64 + tm * 16 + mrow;
                int c = n0 + warp_n * 64 + tn * 8 + ncol;
                int lc = c & 1023;
                float2 bb = *(const float2*)&bias[c];
                u32 h0, l0, h1, l1;
                split2h(cf[tm][tn][0] + bb.x, cf[tm][tn][1] + bb.y, h0, l0);
                split2h(cf[tm][tn][2] + bb.x, cf[tm][tn][3] + bb.y, h1, l1);
                *(u32*)(oq_h + (size_t)r * C_DIM + lc) = h0;
                *(u32*)(oq_l + (size_t)r * C_DIM + lc) = l0;
                *(u32*)(oq_h + (size_t)(r + 8) * C_DIM + lc) = h1;
                *(u32*)(oq_l + (size_t)(r + 8) * C_DIM + lc) = l1;
            }
    } else {
        // K / V: single fp16
        __half* dst = part == 1 ? ok16 : ov16;
#pragma unroll
        for (int tm = 0; tm < 4; tm++)
#pragma unroll
            for (int tn = 0; tn < 8; tn++) {
                int r = m0 + warp_m * 64 + tm * 16 + mrow;
                int c = n0 + warp_n * 64 + tn * 8 + ncol;
                int lc = c & 1023;
                float2 bb = *(const float2*)&bias[c];
                u32 v0 = cvt_f16x2(cf[tm][tn][0] + bb.x, cf[tm][tn][1] + bb.y);
                u32 v1 = cvt_f16x2(cf[tm][tn][2] + bb.x, cf[tm][tn][3] + bb.y);
                *(u32*)(dst + (size_t)r * C_DIM + lc) = v0;
                *(u32*)(dst + (size_t)(r + 8) * C_DIM + lc) = v1;
            }
    }
#undef G_LOAD
#undef COMPUTE
}

// ---------------- fp16 2-pass GEMM (proj): C = (Ah+Al) @ B16^T + bias --------
#define STAGE3_B (3 * ARR_B)
#define G2SMEM   (2 * STAGE3_B)

__global__ void __launch_bounds__(128) gemm_proj_kernel(
    const __half* __restrict__ Ah, const __half* __restrict__ Al,
    const __half* __restrict__ B16,
    const float* __restrict__ bias, float* __restrict__ C,
    int M, int N, int K)
{
    const int tid = threadIdx.x, lane = tid & 31, wid = tid >> 5;
    const int warp_m = wid & 1, warp_n = wid >> 1;
    const int m0 = blockIdx.y * 128, n0 = blockIdx.x * 128;

    const int grp = lane >> 3, lrow = lane & 7;
    const int a_row = (grp & 1) * 8 + lrow, a_kb = (grp >> 1) * 16;
    const int b_row = (grp >> 1) * 8 + lrow, b_kb = (grp & 1) * 16;

    const __half* srcs[3] = {Ah, Al, B16};
    const int r0s[3] = {m0, m0, n0};

    float cf[4][8][4];
#pragma unroll
    for (int tm = 0; tm < 4; tm++)
#pragma unroll
        for (int tn = 0; tn < 8; tn++)
#pragma unroll
            for (int q = 0; q < 4; q++) cf[tm][tn][q] = 0.f;

#define G2_LOAD(st, k0v)                                                        \
    do {                                                                        \
        char* _b = sm_raw + (st) * STAGE3_B;                                    \
        _Pragma("unroll")                                                       \
        for (int t = 0; t < 3; t++) {                                           \
            const __half* _s = srcs[t] + (size_t)r0s[t] * K + (k0v);            \
            _Pragma("unroll")                                                   \
            for (int j = 0; j < 4; j++) {                                       \
                int _i = tid + j * 128;                                         \
                int _r = _i >> 2, _c = _i & 3;                                  \
                u32 _d = smem_u32(_b + t * ARR_B + _r * RSTRIDE + _c * 16);     \
                CP_ASYNC16(_d, _s + (size_t)_r * K + _c * 8);                   \
            }                                                                   \
        }                                                                       \
    } while (0)

#define G2_COMPUTE(st)                                                          \
    do {                                                                        \
        u32 _sb = smem_u32(sm_raw) + (st) * STAGE3_B;                           \
        _Pragma("unroll")                                                       \
        for (int ks = 0; ks < 2; ks++) {                                        \
            u32 afr[2][4][4], bfr[4][4];                                        \
            _Pragma("unroll")                                                   \
            for (int s = 0; s < 2; s++)                                         \
                _Pragma("unroll")                                               \
                for (int tm = 0; tm < 4; tm++)                                  \
                    ldsm_x4(afr[s][tm][0], afr[s][tm][1],                       \
                            afr[s][tm][2], afr[s][tm][3],                       \
                            _sb + s * ARR_B +                                   \
                            (warp_m * 64 + tm * 16 + a_row) * RSTRIDE +         \
                            ks * 32 + a_kb);                                    \
            _Pragma("unroll")                                                   \
            for (int t2 = 0; t2 < 4; t2++)                                      \
                ldsm_x4(bfr[t2][0], bfr[t2][1], bfr[t2][2], bfr[t2][3],         \
                        _sb + 2 * ARR_B +                                       \
                        (warp_n * 64 + t2 * 16 + b_row) * RSTRIDE +             \
                        ks * 32 + b_kb);                                        \
            _Pragma("unroll")                                                   \
            for (int tm = 0; tm < 4; tm++)                                      \
                _Pragma("unroll")                                               \
                for (int tn = 0; tn < 8; tn++)                                  \
                    mma16816h(cf[tm][tn], afr[0][tm],                           \
                              &bfr[tn >> 1][(tn & 1) * 2]);                     \
            _Pragma("unroll")                                                   \
            for (int tm = 0; tm < 4; tm++)                                      \
                _Pragma("unroll")                                               \
                for (int tn = 0; tn < 8; tn++)                                  \
                    mma16816h(cf[tm][tn], afr[1][tm],                           \
                              &bfr[tn >> 1][(tn & 1) * 2]);                     \
        }                                                                       \
    } while (0)

    const int NIT = K / 32;
    G2_LOAD(0, 0);
    CP_COMMIT();
    for (int it = 0; it < NIT; it++) {
        if (it + 1 < NIT) {
            G2_LOAD((it + 1) & 1, (it + 1) * 32);
            CP_COMMIT();
            CP_WAIT1();
        } else {
            CP_WAIT0();
        }
        __syncthreads();
        G2_COMPUTE(it & 1);
        __syncthreads();
    }

    const int mrow = lane >> 2, ncol = (lane & 3) * 2;
#pragma unroll
    for (int tm = 0; tm < 4; tm++)
#pragma unroll
        for (int tn = 0; tn < 8; tn++) {
            int r = m0 + warp_m * 64 + tm * 16 + mrow;
            int c = n0 + warp_n * 64 + tn * 8 + ncol;
            float2 bb = *(const float2*)&bias[c];
            *(float2*)&C[(size_t)r * N + c] =
                make_float2(cf[tm][tn][0] + bb.x, cf[tm][tn][1] + bb.y);
            *(float2*)&C[(size_t)(r + 8) * N + c] =
                make_float2(cf[tm][tn][2] + bb.x, cf[tm][tn][3] + bb.y);
        }
#undef G2_LOAD
#undef G2_COMPUTE
}

// ---------------- tensor-core flash attention -------------------------------
// S = (Qh+Ql) @ K16^T (fp16 2-pass).  PV = (Ph+Pl) @ V16 (fp16 2-pass).
#define FA_RS   72
#define FA_ARR  (128 * FA_RS)
#define FA_ST0  (2 * FA_ARR)
#define FA_STSZ (2 * FA_ARR)                 // K16, V16
#define FA_SMEM ((2 * FA_ARR + 2 * FA_STSZ) * 2)   // 110592 B

__global__ void __launch_bounds__(256) flash_attn_mma(
    const __half* __restrict__ qh, const __half* __restrict__ ql,
    const __half* __restrict__ k16, const __half* __restrict__ v16,
    __half* __restrict__ oh, __half* __restrict__ ol)
{
    __half* sm = (__half*)sm_raw;
    const int tid = threadIdx.x, lane = tid & 31, w = tid >> 5;
    const int qt = blockIdx.x;
    const int b = blockIdx.y >> 4, h = blockIdx.y & 15;
    const size_t rowbase = (size_t)b * T_SZ;
    const int colbase = h * HD;

    const __half* kvsrc[2] = {k16, v16};

#define FA_LOAD(st, kt)                                                         \
    do {                                                                        \
        _Pragma("unroll")                                                       \
        for (int a4 = 0; a4 < 2; a4++) {                                        \
            _Pragma("unroll")                                                   \
            for (int j = 0; j < 4; j++) {                                       \
                int idx = tid + j * 256;                                        \
                int r = idx >> 3, c8 = idx & 7;                                 \
                u32 d = smem_u32(sm + FA_ST0 + (st) * FA_STSZ + a4 * FA_ARR +   \
                                 r * FA_RS + c8 * 8);                           \
                CP_ASYNC16(d, kvsrc[a4] +                                       \
                           (rowbase + (kt) * 128 + r) * C_DIM + colbase + c8 * 8); \
            }                                                                   \
        }                                                                       \
    } while (0)

    FA_LOAD(0, 0);
    CP_COMMIT();

    {
        const __half* qsrc[2] = {qh, ql};
#pragma unroll
        for (int a2 = 0; a2 < 2; a2++)
#pragma unroll
            for (int j = 0; j < 4; j++) {
                int idx = tid + j * 256;
                int r = idx >> 3, c8 = idx & 7;
                uint4 v = *(const uint4*)(qsrc[a2] +
                    (rowbase + qt * 128 + r) * C_DIM + colbase + c8 * 8);
                *(uint4*)(sm + a2 * FA_ARR + r * FA_RS + c8 * 8) = v;
            }
    }
    __syncthreads();

    u32 qfh[4][4], qfl[4][4];
    {
        u32 qbase = smem_u32(sm);
        int arow = w * 16 + (lane & 15);
        int acol = (lane >> 4) * 8;
#pragma unroll
        for (int ks = 0; ks < 4; ks++) {
            u32 off = (arow * FA_RS + ks * 16 + acol) * 2;
            ldsm_x4(qfh[ks][0], qfh[ks][1], qfh[ks][2], qfh[ks][3], qbase + off);
            ldsm_x4(qfl[ks][0], qfl[ks][1], qfl[ks][2], qfl[ks][3],
                    qbase + FA_ARR * 2 + off);
        }
    }

    float sf[16][4];
    float of[8][4];
#pragma unroll
    for (int j = 0; j < 8; j++)
#pragma unroll
        for (int q = 0; q < 4; q++) of[j][q] = 0.f;
    float m0 = -CUDART_INF_F, m1 = -CUDART_INF_F, l0 = 0.f, l1 = 0.f;

    const u32 sbase = smem_u32(sm);
    const int krow = (lane & 7) + ((lane >> 4) << 3);
    const int kch  = (lane >> 3) & 1;
    const int vrow = (lane & 7) + (((lane >> 3) & 1) << 3);
    const int vch  = lane >> 4;
    const float sc = ATT_SCALE * LOG2E;

    for (int kt = 0; kt < T_SZ / 128; kt++) {
        if (kt + 1 < T_SZ / 128) { FA_LOAD((kt + 1) & 1, kt + 1); CP_COMMIT(); CP_WAIT1(); }
        else CP_WAIT0();
        __syncthreads();
        u32 stb = sbase + (FA_ST0 + (kt & 1) * FA_STSZ) * 2;

        // ---- S = Q K^T (fp16 2-pass: Qh·K + Ql·K), pass-major ----
#pragma unroll
        for (int j = 0; j < 16; j++) {
            sf[j][0] = 0.f; sf[j][1] = 0.f; sf[j][2] = 0.f; sf[j][3] = 0.f;
        }
#pragma unroll
        for (int jp = 0; jp < 4; jp++) {
            u32 bh[2][4][4];
#pragma unroll
            for (int j2 = 0; j2 < 2; j2++)
#pragma unroll
                for (int ks = 0; ks < 4; ks++) {
                    u32 off = (((jp * 2 + j2) * 16 + krow) * FA_RS +
                               ks * 16 + kch * 8) * 2;
                    ldsm_x4(bh[j2][ks][0], bh[j2][ks][1], bh[j2][ks][2], bh[j2][ks][3],
                            stb + off);
                }
            float* s0 = sf[4 * jp];     float* s1 = sf[4 * jp + 1];
            float* s2 = sf[4 * jp + 2]; float* s3 = sf[4 * jp + 3];
#pragma unroll
            for (int ks = 0; ks < 4; ks++) {
                mma16816h(s0, qfh[ks], &bh[0][ks][0]);
                mma16816h(s1, qfh[ks], &bh[0][ks][2]);
                mma16816h(s2, qfh[ks], &bh[1][ks][0]);
                mma16816h(s3, qfh[ks], &bh[1][ks][2]);
            }
#pragma unroll
            for (int ks = 0; ks < 4; ks++) {
                mma16816h(s0, qfl[ks], &bh[0][ks][0]);
                mma16816h(s1, qfl[ks], &bh[0][ks][2]);
                mma16816h(s2, qfl[ks], &bh[1][ks][0]);
                mma16816h(s3, qfl[ks], &bh[1][ks][2]);
            }
        }

        // ---- online softmax ----
        float mt0 = -CUDART_INF_F, mt1 = -CUDART_INF_F;
#pragma unroll
        for (int j = 0; j < 16; j++) {
            sf[j][0] *= sc; sf[j][1] *= sc; sf[j][2] *= sc; sf[j][3] *= sc;
            mt0 = fmaxf(mt0, fmaxf(sf[j][0], sf[j][1]));
            mt1 = fmaxf(mt1, fmaxf(sf[j][2], sf[j][3]));
        }
        mt0 = fmaxf(mt0, __shfl_xor_sync(0xffffffffu, mt0, 1));
        mt0 = fmaxf(mt0, __shfl_xor_sync(0xffffffffu, mt0, 2));
        mt1 = fmaxf(mt1, __shfl_xor_sync(0xffffffffu, mt1, 1));
        mt1 = fmaxf(mt1, __shfl_xor_sync(0xffffffffu, mt1, 2));
        float mn0 = fmaxf(m0, mt0), mn1 = fmaxf(m1, mt1);
        float f0 = fast_exp2(m0 - mn0), f1 = fast_exp2(m1 - mn1);
        m0 = mn0; m1 = mn1;
        float rs0 = 0.f, rs1 = 0.f;
#pragma unroll
        for (int j = 0; j < 16; j++) {
            sf[j][0] = fast_exp2(sf[j][0] - mn0);
            sf[j][1] = fast_exp2(sf[j][1] - mn0);
            sf[j][2] = fast_exp2(sf[j][2] - mn1);
            sf[j][3] = fast_exp2(sf[j][3] - mn1);
            rs0 += sf[j][0] + sf[j][1];
            rs1 += sf[j][2] + sf[j][3];
        }
        rs0 += __shfl_xor_sync(0xffffffffu, rs0, 1);
        rs0 += __shfl_xor_sync(0xffffffffu, rs0, 2);
        rs1 += __shfl_xor_sync(0xffffffffu, rs1, 1);
        rs1 += __shfl_xor_sync(0xffffffffu, rs1, 2);
        l0 = l0 * f0 + rs0;
        l1 = l1 * f1 + rs1;
#pragma unroll
        for (int j = 0; j < 8; j++) {
            of[j][0] *= f0; of[j][1] *= f0; of[j][2] *= f1; of[j][3] *= f1;
        }

        // ---- O += P V (fp16 2-pass: Ph·V + Pl·V) ----
#pragma unroll
        for (int kp = 0; kp < 8; kp++) {
            u32 ah[4], al[4];
            split2h(sf[2 * kp][0],     sf[2 * kp][1],     ah[0], al[0]);
            split2h(sf[2 * kp][2],     sf[2 * kp][3],     ah[1], al[1]);
            split2h(sf[2 * kp + 1][0], sf[2 * kp + 1][1], ah[2], al[2]);
            split2h(sf[2 * kp + 1][2], sf[2 * kp + 1][3], ah[3], al[3]);
            u32 bv[4][4];
#pragma unroll
            for (int dt = 0; dt < 4; dt++) {
                u32 off = ((kp * 16 + vrow) * FA_RS + dt * 16 + vch * 8) * 2;
                ldsm_x4t(bv[dt][0], bv[dt][1], bv[dt][2], bv[dt][3],
                         stb + FA_ARR * 2 + off);
            }
#pragma unroll
            for (int dt = 0; dt < 4; dt++) {
                mma16816h(of[2 * dt],     ah, &bv[dt][0]);
                mma16816h(of[2 * dt + 1], ah, &bv[dt][2]);
            }
#pragma unroll
            for (int dt = 0; dt < 4; dt++) {
                mma16816h(of[2 * dt],     al, &bv[dt][0]);
                mma16816h(of[2 * dt + 1], al, &bv[dt][2]);
            }
        }
        __syncthreads();
    }

    // ---- epilogue: normalize, split to fp16 hi/lo ----
    float inv0 = 1.f / l0, inv1 = 1.f / l1;
    const int g = lane >> 2, t2 = (lane & 3) * 2;
    size_t r0 = rowbase + qt * 128 + w * 16 + g;
#pragma unroll
    for (int j = 0; j < 8; j++) {
        int c = colbase + j * 8 + t2;
        u32 h0, lo0, h1, lo1;
        split2h(of[j][0] * inv0, of[j][1] * inv0, h0, lo0);
        split2h(of[j][2] * inv1, of[j][3] * inv1, h1, lo1);
        *(u32*)(oh + r0 * C_DIM + c) = h0;
        *(u32*)(ol + r0 * C_DIM + c) = lo0;
        *(u32*)(oh + (r0 + 8) * C_DIM + c) = h1;
        *(u32*)(ol + (r0 + 8) * C_DIM + c) = lo1;
    }
#undef FA_LOAD
}

// ---------------------------------------------------------------------------
extern "C" void kernel_launch(void* const* d_in, const int* in_sizes, int n_in,
                              void* d_out, int out_size)
{
    const float* x     = (const float*)d_in[0];
    const float* Wqkv  = (const float*)d_in[1];
    const float* bqkv  = (const float*)d_in[2];
    const float* Wproj = (const float*)d_in[3];
    const float* bproj = (const float*)d_in[4];
    float* out = (float*)d_out;

    __nv_bfloat16 *xh, *xl, *wqh, *wql;
    __half *q16h, *q16l, *k16, *v16, *oh16, *ol16, *wp16;
    cudaGetSymbolAddress((void**)&q16h, g_q16h); cudaGetSymbolAddress((void**)&q16l, g_q16l);
    cudaGetSymbolAddress((void**)&k16, g_k16);   cudaGetSymbolAddress((void**)&v16, g_v16);
    cudaGetSymbolAddress((void**)&xh, g_xh);     cudaGetSymbolAddress((void**)&xl, g_xl);
    cudaGetSymbolAddress((void**)&oh16, g_oh16); cudaGetSymbolAddress((void**)&ol16, g_ol16);
    cudaGetSymbolAddress((void**)&wqh, g_wqh);   cudaGetSymbolAddress((void**)&wql, g_wql);
    cudaGetSymbolAddress((void**)&wp16, g_wp16);

    cudaFuncSetAttribute(gemm_qkv_kernel,
                         cudaFuncAttributeMaxDynamicSharedMemorySize, GSMEM);
    cudaFuncSetAttribute(gemm_proj_kernel,
                         cudaFuncAttributeMaxDynamicSharedMemorySize, G2SMEM);
    cudaFuncSetAttribute(flash_attn_mma,
                         cudaFuncAttributeMaxDynamicSharedMemorySize, FA_SMEM);

    split_kernel<<<(M_ROWS * C_DIM / 4 + 255) / 256, 256>>>(x, xh, xl, M_ROWS * C_DIM / 4);
    transpose_split_kernel<<<dim3(C3 / 32, C_DIM / 32), dim3(32, 8)>>>(Wqkv, wqh, wql, C_DIM, C3);
    transpose_f16_kernel<<<dim3(C_DIM / 32, C_DIM / 32), dim3(32, 8)>>>(Wproj, wp16, C_DIM, C_DIM);

    // 1) qkv projection: q -> fp16 hi/lo; k, v -> single fp16
    gemm_qkv_kernel<<<dim3(C3 / 128, M_ROWS / 128), 128, GSMEM>>>(
        xh, xl, wqh, wql, bqkv, M_ROWS, C3, C_DIM,
        q16h, q16l, k16, v16);

    // 2) attention -> fp16 hi/lo
    flash_attn_mma<<<dim3(T_SZ / 128, B_SZ * NH), 256, FA_SMEM>>>(
        q16h, q16l, k16, v16, oh16, ol16);

    // 3) out = attn @ Wproj + bproj (fp16 2-pass)
    gemm_proj_kernel<<<dim3(C_DIM / 128, M_ROWS / 128), 128, G2SMEM>>>(
        oh16, ol16, wp16, bproj, out, M_ROWS, C_DIM, C_DIM);
}

// round 10
// speedup vs baseline: 1.4268x; 1.1711x over previous
#include <cuda_runtime.h>
#include <cuda_bf16.h>
#include <cuda_fp16.h>
#include <math_constants.h>

#define C_DIM 1024
#define C3    3072
#define NH    16
#define HD    64
#define B_SZ  2
#define T_SZ  2048
#define M_ROWS (B_SZ*T_SZ)

#define ATT_SCALE 0.5f
#define LOG2E 1.4426950408889634f

typedef unsigned long long u64;
typedef unsigned int u32;

// ---------------- scratch (no device allocation allowed) -------------------
__device__ __half g_q16h[(size_t)M_ROWS * C_DIM];   // Q fp16 hi
__device__ __half g_q16l[(size_t)M_ROWS * C_DIM];   // Q fp16 lo
__device__ __half g_k16[(size_t)M_ROWS * C_DIM];    // K single fp16
__device__ __half g_v16[(size_t)M_ROWS * C_DIM];    // V single fp16
__device__ __half g_xh16[(size_t)M_ROWS * C_DIM];   // x fp16 hi
__device__ __half g_xl16[(size_t)M_ROWS * C_DIM];   // x fp16 lo
__device__ __half g_oh16[(size_t)M_ROWS * C_DIM];   // attn out hi (fp16)
__device__ __half g_ol16[(size_t)M_ROWS * C_DIM];   // attn out lo (fp16)
__device__ __half g_wq16[(size_t)C3 * C_DIM];       // Wqkv^T single fp16 [N][K]
__device__ __half g_wp16[(size_t)C_DIM * C_DIM];    // Wproj^T single fp16

// ---------------- helpers ----------------------------------------------------
__device__ __forceinline__ u32 smem_u32(const void* p) {
    u32 a; asm("{ .reg .u64 t; cvta.to.shared.u64 t, %1; cvt.u32.u64 %0, t; }"
               : "=r"(a) : "l"(p));
    return a;
}
__device__ __forceinline__ void ldsm_x4(u32& r0, u32& r1, u32& r2, u32& r3, u32 a) {
    asm volatile("ldmatrix.sync.aligned.m8n8.x4.shared.b16 {%0,%1,%2,%3}, [%4];"
                 : "=r"(r0), "=r"(r1), "=r"(r2), "=r"(r3) : "r"(a));
}
__device__ __forceinline__ void ldsm_x4t(u32& r0, u32& r1, u32& r2, u32& r3, u32 a) {
    asm volatile("ldmatrix.sync.aligned.m8n8.x4.trans.shared.b16 {%0,%1,%2,%3}, [%4];"
                 : "=r"(r0), "=r"(r1), "=r"(r2), "=r"(r3) : "r"(a));
}
__device__ __forceinline__ void mma16816h(float* c, const u32* a, const u32* b) {
    asm volatile(
        "mma.sync.aligned.m16n8k16.row.col.f32.f16.f16.f32 "
        "{%0,%1,%2,%3},{%4,%5,%6,%7},{%8,%9},{%0,%1,%2,%3};"
        : "+f"(c[0]), "+f"(c[1]), "+f"(c[2]), "+f"(c[3])
        : "r"(a[0]), "r"(a[1]), "r"(a[2]), "r"(a[3]), "r"(b[0]), "r"(b[1]));
}
__device__ __forceinline__ float fast_exp2(float x) {
    float r; asm("ex2.approx.ftz.f32 %0, %1;" : "=f"(r) : "f"(x)); return r;
}
__device__ __forceinline__ u32 cvt_f16x2(float lo, float hi) {
    u32 r; asm("cvt.rn.f16x2.f32 %0, %1, %2;" : "=r"(r) : "f"(hi), "f"(lo));
    return r;
}
__device__ __forceinline__ void split2h(float f0, float f1, u32& hi, u32& lo) {
    hi = cvt_f16x2(f0, f1);
    __half2 h2 = *reinterpret_cast<__half2*>(&hi);
    float2 hf = __half22float2(h2);
    lo = cvt_f16x2(f0 - hf.x, f1 - hf.y);
}
#define CP_ASYNC16(d, s) asm volatile("cp.async.cg.shared.global [%0], [%1], 16;" :: "r"(d), "l"(s))
#define CP_COMMIT()      asm volatile("cp.async.commit_group;" ::: "memory")
#define CP_WAIT1()       asm volatile("cp.async.wait_group 1;" ::: "memory")
#define CP_WAIT0()       asm volatile("cp.async.wait_group 0;" ::: "memory")

// ---------------- prep: fp32 -> fp16 hi/lo split -----------------------------
__global__ void split16_kernel(const float* __restrict__ in,
                               __half* __restrict__ hi,
                               __half* __restrict__ lo, int n4)
{
    int i = blockIdx.x * blockDim.x + threadIdx.x;
    if (i >= n4) return;
    float4 v = ((const float4*)in)[i];
    u32 h0, l0, h1, l1;
    split2h(v.x, v.y, h0, l0);
    split2h(v.z, v.w, h1, l1);
    ((uint2*)hi)[i] = make_uint2(h0, h1);
    ((uint2*)lo)[i] = make_uint2(l0, l1);
}

// ---------------- prep: W[K][N] -> W^T single fp16 [N][K] -------------------
__global__ void transpose_f16_kernel(const float* __restrict__ W,
                                     __half* __restrict__ W16, int K, int N)
{
    __shared__ float ts[32][33];
    int n0 = blockIdx.x * 32, k0 = blockIdx.y * 32;
    int tx = threadIdx.x, ty = threadIdx.y;  // 32 x 8
#pragma unroll
    for (int r = 0; r < 4; r++)
        ts[ty + 8 * r][tx] = W[(size_t)(k0 + ty + 8 * r) * N + n0 + tx];
    __syncthreads();
#pragma unroll
    for (int r = 0; r < 4; r++) {
        float v = ts[tx][ty + 8 * r];
        W16[(size_t)(n0 + ty + 8 * r) * K + k0 + tx] = __float2half_rn(v);
    }
}

// ---------------- fp16 2-pass GEMM: C = (Ah+Al) @ B16^T + bias --------------
// EPI 0: fp32 C out.   EPI 1: q -> fp16 hi/lo, k/v -> single fp16 (by n-part).
#define RSTRIDE 80
#define ARR_B   (128 * RSTRIDE)
#define STAGE3_B (3 * ARR_B)
#define G2SMEM   (2 * STAGE3_B)

extern __shared__ char sm_raw[];

template<int EPI>
__global__ void __launch_bounds__(128) gemm_f16_kernel(
    const __half* __restrict__ Ah, const __half* __restrict__ Al,
    const __half* __restrict__ B16,
    const float* __restrict__ bias, float* __restrict__ C,
    int M, int N, int K,
    __half* oq_h, __half* oq_l, __half* ok16, __half* ov16)
{
    const int tid = threadIdx.x, lane = tid & 31, wid = tid >> 5;
    const int warp_m = wid & 1, warp_n = wid >> 1;
    const int m0 = blockIdx.y * 128, n0 = blockIdx.x * 128;

    const int grp = lane >> 3, lrow = lane & 7;
    const int a_row = (grp & 1) * 8 + lrow, a_kb = (grp >> 1) * 16;
    const int b_row = (grp >> 1) * 8 + lrow, b_kb = (grp & 1) * 16;

    const __half* srcs[3] = {Ah, Al, B16};
    const int r0s[3] = {m0, m0, n0};

    float cf[4][8][4];
#pragma unroll
    for (int tm = 0; tm < 4; tm++)
#pragma unroll
        for (int tn = 0; tn < 8; tn++)
#pragma unroll
            for (int q = 0; q < 4; q++) cf[tm][tn][q] = 0.f;

#define G2_LOAD(st, k0v)                                                        \
    do {                                                                        \
        char* _b = sm_raw + (st) * STAGE3_B;                                    \
        _Pragma("unroll")                                                       \
        for (int t = 0; t < 3; t++) {                                           \
            const __half* _s = srcs[t] + (size_t)r0s[t] * K + (k0v);            \
            _Pragma("unroll")                                                   \
            for (int j = 0; j < 4; j++) {                                       \
                int _i = tid + j * 128;                                         \
                int _r = _i >> 2, _c = _i & 3;                                  \
                u32 _d = smem_u32(_b + t * ARR_B + _r * RSTRIDE + _c * 16);     \
                CP_ASYNC16(_d, _s + (size_t)_r * K + _c * 8);                   \
            }                                                                   \
        }                                                                       \
    } while (0)

#define G2_COMPUTE(st)                                                          \
    do {                                                                        \
        u32 _sb = smem_u32(sm_raw) + (st) * STAGE3_B;                           \
        _Pragma("unroll")                                                       \
        for (int ks = 0; ks < 2; ks++) {                                        \
            u32 afr[2][4][4], bfr[4][4];                                        \
            _Pragma("unroll")                                                   \
            for (int s = 0; s < 2; s++)                                         \
                _Pragma("unroll")                                               \
                for (int tm = 0; tm < 4; tm++)                                  \
                    ldsm_x4(afr[s][tm][0], afr[s][tm][1],                       \
                            afr[s][tm][2], afr[s][tm][3],                       \
                            _sb + s * ARR_B +                                   \
                            (warp_m * 64 + tm * 16 + a_row) * RSTRIDE +         \
                            ks * 32 + a_kb);                                    \
            _Pragma("unroll")                                                   \
            for (int t2 = 0; t2 < 4; t2++)                                      \
                ldsm_x4(bfr[t2][0], bfr[t2][1], bfr[t2][2], bfr[t2][3],         \
                        _sb + 2 * ARR_B +                                       \
                        (warp_n * 64 + t2 * 16 + b_row) * RSTRIDE +             \
                        ks * 32 + b_kb);                                        \
            _Pragma("unroll")                                                   \
            for (int tm = 0; tm < 4; tm++)                                      \
                _Pragma("unroll")                                               \
                for (int tn = 0; tn < 8; tn++)                                  \
                    mma16816h(cf[tm][tn], afr[0][tm],                           \
                              &bfr[tn >> 1][(tn & 1) * 2]);                     \
            _Pragma("unroll")                                                   \
            for (int tm = 0; tm < 4; tm++)                                      \
                _Pragma("unroll")                                               \
                for (int tn = 0; tn < 8; tn++)                                  \
                    mma16816h(cf[tm][tn], afr[1][tm],                           \
                              &bfr[tn >> 1][(tn & 1) * 2]);                     \
        }                                                                       \
    } while (0)

    const int NIT = K / 32;
    G2_LOAD(0, 0);
    CP_COMMIT();
    for (int it = 0; it < NIT; it++) {
        if (it + 1 < NIT) {
            G2_LOAD((it + 1) & 1, (it + 1) * 32);
            CP_COMMIT();
            CP_WAIT1();
        } else {
            CP_WAIT0();
        }
        __syncthreads();
        G2_COMPUTE(it & 1);
        __syncthreads();
    }

    const int mrow = lane >> 2, ncol = (lane & 3) * 2;
    if (EPI == 0) {
#pragma unroll
        for (int tm = 0; tm < 4; tm++)
#pragma unroll
            for (int tn = 0; tn < 8; tn++) {
                int r = m0 + warp_m * 64 + tm * 16 + mrow;
                int c = n0 + warp_n * 64 + tn * 8 + ncol;
                float2 bb = *(const float2*)&bias[c];
                *(float2*)&C[(size_t)r * N + c] =
                    make_float2(cf[tm][tn][0] + bb.x, cf[tm][tn][1] + bb.y);
                *(float2*)&C[(size_t)(r + 8) * N + c] =
                    make_float2(cf[tm][tn][2] + bb.x, cf[tm][tn][3] + bb.y);
            }
    } else {
        int part = n0 >> 10;
        if (part == 0) {
            // Q: fp16 hi/lo split
#pragma unroll
            for (int tm = 0; tm < 4; tm++)
#pragma unroll
                for (int tn = 0; tn < 8; tn++) {
                    int r = m0 + warp_m * 64 + tm * 16 + mrow;
                    int c = n0 + warp_n * 64 + tn * 8 + ncol;
                    int lc = c & 1023;
                    float2 bb = *(const float2*)&bias[c];
                    u32 h0, l0, h1, l1;
                    split2h(cf[tm][tn][0] + bb.x, cf[tm][tn][1] + bb.y, h0, l0);
                    split2h(cf[tm][tn][2] + bb.x, cf[tm][tn][3] + bb.y, h1, l1);
                    *(u32*)(oq_h + (size_t)r * C_DIM + lc) = h0;
                    *(u32*)(oq_l + (size_t)r * C_DIM + lc) = l0;
                    *(u32*)(oq_h + (size_t)(r + 8) * C_DIM + lc) = h1;
                    *(u32*)(oq_l + (size_t)(r + 8) * C_DIM + lc) = l1;
                }
        } else {
            // K / V: single fp16
            __half* dst = part == 1 ? ok16 : ov16;
#pragma unroll
            for (int tm = 0; tm < 4; tm++)
#pragma unroll
                for (int tn = 0; tn < 8; tn++) {
                    int r = m0 + warp_m * 64 + tm * 16 + mrow;
                    int c = n0 + warp_n * 64 + tn * 8 + ncol;
                    int lc = c & 1023;
                    float2 bb = *(const float2*)&bias[c];
                    u32 v0 = cvt_f16x2(cf[tm][tn][0] + bb.x, cf[tm][tn][1] + bb.y);
                    u32 v1 = cvt_f16x2(cf[tm][tn][2] + bb.x, cf[tm][tn][3] + bb.y);
                    *(u32*)(dst + (size_t)r * C_DIM + lc) = v0;
                    *(u32*)(dst + (size_t)(r + 8) * C_DIM + lc) = v1;
                }
        }
    }
#undef G2_LOAD
#undef G2_COMPUTE
}

// ---------------- tensor-core flash attention -------------------------------
// S = (Qh+Ql) @ K16^T (fp16 2-pass).  PV = (Ph+Pl) @ V16 (fp16 2-pass).
#define FA_RS   72
#define FA_ARR  (128 * FA_RS)
#define FA_ST0  (2 * FA_ARR)
#define FA_STSZ (2 * FA_ARR)                 // K16, V16
#define FA_SMEM ((2 * FA_ARR + 2 * FA_STSZ) * 2)   // 110592 B

__global__ void __launch_bounds__(256) flash_attn_mma(
    const __half* __restrict__ qh, const __half* __restrict__ ql,
    const __half* __restrict__ k16, const __half* __restrict__ v16,
    __half* __restrict__ oh, __half* __restrict__ ol)
{
    __half* sm = (__half*)sm_raw;
    const int tid = threadIdx.x, lane = tid & 31, w = tid >> 5;
    const int qt = blockIdx.x;
    const int b = blockIdx.y >> 4, h = blockIdx.y & 15;
    const size_t rowbase = (size_t)b * T_SZ;
    const int colbase = h * HD;

    const __half* kvsrc[2] = {k16, v16};

#define FA_LOAD(st, kt)                                                         \
    do {                                                                        \
        _Pragma("unroll")                                                       \
        for (int a4 = 0; a4 < 2; a4++) {                                        \
            _Pragma("unroll")                                                   \
            for (int j = 0; j < 4; j++) {                                       \
                int idx = tid + j * 256;                                        \
                int r = idx >> 3, c8 = idx & 7;                                 \
                u32 d = smem_u32(sm + FA_ST0 + (st) * FA_STSZ + a4 * FA_ARR +   \
                                 r * FA_RS + c8 * 8);                           \
                CP_ASYNC16(d, kvsrc[a4] +                                       \
                           (rowbase + (kt) * 128 + r) * C_DIM + colbase + c8 * 8); \
            }                                                                   \
        }                                                                       \
    } while (0)

    FA_LOAD(0, 0);
    CP_COMMIT();

    {
        const __half* qsrc[2] = {qh, ql};
#pragma unroll
        for (int a2 = 0; a2 < 2; a2++)
#pragma unroll
            for (int j = 0; j < 4; j++) {
                int idx = tid + j * 256;
                int r = idx >> 3, c8 = idx & 7;
                uint4 v = *(const uint4*)(qsrc[a2] +
                    (rowbase + qt * 128 + r) * C_DIM + colbase + c8 * 8);
                *(uint4*)(sm + a2 * FA_ARR + r * FA_RS + c8 * 8) = v;
            }
    }
    __syncthreads();

    u32 qfh[4][4], qfl[4][4];
    {
        u32 qbase = smem_u32(sm);
        int arow = w * 16 + (lane & 15);
        int acol = (lane >> 4) * 8;
#pragma unroll
        for (int ks = 0; ks < 4; ks++) {
            u32 off = (arow * FA_RS + ks * 16 + acol) * 2;
            ldsm_x4(qfh[ks][0], qfh[ks][1], qfh[ks][2], qfh[ks][3], qbase + off);
            ldsm_x4(qfl[ks][0], qfl[ks][1], qfl[ks][2], qfl[ks][3],
                    qbase + FA_ARR * 2 + off);
        }
    }

    float sf[16][4];
    float of[8][4];
#pragma unroll
    for (int j = 0; j < 8; j++)
#pragma unroll
        for (int q = 0; q < 4; q++) of[j][q] = 0.f;
    float m0 = -CUDART_INF_F, m1 = -CUDART_INF_F, l0 = 0.f, l1 = 0.f;

    const u32 sbase = smem_u32(sm);
    const int krow = (lane & 7) + ((lane >> 4) << 3);
    const int kch  = (lane >> 3) & 1;
    const int vrow = (lane & 7) + (((lane >> 3) & 1) << 3);
    const int vch  = lane >> 4;
    const float sc = ATT_SCALE * LOG2E;

    for (int kt = 0; kt < T_SZ / 128; kt++) {
        if (kt + 1 < T_SZ / 128) { FA_LOAD((kt + 1) & 1, kt + 1); CP_COMMIT(); CP_WAIT1(); }
        else CP_WAIT0();
        __syncthreads();
        u32 stb = sbase + (FA_ST0 + (kt & 1) * FA_STSZ) * 2;

        // ---- S = Q K^T (fp16 2-pass), pass-major ----
#pragma unroll
        for (int j = 0; j < 16; j++) {
            sf[j][0] = 0.f; sf[j][1] = 0.f; sf[j][2] = 0.f; sf[j][3] = 0.f;
        }
#pragma unroll
        for (int jp = 0; jp < 4; jp++) {
            u32 bh[2][4][4];
#pragma unroll
            for (int j2 = 0; j2 < 2; j2++)
#pragma unroll
                for (int ks = 0; ks < 4; ks++) {
                    u32 off = (((jp * 2 + j2) * 16 + krow) * FA_RS +
                               ks * 16 + kch * 8) * 2;
                    ldsm_x4(bh[j2][ks][0], bh[j2][ks][1], bh[j2][ks][2], bh[j2][ks][3],
                            stb + off);
                }
            float* s0 = sf[4 * jp];     float* s1 = sf[4 * jp + 1];
            float* s2 = sf[4 * jp + 2]; float* s3 = sf[4 * jp + 3];
#pragma unroll
            for (int ks = 0; ks < 4; ks++) {
                mma16816h(s0, qfh[ks], &bh[0][ks][0]);
                mma16816h(s1, qfh[ks], &bh[0][ks][2]);
                mma16816h(s2, qfh[ks], &bh[1][ks][0]);
                mma16816h(s3, qfh[ks], &bh[1][ks][2]);
            }
#pragma unroll
            for (int ks = 0; ks < 4; ks++) {
                mma16816h(s0, qfl[ks], &bh[0][ks][0]);
                mma16816h(s1, qfl[ks], &bh[0][ks][2]);
                mma16816h(s2, qfl[ks], &bh[1][ks][0]);
                mma16816h(s3, qfl[ks], &bh[1][ks][2]);
            }
        }

        // ---- online softmax ----
        float mt0 = -CUDART_INF_F, mt1 = -CUDART_INF_F;
#pragma unroll
        for (int j = 0; j < 16; j++) {
            sf[j][0] *= sc; sf[j][1] *= sc; sf[j][2] *= sc; sf[j][3] *= sc;
            mt0 = fmaxf(mt0, fmaxf(sf[j][0], sf[j][1]));
            mt1 = fmaxf(mt1, fmaxf(sf[j][2], sf[j][3]));
        }
        mt0 = fmaxf(mt0, __shfl_xor_sync(0xffffffffu, mt0, 1));
        mt0 = fmaxf(mt0, __shfl_xor_sync(0xffffffffu, mt0, 2));
        mt1 = fmaxf(mt1, __shfl_xor_sync(0xffffffffu, mt1, 1));
        mt1 = fmaxf(mt1, __shfl_xor_sync(0xffffffffu, mt1, 2));
        float mn0 = fmaxf(m0, mt0), mn1 = fmaxf(m1, mt1);
        float f0 = fast_exp2(m0 - mn0), f1 = fast_exp2(m1 - mn1);
        m0 = mn0; m1 = mn1;
        float rs0 = 0.f, rs1 = 0.f;
#pragma unroll
        for (int j = 0; j < 16; j++) {
            sf[j][0] = fast_exp2(sf[j][0] - mn0);
            sf[j][1] = fast_exp2(sf[j][1] - mn0);
            sf[j][2] = fast_exp2(sf[j][2] - mn1);
            sf[j][3] = fast_exp2(sf[j][3] - mn1);
            rs0 += sf[j][0] + sf[j][1];
            rs1 += sf[j][2] + sf[j][3];
        }
        rs0 += __shfl_xor_sync(0xffffffffu, rs0, 1);
        rs0 += __shfl_xor_sync(0xffffffffu, rs0, 2);
        rs1 += __shfl_xor_sync(0xffffffffu, rs1, 1);
        rs1 += __shfl_xor_sync(0xffffffffu, rs1, 2);
        l0 = l0 * f0 + rs0;
        l1 = l1 * f1 + rs1;
#pragma unroll
        for (int j = 0; j < 8; j++) {
            of[j][0] *= f0; of[j][1] *= f0; of[j][2] *= f1; of[j][3] *= f1;
        }

        // ---- O += P V (fp16 2-pass) ----
#pragma unroll
        for (int kp = 0; kp < 8; kp++) {
            u32 ah[4], al[4];
            split2h(sf[2 * kp][0],     sf[2 * kp][1],     ah[0], al[0]);
            split2h(sf[2 * kp][2],     sf[2 * kp][3],     ah[1], al[1]);
            split2h(sf[2 * kp + 1][0], sf[2 * kp + 1][1], ah[2], al[2]);
            split2h(sf[2 * kp + 1][2], sf[2 * kp + 1][3], ah[3], al[3]);
            u32 bv[4][4];
#pragma unroll
            for (int dt = 0; dt < 4; dt++) {
                u32 off = ((kp * 16 + vrow) * FA_RS + dt * 16 + vch * 8) * 2;
                ldsm_x4t(bv[dt][0], bv[dt][1], bv[dt][2], bv[dt][3],
                         stb + FA_ARR * 2 + off);
            }
#pragma unroll
            for (int dt = 0; dt < 4; dt++) {
                mma16816h(of[2 * dt],     ah, &bv[dt][0]);
                mma16816h(of[2 * dt + 1], ah, &bv[dt][2]);
            }
#pragma unroll
            for (int dt = 0; dt < 4; dt++) {
                mma16816h(of[2 * dt],     al, &bv[dt][0]);
                mma16816h(of[2 * dt + 1], al, &bv[dt][2]);
            }
        }
        __syncthreads();
    }

    // ---- epilogue: normalize, split to fp16 hi/lo ----
    float inv0 = 1.f / l0, inv1 = 1.f / l1;
    const int g = lane >> 2, t2 = (lane & 3) * 2;
    size_t r0 = rowbase + qt * 128 + w * 16 + g;
#pragma unroll
    for (int j = 0; j < 8; j++) {
        int c = colbase + j * 8 + t2;
        u32 h0, lo0, h1, lo1;
        split2h(of[j][0] * inv0, of[j][1] * inv0, h0, lo0);
        split2h(of[j][2] * inv1, of[j][3] * inv1, h1, lo1);
        *(u32*)(oh + r0 * C_DIM + c) = h0;
        *(u32*)(ol + r0 * C_DIM + c) = lo0;
        *(u32*)(oh + (r0 + 8) * C_DIM + c) = h1;
        *(u32*)(ol + (r0 + 8) * C_DIM + c) = lo1;
    }
#undef FA_LOAD
}

// ---------------------------------------------------------------------------
extern "C" void kernel_launch(void* const* d_in, const int* in_sizes, int n_in,
                              void* d_out, int out_size)
{
    const float* x     = (const float*)d_in[0];
    const float* Wqkv  = (const float*)d_in[1];
    const float* bqkv  = (const float*)d_in[2];
    const float* Wproj = (const float*)d_in[3];
    const float* bproj = (const float*)d_in[4];
    float* out = (float*)d_out;

    __half *q16h, *q16l, *k16, *v16, *xh16, *xl16, *oh16, *ol16, *wq16, *wp16;
    cudaGetSymbolAddress((void**)&q16h, g_q16h); cudaGetSymbolAddress((void**)&q16l, g_q16l);
    cudaGetSymbolAddress((void**)&k16, g_k16);   cudaGetSymbolAddress((void**)&v16, g_v16);
    cudaGetSymbolAddress((void**)&xh16, g_xh16); cudaGetSymbolAddress((void**)&xl16, g_xl16);
    cudaGetSymbolAddress((void**)&oh16, g_oh16); cudaGetSymbolAddress((void**)&ol16, g_ol16);
    cudaGetSymbolAddress((void**)&wq16, g_wq16); cudaGetSymbolAddress((void**)&wp16, g_wp16);

    cudaFuncSetAttribute(gemm_f16_kernel<0>,
                         cudaFuncAttributeMaxDynamicSharedMemorySize, G2SMEM);
    cudaFuncSetAttribute(gemm_f16_kernel<1>,
                         cudaFuncAttributeMaxDynamicSharedMemorySize, G2SMEM);
    cudaFuncSetAttribute(flash_attn_mma,
                         cudaFuncAttributeMaxDynamicSharedMemorySize, FA_SMEM);

    // prep: x -> fp16 hi/lo; weights -> transposed single fp16
    split16_kernel<<<(M_ROWS * C_DIM / 4 + 255) / 256, 256>>>(
        x, xh16, xl16, M_ROWS * C_DIM / 4);
    transpose_f16_kernel<<<dim3(C3 / 32, C_DIM / 32), dim3(32, 8)>>>(
        Wqkv, wq16, C_DIM, C3);
    transpose_f16_kernel<<<dim3(C_DIM / 32, C_DIM / 32), dim3(32, 8)>>>(
        Wproj, wp16, C_DIM, C_DIM);

    // 1) qkv projection (fp16 2-pass): q -> fp16 hi/lo; k, v -> single fp16
    gemm_f16_kernel<1><<<dim3(C3 / 128, M_ROWS / 128), 128, G2SMEM>>>(
        xh16, xl16, wq16, bqkv, nullptr, M_ROWS, C3, C_DIM,
        q16h, q16l, k16, v16);

    // 2) attention -> fp16 hi/lo
    flash_attn_mma<<<dim3(T_SZ / 128, B_SZ * NH), 256, FA_SMEM>>>(
        q16h, q16l, k16, v16, oh16, ol16);

    // 3) out = attn @ Wproj + bproj (fp16 2-pass)
    gemm_f16_kernel<0><<<dim3(C_DIM / 128, M_ROWS / 128), 128, G2SMEM>>>(
        oh16, ol16, wp16, bproj, out, M_ROWS, C_DIM, C_DIM,
        nullptr, nullptr, nullptr, nullptr);
}

// round 11
// speedup vs baseline: 1.6711x; 1.1712x over previous
#include <cuda_runtime.h>
#include <cuda_bf16.h>
#include <cuda_fp16.h>
#include <math_constants.h>

#define C_DIM 1024
#define C3    3072
#define NH    16
#define HD    64
#define B_SZ  2
#define T_SZ  2048
#define M_ROWS (B_SZ*T_SZ)

#define ATT_SCALE 0.5f
#define LOG2E 1.4426950408889634f

typedef unsigned long long u64;
typedef unsigned int u32;

// ---------------- scratch (no device allocation allowed) -------------------
__device__ __half g_q16h[(size_t)M_ROWS * C_DIM];   // Q fp16 hi
__device__ __half g_q16l[(size_t)M_ROWS * C_DIM];   // Q fp16 lo
__device__ __half g_k16[(size_t)M_ROWS * C_DIM];    // K single fp16
__device__ __half g_v16[(size_t)M_ROWS * C_DIM];    // V single fp16
__device__ __half g_xh16[(size_t)M_ROWS * C_DIM];   // x fp16 hi
__device__ __half g_xl16[(size_t)M_ROWS * C_DIM];   // x fp16 lo
__device__ __half g_o16[(size_t)M_ROWS * C_DIM];    // attn out single fp16
__device__ __half g_wq16[(size_t)C3 * C_DIM];       // Wqkv^T single fp16 [N][K]
__device__ __half g_wp16[(size_t)C_DIM * C_DIM];    // Wproj^T single fp16

// ---------------- helpers ----------------------------------------------------
__device__ __forceinline__ u32 smem_u32(const void* p) {
    u32 a; asm("{ .reg .u64 t; cvta.to.shared.u64 t, %1; cvt.u32.u64 %0, t; }"
               : "=r"(a) : "l"(p));
    return a;
}
__device__ __forceinline__ void ldsm_x4(u32& r0, u32& r1, u32& r2, u32& r3, u32 a) {
    asm volatile("ldmatrix.sync.aligned.m8n8.x4.shared.b16 {%0,%1,%2,%3}, [%4];"
                 : "=r"(r0), "=r"(r1), "=r"(r2), "=r"(r3) : "r"(a));
}
__device__ __forceinline__ void ldsm_x4t(u32& r0, u32& r1, u32& r2, u32& r3, u32 a) {
    asm volatile("ldmatrix.sync.aligned.m8n8.x4.trans.shared.b16 {%0,%1,%2,%3}, [%4];"
                 : "=r"(r0), "=r"(r1), "=r"(r2), "=r"(r3) : "r"(a));
}
__device__ __forceinline__ void mma16816h(float* c, const u32* a, const u32* b) {
    asm volatile(
        "mma.sync.aligned.m16n8k16.row.col.f32.f16.f16.f32 "
        "{%0,%1,%2,%3},{%4,%5,%6,%7},{%8,%9},{%0,%1,%2,%3};"
        : "+f"(c[0]), "+f"(c[1]), "+f"(c[2]), "+f"(c[3])
        : "r"(a[0]), "r"(a[1]), "r"(a[2]), "r"(a[3]), "r"(b[0]), "r"(b[1]));
}
__device__ __forceinline__ float fast_exp2(float x) {
    float r; asm("ex2.approx.ftz.f32 %0, %1;" : "=f"(r) : "f"(x)); return r;
}
__device__ __forceinline__ u32 cvt_f16x2(float lo, float hi) {
    u32 r; asm("cvt.rn.f16x2.f32 %0, %1, %2;" : "=r"(r) : "f"(hi), "f"(lo));
    return r;
}
__device__ __forceinline__ void split2h(float f0, float f1, u32& hi, u32& lo) {
    hi = cvt_f16x2(f0, f1);
    __half2 h2 = *reinterpret_cast<__half2*>(&hi);
    float2 hf = __half22float2(h2);
    lo = cvt_f16x2(f0 - hf.x, f1 - hf.y);
}
#define CP_ASYNC16(d, s) asm volatile("cp.async.cg.shared.global [%0], [%1], 16;" :: "r"(d), "l"(s))
#define CP_COMMIT()      asm volatile("cp.async.commit_group;" ::: "memory")
#define CP_WAIT1()       asm volatile("cp.async.wait_group 1;" ::: "memory")
#define CP_WAIT0()       asm volatile("cp.async.wait_group 0;" ::: "memory")

// ---------------- prep: fp32 -> fp16 hi/lo split -----------------------------
__global__ void split16_kernel(const float* __restrict__ in,
                               __half* __restrict__ hi,
                               __half* __restrict__ lo, int n4)
{
    int i = blockIdx.x * blockDim.x + threadIdx.x;
    if (i >= n4) return;
    float4 v = ((const float4*)in)[i];
    u32 h0, l0, h1, l1;
    split2h(v.x, v.y, h0, l0);
    split2h(v.z, v.w, h1, l1);
    ((uint2*)hi)[i] = make_uint2(h0, h1);
    ((uint2*)lo)[i] = make_uint2(l0, l1);
}

// ---------------- prep: W[K][N] -> W^T single fp16 [N][K] -------------------
__global__ void transpose_f16_kernel(const float* __restrict__ W,
                                     __half* __restrict__ W16, int K, int N)
{
    __shared__ float ts[32][33];
    int n0 = blockIdx.x * 32, k0 = blockIdx.y * 32;
    int tx = threadIdx.x, ty = threadIdx.y;  // 32 x 8
#pragma unroll
    for (int r = 0; r < 4; r++)
        ts[ty + 8 * r][tx] = W[(size_t)(k0 + ty + 8 * r) * N + n0 + tx];
    __syncthreads();
#pragma unroll
    for (int r = 0; r < 4; r++) {
        float v = ts[tx][ty + 8 * r];
        W16[(size_t)(n0 + ty + 8 * r) * K + k0 + tx] = __float2half_rn(v);
    }
}

// ---------------- fp16 GEMM: C = (sum_a A_a) @ B16^T + bias -----------------
// NA = number of A passes (1 or 2). EPI 0: fp32 C out.
// EPI 1: q -> fp16 hi/lo, k/v -> single fp16 (by n-part).
#define RSTRIDE 80
#define ARR_B   (128 * RSTRIDE)

extern __shared__ char sm_raw[];

template<int NA, int EPI>
__global__ void __launch_bounds__(128) gemm_f16_kernel(
    const __half* __restrict__ A0, const __half* __restrict__ A1,
    const __half* __restrict__ B16,
    const float* __restrict__ bias, float* __restrict__ C,
    int M, int N, int K,
    __half* oq_h, __half* oq_l, __half* ok16, __half* ov16)
{
    const int NARR = NA + 1;
    const int STB  = NARR * ARR_B;

    const int tid = threadIdx.x, lane = tid & 31, wid = tid >> 5;
    const int warp_m = wid & 1, warp_n = wid >> 1;
    const int m0 = blockIdx.y * 128, n0 = blockIdx.x * 128;

    const int grp = lane >> 3, lrow = lane & 7;
    const int a_row = (grp & 1) * 8 + lrow, a_kb = (grp >> 1) * 16;
    const int b_row = (grp >> 1) * 8 + lrow, b_kb = (grp & 1) * 16;

    const __half* srcs[3] = {A0, NA == 2 ? A1 : B16, B16};
    const int r0s[3] = {m0, NA == 2 ? m0 : n0, n0};

    float cf[4][8][4];
#pragma unroll
    for (int tm = 0; tm < 4; tm++)
#pragma unroll
        for (int tn = 0; tn < 8; tn++)
#pragma unroll
            for (int q = 0; q < 4; q++) cf[tm][tn][q] = 0.f;

#define G_LOAD(st, k0v)                                                         \
    do {                                                                        \
        char* _b = sm_raw + (st) * STB;                                         \
        _Pragma("unroll")                                                       \
        for (int t = 0; t < NARR; t++) {                                        \
            const __half* _s = srcs[t] + (size_t)r0s[t] * K + (k0v);            \
            _Pragma("unroll")                                                   \
            for (int j = 0; j < 4; j++) {                                       \
                int _i = tid + j * 128;                                         \
                int _r = _i >> 2, _c = _i & 3;                                  \
                u32 _d = smem_u32(_b + t * ARR_B + _r * RSTRIDE + _c * 16);     \
                CP_ASYNC16(_d, _s + (size_t)_r * K + _c * 8);                   \
            }                                                                   \
        }                                                                       \
    } while (0)

#define G_COMPUTE(st)                                                           \
    do {                                                                        \
        u32 _sb = smem_u32(sm_raw) + (st) * STB;                                \
        _Pragma("unroll")                                                       \
        for (int ks = 0; ks < 2; ks++) {                                        \
            u32 afr[NA][4][4], bfr[4][4];                                       \
            _Pragma("unroll")                                                   \
            for (int s = 0; s < NA; s++)                                        \
                _Pragma("unroll")                                               \
                for (int tm = 0; tm < 4; tm++)                                  \
                    ldsm_x4(afr[s][tm][0], afr[s][tm][1],                       \
                            afr[s][tm][2], afr[s][tm][3],                       \
                            _sb + s * ARR_B +                                   \
                            (warp_m * 64 + tm * 16 + a_row) * RSTRIDE +         \
                            ks * 32 + a_kb);                                    \
            _Pragma("unroll")                                                   \
            for (int t2 = 0; t2 < 4; t2++)                                      \
                ldsm_x4(bfr[t2][0], bfr[t2][1], bfr[t2][2], bfr[t2][3],         \
                        _sb + NA * ARR_B +                                      \
                        (warp_n * 64 + t2 * 16 + b_row) * RSTRIDE +             \
                        ks * 32 + b_kb);                                        \
            _Pragma("unroll")                                                   \
            for (int s = 0; s < NA; s++)                                        \
                _Pragma("unroll")                                               \
                for (int tm = 0; tm < 4; tm++)                                  \
                    _Pragma("unroll")                                           \
                    for (int tn = 0; tn < 8; tn++)                              \
                        mma16816h(cf[tm][tn], afr[s][tm],                       \
                                  &bfr[tn >> 1][(tn & 1) * 2]);                 \
        }                                                                       \
    } while (0)

    const int NIT = K / 32;
    G_LOAD(0, 0);
    CP_COMMIT();
    for (int it = 0; it < NIT; it++) {
        if (it + 1 < NIT) {
            G_LOAD((it + 1) & 1, (it + 1) * 32);
            CP_COMMIT();
            CP_WAIT1();
        } else {
            CP_WAIT0();
        }
        __syncthreads();
        G_COMPUTE(it & 1);
        __syncthreads();
    }

    const int mrow = lane >> 2, ncol = (lane & 3) * 2;
    if (EPI == 0) {
#pragma unroll
        for (int tm = 0; tm < 4; tm++)
#pragma unroll
            for (int tn = 0; tn < 8; tn++) {
                int r = m0 + warp_m * 64 + tm * 16 + mrow;
                int c = n0 + warp_n * 64 + tn * 8 + ncol;
                float2 bb = *(const float2*)&bias[c];
                *(float2*)&C[(size_t)r * N + c] =
                    make_float2(cf[tm][tn][0] + bb.x, cf[tm][tn][1] + bb.y);
                *(float2*)&C[(size_t)(r + 8) * N + c] =
                    make_float2(cf[tm][tn][2] + bb.x, cf[tm][tn][3] + bb.y);
            }
    } else {
        int part = n0 >> 10;
        if (part == 0) {
            // Q: fp16 hi/lo split
#pragma unroll
            for (int tm = 0; tm < 4; tm++)
#pragma unroll
                for (int tn = 0; tn < 8; tn++) {
                    int r = m0 + warp_m * 64 + tm * 16 + mrow;
                    int c = n0 + warp_n * 64 + tn * 8 + ncol;
                    int lc = c & 1023;
                    float2 bb = *(const float2*)&bias[c];
                    u32 h0, l0, h1, l1;
                    split2h(cf[tm][tn][0] + bb.x, cf[tm][tn][1] + bb.y, h0, l0);
                    split2h(cf[tm][tn][2] + bb.x, cf[tm][tn][3] + bb.y, h1, l1);
                    *(u32*)(oq_h + (size_t)r * C_DIM + lc) = h0;
                    *(u32*)(oq_l + (size_t)r * C_DIM + lc) = l0;
                    *(u32*)(oq_h + (size_t)(r + 8) * C_DIM + lc) = h1;
                    *(u32*)(oq_l + (size_t)(r + 8) * C_DIM + lc) = l1;
                }
        } else {
            // K / V: single fp16
            __half* dst = part == 1 ? ok16 : ov16;
#pragma unroll
            for (int tm = 0; tm < 4; tm++)
#pragma unroll
                for (int tn = 0; tn < 8; tn++) {
                    int r = m0 + warp_m * 64 + tm * 16 + mrow;
                    int c = n0 + warp_n * 64 + tn * 8 + ncol;
                    int lc = c & 1023;
                    float2 bb = *(const float2*)&bias[c];
                    u32 v0 = cvt_f16x2(cf[tm][tn][0] + bb.x, cf[tm][tn][1] + bb.y);
                    u32 v1 = cvt_f16x2(cf[tm][tn][2] + bb.x, cf[tm][tn][3] + bb.y);
                    *(u32*)(dst + (size_t)r * C_DIM + lc) = v0;
                    *(u32*)(dst + (size_t)(r + 8) * C_DIM + lc) = v1;
                }
        }
    }
#undef G_LOAD
#undef G_COMPUTE
}

// ---------------- tensor-core flash attention -------------------------------
// S = (Qh+Ql) @ K16^T (fp16 2-pass).  PV = P16 @ V16 (single pass).
#define FA_RS   72
#define FA_ARR  (128 * FA_RS)
#define FA_ST0  (2 * FA_ARR)
#define FA_STSZ (2 * FA_ARR)                 // K16, V16
#define FA_SMEM ((2 * FA_ARR + 2 * FA_STSZ) * 2)   // 110592 B

__global__ void __launch_bounds__(256) flash_attn_mma(
    const __half* __restrict__ qh, const __half* __restrict__ ql,
    const __half* __restrict__ k16, const __half* __restrict__ v16,
    __half* __restrict__ o16)
{
    __half* sm = (__half*)sm_raw;
    const int tid = threadIdx.x, lane = tid & 31, w = tid >> 5;
    const int qt = blockIdx.x;
    const int b = blockIdx.y >> 4, h = blockIdx.y & 15;
    const size_t rowbase = (size_t)b * T_SZ;
    const int colbase = h * HD;

    const __half* kvsrc[2] = {k16, v16};

#define FA_LOAD(st, kt)                                                         \
    do {                                                                        \
        _Pragma("unroll")                                                       \
        for (int a4 = 0; a4 < 2; a4++) {                                        \
            _Pragma("unroll")                                                   \
            for (int j = 0; j < 4; j++) {                                       \
                int idx = tid + j * 256;                                        \
                int r = idx >> 3, c8 = idx & 7;                                 \
                u32 d = smem_u32(sm + FA_ST0 + (st) * FA_STSZ + a4 * FA_ARR +   \
                                 r * FA_RS + c8 * 8);                           \
                CP_ASYNC16(d, kvsrc[a4] +                                       \
                           (rowbase + (kt) * 128 + r) * C_DIM + colbase + c8 * 8); \
            }                                                                   \
        }                                                                       \
    } while (0)

    FA_LOAD(0, 0);
    CP_COMMIT();

    {
        const __half* qsrc[2] = {qh, ql};
#pragma unroll
        for (int a2 = 0; a2 < 2; a2++)
#pragma unroll
            for (int j = 0; j < 4; j++) {
                int idx = tid + j * 256;
                int r = idx >> 3, c8 = idx & 7;
                uint4 v = *(const uint4*)(qsrc[a2] +
                    (rowbase + qt * 128 + r) * C_DIM + colbase + c8 * 8);
                *(uint4*)(sm + a2 * FA_ARR + r * FA_RS + c8 * 8) = v;
            }
    }
    __syncthreads();

    u32 qfh[4][4], qfl[4][4];
    {
        u32 qbase = smem_u32(sm);
        int arow = w * 16 + (lane & 15);
        int acol = (lane >> 4) * 8;
#pragma unroll
        for (int ks = 0; ks < 4; ks++) {
            u32 off = (arow * FA_RS + ks * 16 + acol) * 2;
            ldsm_x4(qfh[ks][0], qfh[ks][1], qfh[ks][2], qfh[ks][3], qbase + off);
            ldsm_x4(qfl[ks][0], qfl[ks][1], qfl[ks][2], qfl[ks][3],
                    qbase + FA_ARR * 2 + off);
        }
    }

    float sf[16][4];
    float of[8][4];
#pragma unroll
    for (int j = 0; j < 8; j++)
#pragma unroll
        for (int q = 0; q < 4; q++) of[j][q] = 0.f;
    float m0 = -CUDART_INF_F, m1 = -CUDART_INF_F, l0 = 0.f, l1 = 0.f;

    const u32 sbase = smem_u32(sm);
    const int krow = (lane & 7) + ((lane >> 4) << 3);
    const int kch  = (lane >> 3) & 1;
    const int vrow = (lane & 7) + (((lane >> 3) & 1) << 3);
    const int vch  = lane >> 4;
    const float sc = ATT_SCALE * LOG2E;

    for (int kt = 0; kt < T_SZ / 128; kt++) {
        if (kt + 1 < T_SZ / 128) { FA_LOAD((kt + 1) & 1, kt + 1); CP_COMMIT(); CP_WAIT1(); }
        else CP_WAIT0();
        __syncthreads();
        u32 stb = sbase + (FA_ST0 + (kt & 1) * FA_STSZ) * 2;

        // ---- S = Q K^T (fp16 2-pass), pass-major ----
#pragma unroll
        for (int j = 0; j < 16; j++) {
            sf[j][0] = 0.f; sf[j][1] = 0.f; sf[j][2] = 0.f; sf[j][3] = 0.f;
        }
#pragma unroll
        for (int jp = 0; jp < 4; jp++) {
            u32 bh[2][4][4];
#pragma unroll
            for (int j2 = 0; j2 < 2; j2++)
#pragma unroll
                for (int ks = 0; ks < 4; ks++) {
                    u32 off = (((jp * 2 + j2) * 16 + krow) * FA_RS +
                               ks * 16 + kch * 8) * 2;
                    ldsm_x4(bh[j2][ks][0], bh[j2][ks][1], bh[j2][ks][2], bh[j2][ks][3],
                            stb + off);
                }
            float* s0 = sf[4 * jp];     float* s1 = sf[4 * jp + 1];
            float* s2 = sf[4 * jp + 2]; float* s3 = sf[4 * jp + 3];
#pragma unroll
            for (int ks = 0; ks < 4; ks++) {
                mma16816h(s0, qfh[ks], &bh[0][ks][0]);
                mma16816h(s1, qfh[ks], &bh[0][ks][2]);
                mma16816h(s2, qfh[ks], &bh[1][ks][0]);
                mma16816h(s3, qfh[ks], &bh[1][ks][2]);
            }
#pragma unroll
            for (int ks = 0; ks < 4; ks++) {
                mma16816h(s0, qfl[ks], &bh[0][ks][0]);
                mma16816h(s1, qfl[ks], &bh[0][ks][2]);
                mma16816h(s2, qfl[ks], &bh[1][ks][0]);
                mma16816h(s3, qfl[ks], &bh[1][ks][2]);
            }
        }

        // ---- online softmax ----
        float mt0 = -CUDART_INF_F, mt1 = -CUDART_INF_F;
#pragma unroll
        for (int j = 0; j < 16; j++) {
            sf[j][0] *= sc; sf[j][1] *= sc; sf[j][2] *= sc; sf[j][3] *= sc;
            mt0 = fmaxf(mt0, fmaxf(sf[j][0], sf[j][1]));
            mt1 = fmaxf(mt1, fmaxf(sf[j][2], sf[j][3]));
        }
        mt0 = fmaxf(mt0, __shfl_xor_sync(0xffffffffu, mt0, 1));
        mt0 = fmaxf(mt0, __shfl_xor_sync(0xffffffffu, mt0, 2));
        mt1 = fmaxf(mt1, __shfl_xor_sync(0xffffffffu, mt1, 1));
        mt1 = fmaxf(mt1, __shfl_xor_sync(0xffffffffu, mt1, 2));
        float mn0 = fmaxf(m0, mt0), mn1 = fmaxf(m1, mt1);
        float f0 = fast_exp2(m0 - mn0), f1 = fast_exp2(m1 - mn1);
        m0 = mn0; m1 = mn1;
        float rs0 = 0.f, rs1 = 0.f;
#pragma unroll
        for (int j = 0; j < 16; j++) {
            sf[j][0] = fast_exp2(sf[j][0] - mn0);
            sf[j][1] = fast_exp2(sf[j][1] - mn0);
            sf[j][2] = fast_exp2(sf[j][2] - mn1);
            sf[j][3] = fast_exp2(sf[j][3] - mn1);
            rs0 += sf[j][0] + sf[j][1];
            rs1 += sf[j][2] + sf[j][3];
        }
        rs0 += __shfl_xor_sync(0xffffffffu, rs0, 1);
        rs0 += __shfl_xor_sync(0xffffffffu, rs0, 2);
        rs1 += __shfl_xor_sync(0xffffffffu, rs1, 1);
        rs1 += __shfl_xor_sync(0xffffffffu, rs1, 2);
        l0 = l0 * f0 + rs0;
        l1 = l1 * f1 + rs1;
#pragma unroll
        for (int j = 0; j < 8; j++) {
            of[j][0] *= f0; of[j][1] *= f0; of[j][2] *= f1; of[j][3] *= f1;
        }

        // ---- O += P V (single fp16 pass) ----
#pragma unroll
        for (int kp = 0; kp < 8; kp++) {
            u32 ah[4];
            ah[0] = cvt_f16x2(sf[2 * kp][0],     sf[2 * kp][1]);
            ah[1] = cvt_f16x2(sf[2 * kp][2],     sf[2 * kp][3]);
            ah[2] = cvt_f16x2(sf[2 * kp + 1][0], sf[2 * kp + 1][1]);
            ah[3] = cvt_f16x2(sf[2 * kp + 1][2], sf[2 * kp + 1][3]);
            u32 bv[4][4];
#pragma unroll
            for (int dt = 0; dt < 4; dt++) {
                u32 off = ((kp * 16 + vrow) * FA_RS + dt * 16 + vch * 8) * 2;
                ldsm_x4t(bv[dt][0], bv[dt][1], bv[dt][2], bv[dt][3],
                         stb + FA_ARR * 2 + off);
            }
#pragma unroll
            for (int dt = 0; dt < 4; dt++) {
                mma16816h(of[2 * dt],     ah, &bv[dt][0]);
                mma16816h(of[2 * dt + 1], ah, &bv[dt][2]);
            }
        }
        __syncthreads();
    }

    // ---- epilogue: normalize, store single fp16 ----
    float inv0 = 1.f / l0, inv1 = 1.f / l1;
    const int g = lane >> 2, t2 = (lane & 3) * 2;
    size_t r0 = rowbase + qt * 128 + w * 16 + g;
#pragma unroll
    for (int j = 0; j < 8; j++) {
        int c = colbase + j * 8 + t2;
        u32 v0 = cvt_f16x2(of[j][0] * inv0, of[j][1] * inv0);
        u32 v1 = cvt_f16x2(of[j][2] * inv1, of[j][3] * inv1);
        *(u32*)(o16 + r0 * C_DIM + c) = v0;
        *(u32*)(o16 + (r0 + 8) * C_DIM + c) = v1;
    }
#undef FA_LOAD
}

// ---------------------------------------------------------------------------
extern "C" void kernel_launch(void* const* d_in, const int* in_sizes, int n_in,
                              void* d_out, int out_size)
{
    const float* x     = (const float*)d_in[0];
    const float* Wqkv  = (const float*)d_in[1];
    const float* bqkv  = (const float*)d_in[2];
    const float* Wproj = (const float*)d_in[3];
    const float* bproj = (const float*)d_in[4];
    float* out = (float*)d_out;

    __half *q16h, *q16l, *k16, *v16, *xh16, *xl16, *o16, *wq16, *wp16;
    cudaGetSymbolAddress((void**)&q16h, g_q16h); cudaGetSymbolAddress((void**)&q16l, g_q16l);
    cudaGetSymbolAddress((void**)&k16, g_k16);   cudaGetSymbolAddress((void**)&v16, g_v16);
    cudaGetSymbolAddress((void**)&xh16, g_xh16); cudaGetSymbolAddress((void**)&xl16, g_xl16);
    cudaGetSymbolAddress((void**)&o16, g_o16);
    cudaGetSymbolAddress((void**)&wq16, g_wq16); cudaGetSymbolAddress((void**)&wp16, g_wp16);

    const int SM_QKV  = 2 * 3 * ARR_B;   // NA=2: A0,A1,B x2 stages = 61440 B
    const int SM_PROJ = 2 * 2 * ARR_B;   // NA=1: A0,B  x2 stages = 40960 B
    cudaFuncSetAttribute(gemm_f16_kernel<2, 1>,
                         cudaFuncAttributeMaxDynamicSharedMemorySize, SM_QKV);
    cudaFuncSetAttribute(gemm_f16_kernel<1, 0>,
                         cudaFuncAttributeMaxDynamicSharedMemorySize, SM_PROJ);
    cudaFuncSetAttribute(flash_attn_mma,
                         cudaFuncAttributeMaxDynamicSharedMemorySize, FA_SMEM);

    // prep: x -> fp16 hi/lo; weights -> transposed single fp16
    split16_kernel<<<(M_ROWS * C_DIM / 4 + 255) / 256, 256>>>(
        x, xh16, xl16, M_ROWS * C_DIM / 4);
    transpose_f16_kernel<<<dim3(C3 / 32, C_DIM / 32), dim3(32, 8)>>>(
        Wqkv, wq16, C_DIM, C3);
    transpose_f16_kernel<<<dim3(C_DIM / 32, C_DIM / 32), dim3(32, 8)>>>(
        Wproj, wp16, C_DIM, C_DIM);

    // 1) qkv projection (fp16 2-pass): q -> fp16 hi/lo; k, v -> single fp16
    gemm_f16_kernel<2, 1><<<dim3(C3 / 128, M_ROWS / 128), 128, SM_QKV>>>(
        xh16, xl16, wq16, bqkv, nullptr, M_ROWS, C3, C_DIM,
        q16h, q16l, k16, v16);

    // 2) attention -> single fp16
    flash_attn_mma<<<dim3(T_SZ / 128, B_SZ * NH), 256, FA_SMEM>>>(
        q16h, q16l, k16, v16, o16);

    // 3) out = attn @ Wproj + bproj (fp16 single-pass)
    gemm_f16_kernel<1, 0><<<dim3(C_DIM / 128, M_ROWS / 128), 128, SM_PROJ>>>(
        o16, nullptr, wp16, bproj, out, M_ROWS, C_DIM, C_DIM,
        nullptr, nullptr, nullptr, nullptr);
}

// round 12
// speedup vs baseline: 1.8443x; 1.1036x over previous
#include <cuda_runtime.h>
#include <cuda_bf16.h>
#include <cuda_fp16.h>
#include <math_constants.h>

#define C_DIM 1024
#define C3    3072
#define NH    16
#define HD    64
#define B_SZ  2
#define T_SZ  2048
#define M_ROWS (B_SZ*T_SZ)

#define ATT_SCALE 0.5f
#define LOG2E 1.4426950408889634f

typedef unsigned long long u64;
typedef unsigned int u32;

// ---------------- scratch (no device allocation allowed) -------------------
__device__ __half g_q16[(size_t)M_ROWS * C_DIM];    // Q single fp16
__device__ __half g_k16[(size_t)M_ROWS * C_DIM];    // K single fp16
__device__ __half g_v16[(size_t)M_ROWS * C_DIM];    // V single fp16
__device__ __half g_xh16[(size_t)M_ROWS * C_DIM];   // x fp16 hi
__device__ __half g_xl16[(size_t)M_ROWS * C_DIM];   // x fp16 lo
__device__ __half g_o16[(size_t)M_ROWS * C_DIM];    // attn out single fp16
__device__ __half g_wq16[(size_t)C3 * C_DIM];       // Wqkv^T single fp16 [N][K]
__device__ __half g_wp16[(size_t)C_DIM * C_DIM];    // Wproj^T single fp16

// ---------------- helpers ----------------------------------------------------
__device__ __forceinline__ u32 smem_u32(const void* p) {
    u32 a; asm("{ .reg .u64 t; cvta.to.shared.u64 t, %1; cvt.u32.u64 %0, t; }"
               : "=r"(a) : "l"(p));
    return a;
}
__device__ __forceinline__ void ldsm_x4(u32& r0, u32& r1, u32& r2, u32& r3, u32 a) {
    asm volatile("ldmatrix.sync.aligned.m8n8.x4.shared.b16 {%0,%1,%2,%3}, [%4];"
                 : "=r"(r0), "=r"(r1), "=r"(r2), "=r"(r3) : "r"(a));
}
__device__ __forceinline__ void ldsm_x4t(u32& r0, u32& r1, u32& r2, u32& r3, u32 a) {
    asm volatile("ldmatrix.sync.aligned.m8n8.x4.trans.shared.b16 {%0,%1,%2,%3}, [%4];"
                 : "=r"(r0), "=r"(r1), "=r"(r2), "=r"(r3) : "r"(a));
}
__device__ __forceinline__ void mma16816h(float* c, const u32* a, const u32* b) {
    asm volatile(
        "mma.sync.aligned.m16n8k16.row.col.f32.f16.f16.f32 "
        "{%0,%1,%2,%3},{%4,%5,%6,%7},{%8,%9},{%0,%1,%2,%3};"
        : "+f"(c[0]), "+f"(c[1]), "+f"(c[2]), "+f"(c[3])
        : "r"(a[0]), "r"(a[1]), "r"(a[2]), "r"(a[3]), "r"(b[0]), "r"(b[1]));
}
__device__ __forceinline__ float fast_exp2(float x) {
    float r; asm("ex2.approx.ftz.f32 %0, %1;" : "=f"(r) : "f"(x)); return r;
}
__device__ __forceinline__ u32 cvt_f16x2(float lo, float hi) {
    u32 r; asm("cvt.rn.f16x2.f32 %0, %1, %2;" : "=r"(r) : "f"(hi), "f"(lo));
    return r;
}
__device__ __forceinline__ void split2h(float f0, float f1, u32& hi, u32& lo) {
    hi = cvt_f16x2(f0, f1);
    __half2 h2 = *reinterpret_cast<__half2*>(&hi);
    float2 hf = __half22float2(h2);
    lo = cvt_f16x2(f0 - hf.x, f1 - hf.y);
}
#define CP_ASYNC16(d, s) asm volatile("cp.async.cg.shared.global [%0], [%1], 16;" :: "r"(d), "l"(s))
#define CP_COMMIT()      asm volatile("cp.async.commit_group;" ::: "memory")
#define CP_WAIT1()       asm volatile("cp.async.wait_group 1;" ::: "memory")
#define CP_WAIT0()       asm volatile("cp.async.wait_group 0;" ::: "memory")

// ---------------- prep: fp32 -> fp16 hi/lo split -----------------------------
__global__ void split16_kernel(const float* __restrict__ in,
                               __half* __restrict__ hi,
                               __half* __restrict__ lo, int n4)
{
    int i = blockIdx.x * blockDim.x + threadIdx.x;
    if (i >= n4) return;
    float4 v = ((const float4*)in)[i];
    u32 h0, l0, h1, l1;
    split2h(v.x, v.y, h0, l0);
    split2h(v.z, v.w, h1, l1);
    ((uint2*)hi)[i] = make_uint2(h0, h1);
    ((uint2*)lo)[i] = make_uint2(l0, l1);
}

// ---------------- prep: W[K][N] -> W^T single fp16 [N][K] -------------------
__global__ void transpose_f16_kernel(const float* __restrict__ W,
                                     __half* __restrict__ W16, int K, int N)
{
    __shared__ float ts[32][33];
    int n0 = blockIdx.x * 32, k0 = blockIdx.y * 32;
    int tx = threadIdx.x, ty = threadIdx.y;  // 32 x 8
#pragma unroll
    for (int r = 0; r < 4; r++)
        ts[ty + 8 * r][tx] = W[(size_t)(k0 + ty + 8 * r) * N + n0 + tx];
    __syncthreads();
#pragma unroll
    for (int r = 0; r < 4; r++) {
        float v = ts[tx][ty + 8 * r];
        W16[(size_t)(n0 + ty + 8 * r) * K + k0 + tx] = __float2half_rn(v);
    }
}

// ---------------- fp16 GEMM: C = (sum_a A_a) @ B16^T + bias -----------------
// NA = number of A passes (1 or 2). EPI 0: fp32 C out.
// EPI 1: q/k/v -> single fp16 (dst by n-part).
#define RSTRIDE 80
#define ARR_B   (128 * RSTRIDE)

extern __shared__ char sm_raw[];

template<int NA, int EPI>
__global__ void __launch_bounds__(128) gemm_f16_kernel(
    const __half* __restrict__ A0, const __half* __restrict__ A1,
    const __half* __restrict__ B16,
    const float* __restrict__ bias, float* __restrict__ C,
    int M, int N, int K,
    __half* oq16, __half* ok16, __half* ov16)
{
    const int NARR = NA + 1;
    const int STB  = NARR * ARR_B;

    const int tid = threadIdx.x, lane = tid & 31, wid = tid >> 5;
    const int warp_m = wid & 1, warp_n = wid >> 1;
    const int m0 = blockIdx.y * 128, n0 = blockIdx.x * 128;

    const int grp = lane >> 3, lrow = lane & 7;
    const int a_row = (grp & 1) * 8 + lrow, a_kb = (grp >> 1) * 16;
    const int b_row = (grp >> 1) * 8 + lrow, b_kb = (grp & 1) * 16;

    const __half* srcs[3] = {A0, NA == 2 ? A1 : B16, B16};
    const int r0s[3] = {m0, NA == 2 ? m0 : n0, n0};

    float cf[4][8][4];
#pragma unroll
    for (int tm = 0; tm < 4; tm++)
#pragma unroll
        for (int tn = 0; tn < 8; tn++)
#pragma unroll
            for (int q = 0; q < 4; q++) cf[tm][tn][q] = 0.f;

#define G_LOAD(st, k0v)                                                         \
    do {                                                                        \
        char* _b = sm_raw + (st) * STB;                                         \
        _Pragma("unroll")                                                       \
        for (int t = 0; t < NARR; t++) {                                        \
            const __half* _s = srcs[t] + (size_t)r0s[t] * K + (k0v);            \
            _Pragma("unroll")                                                   \
            for (int j = 0; j < 4; j++) {                                       \
                int _i = tid + j * 128;                                         \
                int _r = _i >> 2, _c = _i & 3;                                  \
                u32 _d = smem_u32(_b + t * ARR_B + _r * RSTRIDE + _c * 16);     \
                CP_ASYNC16(_d, _s + (size_t)_r * K + _c * 8);                   \
            }                                                                   \
        }                                                                       \
    } while (0)

#define G_COMPUTE(st)                                                           \
    do {                                                                        \
        u32 _sb = smem_u32(sm_raw) + (st) * STB;                                \
        _Pragma("unroll")                                                       \
        for (int ks = 0; ks < 2; ks++) {                                        \
            u32 afr[NA][4][4], bfr[4][4];                                       \
            _Pragma("unroll")                                                   \
            for (int s = 0; s < NA; s++)                                        \
                _Pragma("unroll")                                               \
                for (int tm = 0; tm < 4; tm++)                                  \
                    ldsm_x4(afr[s][tm][0], afr[s][tm][1],                       \
                            afr[s][tm][2], afr[s][tm][3],                       \
                            _sb + s * ARR_B +                                   \
                            (warp_m * 64 + tm * 16 + a_row) * RSTRIDE +         \
                            ks * 32 + a_kb);                                    \
            _Pragma("unroll")                                                   \
            for (int t2 = 0; t2 < 4; t2++)                                      \
                ldsm_x4(bfr[t2][0], bfr[t2][1], bfr[t2][2], bfr[t2][3],         \
                        _sb + NA * ARR_B +                                      \
                        (warp_n * 64 + t2 * 16 + b_row) * RSTRIDE +             \
                        ks * 32 + b_kb);                                        \
            _Pragma("unroll")                                                   \
            for (int s = 0; s < NA; s++)                                        \
                _Pragma("unroll")                                               \
                for (int tm = 0; tm < 4; tm++)                                  \
                    _Pragma("unroll")                                           \
                    for (int tn = 0; tn < 8; tn++)                              \
                        mma16816h(cf[tm][tn], afr[s][tm],                       \
                                  &bfr[tn >> 1][(tn & 1) * 2]);                 \
        }                                                                       \
    } while (0)

    const int NIT = K / 32;
    G_LOAD(0, 0);
    CP_COMMIT();
    for (int it = 0; it < NIT; it++) {
        if (it + 1 < NIT) {
            G_LOAD((it + 1) & 1, (it + 1) * 32);
            CP_COMMIT();
            CP_WAIT1();
        } else {
            CP_WAIT0();
        }
        __syncthreads();
        G_COMPUTE(it & 1);
        __syncthreads();
    }

    const int mrow = lane >> 2, ncol = (lane & 3) * 2;
    if (EPI == 0) {
#pragma unroll
        for (int tm = 0; tm < 4; tm++)
#pragma unroll
            for (int tn = 0; tn < 8; tn++) {
                int r = m0 + warp_m * 64 + tm * 16 + mrow;
                int c = n0 + warp_n * 64 + tn * 8 + ncol;
                float2 bb = *(const float2*)&bias[c];
                *(float2*)&C[(size_t)r * N + c] =
                    make_float2(cf[tm][tn][0] + bb.x, cf[tm][tn][1] + bb.y);
                *(float2*)&C[(size_t)(r + 8) * N + c] =
                    make_float2(cf[tm][tn][2] + bb.x, cf[tm][tn][3] + bb.y);
            }
    } else {
        int part = n0 >> 10;
        __half* dst = part == 0 ? oq16 : (part == 1 ? ok16 : ov16);
#pragma unroll
        for (int tm = 0; tm < 4; tm++)
#pragma unroll
            for (int tn = 0; tn < 8; tn++) {
                int r = m0 + warp_m * 64 + tm * 16 + mrow;
                int c = n0 + warp_n * 64 + tn * 8 + ncol;
                int lc = c & 1023;
                float2 bb = *(const float2*)&bias[c];
                u32 v0 = cvt_f16x2(cf[tm][tn][0] + bb.x, cf[tm][tn][1] + bb.y);
                u32 v1 = cvt_f16x2(cf[tm][tn][2] + bb.x, cf[tm][tn][3] + bb.y);
                *(u32*)(dst + (size_t)r * C_DIM + lc) = v0;
                *(u32*)(dst + (size_t)(r + 8) * C_DIM + lc) = v1;
            }
    }
#undef G_LOAD
#undef G_COMPUTE
}

// ---------------- tensor-core flash attention -------------------------------
// S = Q16 @ K16^T (single pass).  PV = P16 @ V16 (single pass).
#define FA_RS   72
#define FA_ARR  (128 * FA_RS)
#define FA_ST0  FA_ARR                       // Q: one array
#define FA_STSZ (2 * FA_ARR)                 // K16, V16
#define FA_SMEM ((FA_ARR + 2 * FA_STSZ) * 2)   // 92160 B -> 2 CTAs/SM

__global__ void __launch_bounds__(256) flash_attn_mma(
    const __half* __restrict__ q16, const __half* __restrict__ k16,
    const __half* __restrict__ v16, __half* __restrict__ o16)
{
    __half* sm = (__half*)sm_raw;
    const int tid = threadIdx.x, lane = tid & 31, w = tid >> 5;
    const int qt = blockIdx.x;
    const int b = blockIdx.y >> 4, h = blockIdx.y & 15;
    const size_t rowbase = (size_t)b * T_SZ;
    const int colbase = h * HD;

    const __half* kvsrc[2] = {k16, v16};

#define FA_LOAD(st, kt)                                                         \
    do {                                                                        \
        _Pragma("unroll")                                                       \
        for (int a4 = 0; a4 < 2; a4++) {                                        \
            _Pragma("unroll")                                                   \
            for (int j = 0; j < 4; j++) {                                       \
                int idx = tid + j * 256;                                        \
                int r = idx >> 3, c8 = idx & 7;                                 \
                u32 d = smem_u32(sm + FA_ST0 + (st) * FA_STSZ + a4 * FA_ARR +   \
                                 r * FA_RS + c8 * 8);                           \
                CP_ASYNC16(d, kvsrc[a4] +                                       \
                           (rowbase + (kt) * 128 + r) * C_DIM + colbase + c8 * 8); \
            }                                                                   \
        }                                                                       \
    } while (0)

    FA_LOAD(0, 0);
    CP_COMMIT();

    // stage Q (single fp16)
#pragma unroll
    for (int j = 0; j < 4; j++) {
        int idx = tid + j * 256;
        int r = idx >> 3, c8 = idx & 7;
        uint4 v = *(const uint4*)(q16 +
            (rowbase + qt * 128 + r) * C_DIM + colbase + c8 * 8);
        *(uint4*)(sm + r * FA_RS + c8 * 8) = v;
    }
    __syncthreads();

    u32 qf[4][4];
    {
        u32 qbase = smem_u32(sm);
        int arow = w * 16 + (lane & 15);
        int acol = (lane >> 4) * 8;
#pragma unroll
        for (int ks = 0; ks < 4; ks++) {
            u32 off = (arow * FA_RS + ks * 16 + acol) * 2;
            ldsm_x4(qf[ks][0], qf[ks][1], qf[ks][2], qf[ks][3], qbase + off);
        }
    }

    float sf[16][4];
    float of[8][4];
#pragma unroll
    for (int j = 0; j < 8; j++)
#pragma unroll
        for (int q = 0; q < 4; q++) of[j][q] = 0.f;
    float m0 = -CUDART_INF_F, m1 = -CUDART_INF_F, l0 = 0.f, l1 = 0.f;

    const u32 sbase = smem_u32(sm);
    const int krow = (lane & 7) + ((lane >> 4) << 3);
    const int kch  = (lane >> 3) & 1;
    const int vrow = (lane & 7) + (((lane >> 3) & 1) << 3);
    const int vch  = lane >> 4;
    const float sc = ATT_SCALE * LOG2E;

    for (int kt = 0; kt < T_SZ / 128; kt++) {
        if (kt + 1 < T_SZ / 128) { FA_LOAD((kt + 1) & 1, kt + 1); CP_COMMIT(); CP_WAIT1(); }
        else CP_WAIT0();
        __syncthreads();
        u32 stb = sbase + (FA_ST0 + (kt & 1) * FA_STSZ) * 2;

        // ---- S = Q K^T (single fp16 pass), pass-major ----
#pragma unroll
        for (int j = 0; j < 16; j++) {
            sf[j][0] = 0.f; sf[j][1] = 0.f; sf[j][2] = 0.f; sf[j][3] = 0.f;
        }
#pragma unroll
        for (int jp = 0; jp < 4; jp++) {
            u32 bh[2][4][4];
#pragma unroll
            for (int j2 = 0; j2 < 2; j2++)
#pragma unroll
                for (int ks = 0; ks < 4; ks++) {
                    u32 off = (((jp * 2 + j2) * 16 + krow) * FA_RS +
                               ks * 16 + kch * 8) * 2;
                    ldsm_x4(bh[j2][ks][0], bh[j2][ks][1], bh[j2][ks][2], bh[j2][ks][3],
                            stb + off);
                }
            float* s0 = sf[4 * jp];     float* s1 = sf[4 * jp + 1];
            float* s2 = sf[4 * jp + 2]; float* s3 = sf[4 * jp + 3];
#pragma unroll
            for (int ks = 0; ks < 4; ks++) {
                mma16816h(s0, qf[ks], &bh[0][ks][0]);
                mma16816h(s1, qf[ks], &bh[0][ks][2]);
                mma16816h(s2, qf[ks], &bh[1][ks][0]);
                mma16816h(s3, qf[ks], &bh[1][ks][2]);
            }
        }

        // ---- online softmax ----
        float mt0 = -CUDART_INF_F, mt1 = -CUDART_INF_F;
#pragma unroll
        for (int j = 0; j < 16; j++) {
            sf[j][0] *= sc; sf[j][1] *= sc; sf[j][2] *= sc; sf[j][3] *= sc;
            mt0 = fmaxf(mt0, fmaxf(sf[j][0], sf[j][1]));
            mt1 = fmaxf(mt1, fmaxf(sf[j][2], sf[j][3]));
        }
        mt0 = fmaxf(mt0, __shfl_xor_sync(0xffffffffu, mt0, 1));
        mt0 = fmaxf(mt0, __shfl_xor_sync(0xffffffffu, mt0, 2));
        mt1 = fmaxf(mt1, __shfl_xor_sync(0xffffffffu, mt1, 1));
        mt1 = fmaxf(mt1, __shfl_xor_sync(0xffffffffu, mt1, 2));
        float mn0 = fmaxf(m0, mt0), mn1 = fmaxf(m1, mt1);
        float f0 = fast_exp2(m0 - mn0), f1 = fast_exp2(m1 - mn1);
        m0 = mn0; m1 = mn1;
        float rs0 = 0.f, rs1 = 0.f;
#pragma unroll
        for (int j = 0; j < 16; j++) {
            sf[j][0] = fast_exp2(sf[j][0] - mn0);
            sf[j][1] = fast_exp2(sf[j][1] - mn0);
            sf[j][2] = fast_exp2(sf[j][2] - mn1);
            sf[j][3] = fast_exp2(sf[j][3] - mn1);
            rs0 += sf[j][0] + sf[j][1];
            rs1 += sf[j][2] + sf[j][3];
        }
        rs0 += __shfl_xor_sync(0xffffffffu, rs0, 1);
        rs0 += __shfl_xor_sync(0xffffffffu, rs0, 2);
        rs1 += __shfl_xor_sync(0xffffffffu, rs1, 1);
        rs1 += __shfl_xor_sync(0xffffffffu, rs1, 2);
        l0 = l0 * f0 + rs0;
        l1 = l1 * f1 + rs1;
#pragma unroll
        for (int j = 0; j < 8; j++) {
            of[j][0] *= f0; of[j][1] *= f0; of[j][2] *= f1; of[j][3] *= f1;
        }

        // ---- O += P V (single fp16 pass) ----
#pragma unroll
        for (int kp = 0; kp < 8; kp++) {
            u32 ah[4];
            ah[0] = cvt_f16x2(sf[2 * kp][0],     sf[2 * kp][1]);
            ah[1] = cvt_f16x2(sf[2 * kp][2],     sf[2 * kp][3]);
            ah[2] = cvt_f16x2(sf[2 * kp + 1][0], sf[2 * kp + 1][1]);
            ah[3] = cvt_f16x2(sf[2 * kp + 1][2], sf[2 * kp + 1][3]);
            u32 bv[4][4];
#pragma unroll
            for (int dt = 0; dt < 4; dt++) {
                u32 off = ((kp * 16 + vrow) * FA_RS + dt * 16 + vch * 8) * 2;
                ldsm_x4t(bv[dt][0], bv[dt][1], bv[dt][2], bv[dt][3],
                         stb + FA_ARR * 2 + off);
            }
#pragma unroll
            for (int dt = 0; dt < 4; dt++) {
                mma16816h(of[2 * dt],     ah, &bv[dt][0]);
                mma16816h(of[2 * dt + 1], ah, &bv[dt][2]);
            }
        }
        __syncthreads();
    }

    // ---- epilogue: normalize, store single fp16 ----
    float inv0 = 1.f / l0, inv1 = 1.f / l1;
    const int g = lane >> 2, t2 = (lane & 3) * 2;
    size_t r0 = rowbase + qt * 128 + w * 16 + g;
#pragma unroll
    for (int j = 0; j < 8; j++) {
        int c = colbase + j * 8 + t2;
        u32 v0 = cvt_f16x2(of[j][0] * inv0, of[j][1] * inv0);
        u32 v1 = cvt_f16x2(of[j][2] * inv1, of[j][3] * inv1);
        *(u32*)(o16 + r0 * C_DIM + c) = v0;
        *(u32*)(o16 + (r0 + 8) * C_DIM + c) = v1;
    }
#undef FA_LOAD
}

// ---------------------------------------------------------------------------
extern "C" void kernel_launch(void* const* d_in, const int* in_sizes, int n_in,
                              void* d_out, int out_size)
{
    const float* x     = (const float*)d_in[0];
    const float* Wqkv  = (const float*)d_in[1];
    const float* bqkv  = (const float*)d_in[2];
    const float* Wproj = (const float*)d_in[3];
    const float* bproj = (const float*)d_in[4];
    float* out = (float*)d_out;

    __half *q16, *k16, *v16, *xh16, *xl16, *o16, *wq16, *wp16;
    cudaGetSymbolAddress((void**)&q16, g_q16);
    cudaGetSymbolAddress((void**)&k16, g_k16);   cudaGetSymbolAddress((void**)&v16, g_v16);
    cudaGetSymbolAddress((void**)&xh16, g_xh16); cudaGetSymbolAddress((void**)&xl16, g_xl16);
    cudaGetSymbolAddress((void**)&o16, g_o16);
    cudaGetSymbolAddress((void**)&wq16, g_wq16); cudaGetSymbolAddress((void**)&wp16, g_wp16);

    const int SM_QKV  = 2 * 3 * ARR_B;   // NA=2: A0,A1,B x2 stages = 61440 B
    const int SM_PROJ = 2 * 2 * ARR_B;   // NA=1: A0,B  x2 stages = 40960 B
    cudaFuncSetAttribute(gemm_f16_kernel<2, 1>,
                         cudaFuncAttributeMaxDynamicSharedMemorySize, SM_QKV);
    cudaFuncSetAttribute(gemm_f16_kernel<1, 0>,
                         cudaFuncAttributeMaxDynamicSharedMemorySize, SM_PROJ);
    cudaFuncSetAttribute(flash_attn_mma,
                         cudaFuncAttributeMaxDynamicSharedMemorySize, FA_SMEM);

    // prep: x -> fp16 hi/lo; weights -> transposed single fp16
    split16_kernel<<<(M_ROWS * C_DIM / 4 + 255) / 256, 256>>>(
        x, xh16, xl16, M_ROWS * C_DIM / 4);
    transpose_f16_kernel<<<dim3(C3 / 32, C_DIM / 32), dim3(32, 8)>>>(
        Wqkv, wq16, C_DIM, C3);
    transpose_f16_kernel<<<dim3(C_DIM / 32, C_DIM / 32), dim3(32, 8)>>>(
        Wproj, wp16, C_DIM, C_DIM);

    // 1) qkv projection (fp16 2-pass): q, k, v -> single fp16
    gemm_f16_kernel<2, 1><<<dim3(C3 / 128, M_ROWS / 128), 128, SM_QKV>>>(
        xh16, xl16, wq16, bqkv, nullptr, M_ROWS, C3, C_DIM,
        q16, k16, v16);

    // 2) attention -> single fp16
    flash_attn_mma<<<dim3(T_SZ / 128, B_SZ * NH), 256, FA_SMEM>>>(
        q16, k16, v16, o16);

    // 3) out = attn @ Wproj + bproj (fp16 single-pass)
    gemm_f16_kernel<1, 0><<<dim3(C_DIM / 128, M_ROWS / 128), 128, SM_PROJ>>>(
        o16, nullptr, wp16, bproj, out, M_ROWS, C_DIM, C_DIM,
        nullptr, nullptr, nullptr);
}

// round 13
// speedup vs baseline: 2.1024x; 1.1400x over previous
#include <cuda_runtime.h>
#include <cuda_bf16.h>
#include <cuda_fp16.h>
#include <math_constants.h>

#define C_DIM 1024
#define C3    3072
#define NH    16
#define HD    64
#define B_SZ  2
#define T_SZ  2048
#define M_ROWS (B_SZ*T_SZ)

#define ATT_SCALE 0.5f
#define LOG2E 1.4426950408889634f

typedef unsigned long long u64;
typedef unsigned int u32;

// ---------------- scratch (no device allocation allowed) -------------------
__device__ __half g_q16[(size_t)M_ROWS * C_DIM];    // Q single fp16
__device__ __half g_k16[(size_t)M_ROWS * C_DIM];    // K single fp16
__device__ __half g_v16[(size_t)M_ROWS * C_DIM];    // V single fp16
__device__ __half g_xh16[(size_t)M_ROWS * C_DIM];   // x fp16 hi
__device__ __half g_xl16[(size_t)M_ROWS * C_DIM];   // x fp16 lo
__device__ __half g_o16[(size_t)M_ROWS * C_DIM];    // attn out single fp16
__device__ __half g_wq16[(size_t)C3 * C_DIM];       // Wqkv^T single fp16 [N][K]
__device__ __half g_wp16[(size_t)C_DIM * C_DIM];    // Wproj^T single fp16

// ---------------- helpers ----------------------------------------------------
__device__ __forceinline__ u32 smem_u32(const void* p) {
    u32 a; asm("{ .reg .u64 t; cvta.to.shared.u64 t, %1; cvt.u32.u64 %0, t; }"
               : "=r"(a) : "l"(p));
    return a;
}
__device__ __forceinline__ void ldsm_x4(u32& r0, u32& r1, u32& r2, u32& r3, u32 a) {
    asm volatile("ldmatrix.sync.aligned.m8n8.x4.shared.b16 {%0,%1,%2,%3}, [%4];"
                 : "=r"(r0), "=r"(r1), "=r"(r2), "=r"(r3) : "r"(a));
}
__device__ __forceinline__ void ldsm_x4t(u32& r0, u32& r1, u32& r2, u32& r3, u32 a) {
    asm volatile("ldmatrix.sync.aligned.m8n8.x4.trans.shared.b16 {%0,%1,%2,%3}, [%4];"
                 : "=r"(r0), "=r"(r1), "=r"(r2), "=r"(r3) : "r"(a));
}
__device__ __forceinline__ void mma16816h(float* c, const u32* a, const u32* b) {
    asm volatile(
        "mma.sync.aligned.m16n8k16.row.col.f32.f16.f16.f32 "
        "{%0,%1,%2,%3},{%4,%5,%6,%7},{%8,%9},{%0,%1,%2,%3};"
        : "+f"(c[0]), "+f"(c[1]), "+f"(c[2]), "+f"(c[3])
        : "r"(a[0]), "r"(a[1]), "r"(a[2]), "r"(a[3]), "r"(b[0]), "r"(b[1]));
}
__device__ __forceinline__ float fast_exp2(float x) {
    float r; asm("ex2.approx.ftz.f32 %0, %1;" : "=f"(r) : "f"(x)); return r;
}
__device__ __forceinline__ u32 cvt_f16x2(float lo, float hi) {
    u32 r; asm("cvt.rn.f16x2.f32 %0, %1, %2;" : "=r"(r) : "f"(hi), "f"(lo));
    return r;
}
__device__ __forceinline__ void split2h(float f0, float f1, u32& hi, u32& lo) {
    hi = cvt_f16x2(f0, f1);
    __half2 h2 = *reinterpret_cast<__half2*>(&hi);
    float2 hf = __half22float2(h2);
    lo = cvt_f16x2(f0 - hf.x, f1 - hf.y);
}
#define CP_ASYNC16(d, s) asm volatile("cp.async.cg.shared.global [%0], [%1], 16;" :: "r"(d), "l"(s))
#define CP_COMMIT()      asm volatile("cp.async.commit_group;" ::: "memory")
#define CP_WAIT1()       asm volatile("cp.async.wait_group 1;" ::: "memory")
#define CP_WAIT0()       asm volatile("cp.async.wait_group 0;" ::: "memory")

// ---------------- prep: fp32 -> fp16 hi/lo split -----------------------------
__global__ void split16_kernel(const float* __restrict__ in,
                               __half* __restrict__ hi,
                               __half* __restrict__ lo, int n4)
{
    int i = blockIdx.x * blockDim.x + threadIdx.x;
    if (i >= n4) return;
    float4 v = ((const float4*)in)[i];
    u32 h0, l0, h1, l1;
    split2h(v.x, v.y, h0, l0);
    split2h(v.z, v.w, h1, l1);
    ((uint2*)hi)[i] = make_uint2(h0, h1);
    ((uint2*)lo)[i] = make_uint2(l0, l1);
}

// ---------------- prep: W[K][N] -> W^T single fp16 [N][K] -------------------
__global__ void transpose_f16_kernel(const float* __restrict__ W,
                                     __half* __restrict__ W16, int K, int N)
{
    __shared__ float ts[32][33];
    int n0 = blockIdx.x * 32, k0 = blockIdx.y * 32;
    int tx = threadIdx.x, ty = threadIdx.y;  // 32 x 8
#pragma unroll
    for (int r = 0; r < 4; r++)
        ts[ty + 8 * r][tx] = W[(size_t)(k0 + ty + 8 * r) * N + n0 + tx];
    __syncthreads();
#pragma unroll
    for (int r = 0; r < 4; r++) {
        float v = ts[tx][ty + 8 * r];
        W16[(size_t)(n0 + ty + 8 * r) * K + k0 + tx] = __float2half_rn(v);
    }
}

// ---------------- fp16 GEMM: C = (A0 [+A1]) @ B16^T + bias ------------------
// NA=2: second A pass applied ONLY where useA1 (q columns). NA=1: single pass.
// EPI 0: fp32 C out.   EPI 1: q/k/v -> single fp16 (dst by n-part).
#define RSTRIDE 80
#define ARR_B   (128 * RSTRIDE)

extern __shared__ char sm_raw[];

template<int NA, int EPI>
__global__ void __launch_bounds__(128) gemm_f16_kernel(
    const __half* __restrict__ A0, const __half* __restrict__ A1,
    const __half* __restrict__ B16,
    const float* __restrict__ bias, float* __restrict__ C,
    int M, int N, int K,
    __half* oq16, __half* ok16, __half* ov16)
{
    const int STB = (NA + 1) * ARR_B;

    const int tid = threadIdx.x, lane = tid & 31, wid = tid >> 5;
    const int warp_m = wid & 1, warp_n = wid >> 1;
    const int m0 = blockIdx.y * 128, n0 = blockIdx.x * 128;

    // 2nd A pass only for Q columns (n0 < C_DIM); uniform per block.
    const bool useA1 = (NA == 2) && (n0 < C_DIM);

    const int grp = lane >> 3, lrow = lane & 7;
    const int a_row = (grp & 1) * 8 + lrow, a_kb = (grp >> 1) * 16;
    const int b_row = (grp >> 1) * 8 + lrow, b_kb = (grp & 1) * 16;

    float cf[4][8][4];
#pragma unroll
    for (int tm = 0; tm < 4; tm++)
#pragma unroll
        for (int tn = 0; tn < 8; tn++)
#pragma unroll
            for (int q = 0; q < 4; q++) cf[tm][tn][q] = 0.f;

#define G_LOAD(st, k0v)                                                         \
    do {                                                                        \
        char* _b = sm_raw + (st) * STB;                                         \
        _Pragma("unroll")                                                       \
        for (int j = 0; j < 4; j++) {                                           \
            int _i = tid + j * 128;                                             \
            int _r = _i >> 2, _c = _i & 3;                                      \
            u32 _d0 = smem_u32(_b + _r * RSTRIDE + _c * 16);                    \
            CP_ASYNC16(_d0, A0 + (size_t)(m0 + _r) * K + (k0v) + _c * 8);       \
            u32 _db = smem_u32(_b + NA * ARR_B + _r * RSTRIDE + _c * 16);       \
            CP_ASYNC16(_db, B16 + (size_t)(n0 + _r) * K + (k0v) + _c * 8);      \
            if (useA1) {                                                        \
                u32 _d1 = smem_u32(_b + ARR_B + _r * RSTRIDE + _c * 16);        \
                CP_ASYNC16(_d1, A1 + (size_t)(m0 + _r) * K + (k0v) + _c * 8);   \
            }                                                                   \
        }                                                                       \
    } while (0)

#define G_COMPUTE(st)                                                           \
    do {                                                                        \
        u32 _sb = smem_u32(sm_raw) + (st) * STB;                                \
        _Pragma("unroll")                                                       \
        for (int ks = 0; ks < 2; ks++) {                                        \
            u32 afr0[4][4], bfr[4][4];                                          \
            _Pragma("unroll")                                                   \
            for (int tm = 0; tm < 4; tm++)                                      \
                ldsm_x4(afr0[tm][0], afr0[tm][1], afr0[tm][2], afr0[tm][3],     \
                        _sb + (warp_m * 64 + tm * 16 + a_row) * RSTRIDE +       \
                        ks * 32 + a_kb);                                        \
            _Pragma("unroll")                                                   \
            for (int t2 = 0; t2 < 4; t2++)                                      \
                ldsm_x4(bfr[t2][0], bfr[t2][1], bfr[t2][2], bfr[t2][3],         \
                        _sb + NA * ARR_B +                                      \
                        (warp_n * 64 + t2 * 16 + b_row) * RSTRIDE +             \
                        ks * 32 + b_kb);                                        \
            _Pragma("unroll")                                                   \
            for (int tm = 0; tm < 4; tm++)                                      \
                _Pragma("unroll")                                               \
                for (int tn = 0; tn < 8; tn++)                                  \
                    mma16816h(cf[tm][tn], afr0[tm],                             \
                              &bfr[tn >> 1][(tn & 1) * 2]);                     \
            if (useA1) {                                                        \
                u32 afr1[4][4];                                                 \
                _Pragma("unroll")                                               \
                for (int tm = 0; tm < 4; tm++)                                  \
                    ldsm_x4(afr1[tm][0], afr1[tm][1], afr1[tm][2], afr1[tm][3], \
                            _sb + ARR_B +                                       \
                            (warp_m * 64 + tm * 16 + a_row) * RSTRIDE +         \
                            ks * 32 + a_kb);                                    \
                _Pragma("unroll")                                               \
                for (int tm = 0; tm < 4; tm++)                                  \
                    _Pragma("unroll")                                           \
                    for (int tn = 0; tn < 8; tn++)                              \
                        mma16816h(cf[tm][tn], afr1[tm],                         \
                                  &bfr[tn >> 1][(tn & 1) * 2]);                 \
            }                                                                   \
        }                                                                       \
    } while (0)

    const int NIT = K / 32;
    G_LOAD(0, 0);
    CP_COMMIT();
    for (int it = 0; it < NIT; it++) {
        if (it + 1 < NIT) {
            G_LOAD((it + 1) & 1, (it + 1) * 32);
            CP_COMMIT();
            CP_WAIT1();
        } else {
            CP_WAIT0();
        }
        __syncthreads();
        G_COMPUTE(it & 1);
        __syncthreads();
    }

    const int mrow = lane >> 2, ncol = (lane & 3) * 2;
    if (EPI == 0) {
#pragma unroll
        for (int tm = 0; tm < 4; tm++)
#pragma unroll
            for (int tn = 0; tn < 8; tn++) {
                int r = m0 + warp_m * 64 + tm * 16 + mrow;
                int c = n0 + warp_n * 64 + tn * 8 + ncol;
                float2 bb = *(const float2*)&bias[c];
                *(float2*)&C[(size_t)r * N + c] =
                    make_float2(cf[tm][tn][0] + bb.x, cf[tm][tn][1] + bb.y);
                *(float2*)&C[(size_t)(r + 8) * N + c] =
                    make_float2(cf[tm][tn][2] + bb.x, cf[tm][tn][3] + bb.y);
            }
    } else {
        int part = n0 >> 10;
        __half* dst = part == 0 ? oq16 : (part == 1 ? ok16 : ov16);
#pragma unroll
        for (int tm = 0; tm < 4; tm++)
#pragma unroll
            for (int tn = 0; tn < 8; tn++) {
                int r = m0 + warp_m * 64 + tm * 16 + mrow;
                int c = n0 + warp_n * 64 + tn * 8 + ncol;
                int lc = c & 1023;
                float2 bb = *(const float2*)&bias[c];
                u32 v0 = cvt_f16x2(cf[tm][tn][0] + bb.x, cf[tm][tn][1] + bb.y);
                u32 v1 = cvt_f16x2(cf[tm][tn][2] + bb.x, cf[tm][tn][3] + bb.y);
                *(u32*)(dst + (size_t)r * C_DIM + lc) = v0;
                *(u32*)(dst + (size_t)(r + 8) * C_DIM + lc) = v1;
            }
    }
#undef G_LOAD
#undef G_COMPUTE
}

// ---------------- tensor-core flash attention -------------------------------
// S = Q16 @ K16^T (single pass).  PV = P16 @ V16 (single pass).
#define FA_RS   72
#define FA_ARR  (128 * FA_RS)
#define FA_ST0  FA_ARR                       // Q: one array
#define FA_STSZ (2 * FA_ARR)                 // K16, V16
#define FA_SMEM ((FA_ARR + 2 * FA_STSZ) * 2)   // 92160 B -> 2 CTAs/SM

__global__ void __launch_bounds__(256) flash_attn_mma(
    const __half* __restrict__ q16, const __half* __restrict__ k16,
    const __half* __restrict__ v16, __half* __restrict__ o16)
{
    __half* sm = (__half*)sm_raw;
    const int tid = threadIdx.x, lane = tid & 31, w = tid >> 5;
    const int qt = blockIdx.x;
    const int b = blockIdx.y >> 4, h = blockIdx.y & 15;
    const size_t rowbase = (size_t)b * T_SZ;
    const int colbase = h * HD;

    const __half* kvsrc[2] = {k16, v16};

#define FA_LOAD(st, kt)                                                         \
    do {                                                                        \
        _Pragma("unroll")                                                       \
        for (int a4 = 0; a4 < 2; a4++) {                                        \
            _Pragma("unroll")                                                   \
            for (int j = 0; j < 4; j++) {                                       \
                int idx = tid + j * 256;                                        \
                int r = idx >> 3, c8 = idx & 7;                                 \
                u32 d = smem_u32(sm + FA_ST0 + (st) * FA_STSZ + a4 * FA_ARR +   \
                                 r * FA_RS + c8 * 8);                           \
                CP_ASYNC16(d, kvsrc[a4] +                                       \
                           (rowbase + (kt) * 128 + r) * C_DIM + colbase + c8 * 8); \
            }                                                                   \
        }                                                                       \
    } while (0)

    FA_LOAD(0, 0);
    CP_COMMIT();

    // stage Q (single fp16)
#pragma unroll
    for (int j = 0; j < 4; j++) {
        int idx = tid + j * 256;
        int r = idx >> 3, c8 = idx & 7;
        uint4 v = *(const uint4*)(q16 +
            (rowbase + qt * 128 + r) * C_DIM + colbase + c8 * 8);
        *(uint4*)(sm + r * FA_RS + c8 * 8) = v;
    }
    __syncthreads();

    u32 qf[4][4];
    {
        u32 qbase = smem_u32(sm);
        int arow = w * 16 + (lane & 15);
        int acol = (lane >> 4) * 8;
#pragma unroll
        for (int ks = 0; ks < 4; ks++) {
            u32 off = (arow * FA_RS + ks * 16 + acol) * 2;
            ldsm_x4(qf[ks][0], qf[ks][1], qf[ks][2], qf[ks][3], qbase + off);
        }
    }

    float sf[16][4];
    float of[8][4];
#pragma unroll
    for (int j = 0; j < 8; j++)
#pragma unroll
        for (int q = 0; q < 4; q++) of[j][q] = 0.f;
    float m0 = -CUDART_INF_F, m1 = -CUDART_INF_F, l0 = 0.f, l1 = 0.f;

    const u32 sbase = smem_u32(sm);
    const int krow = (lane & 7) + ((lane >> 4) << 3);
    const int kch  = (lane >> 3) & 1;
    const int vrow = (lane & 7) + (((lane >> 3) & 1) << 3);
    const int vch  = lane >> 4;
    const float sc = ATT_SCALE * LOG2E;

    for (int kt = 0; kt < T_SZ / 128; kt++) {
        if (kt + 1 < T_SZ / 128) { FA_LOAD((kt + 1) & 1, kt + 1); CP_COMMIT(); CP_WAIT1(); }
        else CP_WAIT0();
        __syncthreads();
        u32 stb = sbase + (FA_ST0 + (kt & 1) * FA_STSZ) * 2;

        // ---- S = Q K^T (single fp16 pass), pass-major ----
#pragma unroll
        for (int j = 0; j < 16; j++) {
            sf[j][0] = 0.f; sf[j][1] = 0.f; sf[j][2] = 0.f; sf[j][3] = 0.f;
        }
#pragma unroll
        for (int jp = 0; jp < 4; jp++) {
            u32 bh[2][4][4];
#pragma unroll
            for (int j2 = 0; j2 < 2; j2++)
#pragma unroll
                for (int ks = 0; ks < 4; ks++) {
                    u32 off = (((jp * 2 + j2) * 16 + krow) * FA_RS +
                               ks * 16 + kch * 8) * 2;
                    ldsm_x4(bh[j2][ks][0], bh[j2][ks][1], bh[j2][ks][2], bh[j2][ks][3],
                            stb + off);
                }
            float* s0 = sf[4 * jp];     float* s1 = sf[4 * jp + 1];
            float* s2 = sf[4 * jp + 2]; float* s3 = sf[4 * jp + 3];
#pragma unroll
            for (int ks = 0; ks < 4; ks++) {
                mma16816h(s0, qf[ks], &bh[0][ks][0]);
                mma16816h(s1, qf[ks], &bh[0][ks][2]);
                mma16816h(s2, qf[ks], &bh[1][ks][0]);
                mma16816h(s3, qf[ks], &bh[1][ks][2]);
            }
        }

        // ---- online softmax ----
        float mt0 = -CUDART_INF_F, mt1 = -CUDART_INF_F;
#pragma unroll
        for (int j = 0; j < 16; j++) {
            sf[j][0] *= sc; sf[j][1] *= sc; sf[j][2] *= sc; sf[j][3] *= sc;
            mt0 = fmaxf(mt0, fmaxf(sf[j][0], sf[j][1]));
            mt1 = fmaxf(mt1, fmaxf(sf[j][2], sf[j][3]));
        }
        mt0 = fmaxf(mt0, __shfl_xor_sync(0xffffffffu, mt0, 1));
        mt0 = fmaxf(mt0, __shfl_xor_sync(0xffffffffu, mt0, 2));
        mt1 = fmaxf(mt1, __shfl_xor_sync(0xffffffffu, mt1, 1));
        mt1 = fmaxf(mt1, __shfl_xor_sync(0xffffffffu, mt1, 2));
        float mn0 = fmaxf(m0, mt0), mn1 = fmaxf(m1, mt1);
        float f0 = fast_exp2(m0 - mn0), f1 = fast_exp2(m1 - mn1);
        m0 = mn0; m1 = mn1;
        float rs0 = 0.f, rs1 = 0.f;
#pragma unroll
        for (int j = 0; j < 16; j++) {
            sf[j][0] = fast_exp2(sf[j][0] - mn0);
            sf[j][1] = fast_exp2(sf[j][1] - mn0);
            sf[j][2] = fast_exp2(sf[j][2] - mn1);
            sf[j][3] = fast_exp2(sf[j][3] - mn1);
            rs0 += sf[j][0] + sf[j][1];
            rs1 += sf[j][2] + sf[j][3];
        }
        rs0 += __shfl_xor_sync(0xffffffffu, rs0, 1);
        rs0 += __shfl_xor_sync(0xffffffffu, rs0, 2);
        rs1 += __shfl_xor_sync(0xffffffffu, rs1, 1);
        rs1 += __shfl_xor_sync(0xffffffffu, rs1, 2);
        l0 = l0 * f0 + rs0;
        l1 = l1 * f1 + rs1;
#pragma unroll
        for (int j = 0; j < 8; j++) {
            of[j][0] *= f0; of[j][1] *= f0; of[j][2] *= f1; of[j][3] *= f1;
        }

        // ---- O += P V (single fp16 pass) ----
#pragma unroll
        for (int kp = 0; kp < 8; kp++) {
            u32 ah[4];
            ah[0] = cvt_f16x2(sf[2 * kp][0],     sf[2 * kp][1]);
            ah[1] = cvt_f16x2(sf[2 * kp][2],     sf[2 * kp][3]);
            ah[2] = cvt_f16x2(sf[2 * kp + 1][0], sf[2 * kp + 1][1]);
            ah[3] = cvt_f16x2(sf[2 * kp + 1][2], sf[2 * kp + 1][3]);
            u32 bv[4][4];
#pragma unroll
            for (int dt = 0; dt < 4; dt++) {
                u32 off = ((kp * 16 + vrow) * FA_RS + dt * 16 + vch * 8) * 2;
                ldsm_x4t(bv[dt][0], bv[dt][1], bv[dt][2], bv[dt][3],
                         stb + FA_ARR * 2 + off);
            }
#pragma unroll
            for (int dt = 0; dt < 4; dt++) {
                mma16816h(of[2 * dt],     ah, &bv[dt][0]);
                mma16816h(of[2 * dt + 1], ah, &bv[dt][2]);
            }
        }
        __syncthreads();
    }

    // ---- epilogue: normalize, store single fp16 ----
    float inv0 = 1.f / l0, inv1 = 1.f / l1;
    const int g = lane >> 2, t2 = (lane & 3) * 2;
    size_t r0 = rowbase + qt * 128 + w * 16 + g;
#pragma unroll
    for (int j = 0; j < 8; j++) {
        int c = colbase + j * 8 + t2;
        u32 v0 = cvt_f16x2(of[j][0] * inv0, of[j][1] * inv0);
        u32 v1 = cvt_f16x2(of[j][2] * inv1, of[j][3] * inv1);
        *(u32*)(o16 + r0 * C_DIM + c) = v0;
        *(u32*)(o16 + (r0 + 8) * C_DIM + c) = v1;
    }
#undef FA_LOAD
}

// ---------------------------------------------------------------------------
extern "C" void kernel_launch(void* const* d_in, const int* in_sizes, int n_in,
                              void* d_out, int out_size)
{
    const float* x     = (const float*)d_in[0];
    const float* Wqkv  = (const float*)d_in[1];
    const float* bqkv  = (const float*)d_in[2];
    const float* Wproj = (const float*)d_in[3];
    const float* bproj = (const float*)d_in[4];
    float* out = (float*)d_out;

    __half *q16, *k16, *v16, *xh16, *xl16, *o16, *wq16, *wp16;
    cudaGetSymbolAddress((void**)&q16, g_q16);
    cudaGetSymbolAddress((void**)&k16, g_k16);   cudaGetSymbolAddress((void**)&v16, g_v16);
    cudaGetSymbolAddress((void**)&xh16, g_xh16); cudaGetSymbolAddress((void**)&xl16, g_xl16);
    cudaGetSymbolAddress((void**)&o16, g_o16);
    cudaGetSymbolAddress((void**)&wq16, g_wq16); cudaGetSymbolAddress((void**)&wp16, g_wp16);

    const int SM_QKV  = 2 * 3 * ARR_B;   // NA=2: A0,A1,B x2 stages = 61440 B
    const int SM_PROJ = 2 * 2 * ARR_B;   // NA=1: A0,B  x2 stages = 40960 B
    cudaFuncSetAttribute(gemm_f16_kernel<2, 1>,
                         cudaFuncAttributeMaxDynamicSharedMemorySize, SM_QKV);
    cudaFuncSetAttribute(gemm_f16_kernel<1, 0>,
                         cudaFuncAttributeMaxDynamicSharedMemorySize, SM_PROJ);
    cudaFuncSetAttribute(flash_attn_mma,
                         cudaFuncAttributeMaxDynamicSharedMemorySize, FA_SMEM);

    // prep: x -> fp16 hi/lo; weights -> transposed single fp16
    split16_kernel<<<(M_ROWS * C_DIM / 4 + 255) / 256, 256>>>(
        x, xh16, xl16, M_ROWS * C_DIM / 4);
    transpose_f16_kernel<<<dim3(C3 / 32, C_DIM / 32), dim3(32, 8)>>>(
        Wqkv, wq16, C_DIM, C3);
    transpose_f16_kernel<<<dim3(C_DIM / 32, C_DIM / 32), dim3(32, 8)>>>(
        Wproj, wp16, C_DIM, C_DIM);

    // 1) qkv projection: q 2-pass, k/v single-pass; all stored single fp16
    gemm_f16_kernel<2, 1><<<dim3(C3 / 128, M_ROWS / 128), 128, SM_QKV>>>(
        xh16, xl16, wq16, bqkv, nullptr, M_ROWS, C3, C_DIM,
        q16, k16, v16);

    // 2) attention -> single fp16
    flash_attn_mma<<<dim3(T_SZ / 128, B_SZ * NH), 256, FA_SMEM>>>(
        q16, k16, v16, o16);

    // 3) out = attn @ Wproj + bproj (fp16 single-pass)
    gemm_f16_kernel<1, 0><<<dim3(C_DIM / 128, M_ROWS / 128), 128, SM_PROJ>>>(
        o16, nullptr, wp16, bproj, out, M_ROWS, C_DIM, C_DIM,
        nullptr, nullptr, nullptr);
}